// round 5
// baseline (speedup 1.0000x reference)
#include <cuda_runtime.h>
#include <cuda_bf16.h>
#include <math.h>
#include <stdint.h>

// ---------------- problem constants ----------------
#define B_    2
#define N_    2048
#define DIM_  1024
#define H_    16
#define DH_   64
#define NNK_  2
#define J_    (N_ + NNK_)    // 2050
#define SCALE_ 8.0f
#define KP    3072           // split-K' = 3 * DIM_
#define MTOT  (B_ * N_)      // 4096

// ---------------- scratch (device globals; no allocs allowed) ----------------
__device__ __align__(16) __nv_bfloat16 g_x3   [MTOT * KP];      // [Ahi|Alo|Ahi] of x
__device__ __align__(16) __nv_bfloat16 g_xn3  [MTOT * KP];      // of layernorm(x)
__device__ __align__(16) __nv_bfloat16 g_att3 [MTOT * KP];      // of attention out
__device__ __align__(16) __nv_bfloat16 g_Wq3T [DIM_ * KP];      // [N=1024][Bhi|Bhi|Blo]
__device__ __align__(16) __nv_bfloat16 g_Wkv3T[2 * DIM_ * KP];  // [N=2048][...]
__device__ __align__(16) __nv_bfloat16 g_Wo3T [DIM_ * KP];
__device__ float g_q  [MTOT * DIM_];           // q projection (b,n,h*dh)
__device__ float g_kv [MTOT * 2 * DIM_];       // kv projection
__device__ float g_Qn [B_ * H_ * N_ * DH_];    // l2norm'd q, (b,h,n,d)
__device__ float g_K  [B_ * H_ * J_ * DH_];    // l2norm'd k incl nulls
__device__ float g_V  [B_ * H_ * J_ * DH_];    // v incl nulls

// ---------------- helpers ----------------
__device__ __forceinline__ void split_bf16(float v, __nv_bfloat16& hi, __nv_bfloat16& lo) {
    hi = __float2bfloat16_rn(v);
    lo = __float2bfloat16_rn(v - __bfloat162float(hi));
}

__device__ __forceinline__ void ldmx4(uint32_t* r, uint32_t addr) {
    asm volatile("ldmatrix.sync.aligned.m8n8.x4.shared.b16 {%0,%1,%2,%3}, [%4];"
                 : "=r"(r[0]), "=r"(r[1]), "=r"(r[2]), "=r"(r[3]) : "r"(addr));
}
__device__ __forceinline__ void ldmx2(uint32_t* r, uint32_t addr) {
    asm volatile("ldmatrix.sync.aligned.m8n8.x2.shared.b16 {%0,%1}, [%2];"
                 : "=r"(r[0]), "=r"(r[1]) : "r"(addr));
}
__device__ __forceinline__ void mma16816(float* d, const uint32_t* a, const uint32_t* b) {
    asm volatile("mma.sync.aligned.m16n8k16.row.col.f32.bf16.bf16.f32 {%0,%1,%2,%3},{%4,%5,%6,%7},{%8,%9},{%0,%1,%2,%3};"
                 : "+f"(d[0]), "+f"(d[1]), "+f"(d[2]), "+f"(d[3])
                 : "r"(a[0]), "r"(a[1]), "r"(a[2]), "r"(a[3]), "r"(b[0]), "r"(b[1]));
}

// ---------------- LayerNorm -> xn3 (A-side split layout) ----------------
__global__ void ln_kernel(const float* __restrict__ x,
                          const float* __restrict__ gamma,
                          __nv_bfloat16* __restrict__ xn3) {
    int row = blockIdx.x;
    const float* xr = x + (size_t)row * DIM_;
    float v[4];
    float s = 0.f, sq = 0.f;
#pragma unroll
    for (int i = 0; i < 4; i++) {
        float t = xr[threadIdx.x + i * 256];
        v[i] = t; s += t; sq += t * t;
    }
#pragma unroll
    for (int off = 16; off > 0; off >>= 1) {
        s  += __shfl_xor_sync(0xffffffffu, s,  off);
        sq += __shfl_xor_sync(0xffffffffu, sq, off);
    }
    __shared__ float sa[8], sb[8];
    int w = threadIdx.x >> 5, l = threadIdx.x & 31;
    if (l == 0) { sa[w] = s; sb[w] = sq; }
    __syncthreads();
    if (threadIdx.x == 0) {
        float a = 0.f, bq = 0.f;
#pragma unroll
        for (int i = 0; i < 8; i++) { a += sa[i]; bq += sb[i]; }
        sa[0] = a; sb[0] = bq;
    }
    __syncthreads();
    float mean = sa[0] * (1.0f / DIM_);
    float var  = sb[0] * (1.0f / DIM_) - mean * mean;
    float rstd = rsqrtf(var + 1e-5f);
    __nv_bfloat16* outr = xn3 + (size_t)row * KP;
#pragma unroll
    for (int i = 0; i < 4; i++) {
        int d = threadIdx.x + i * 256;
        float o = (v[i] - mean) * rstd * gamma[d];
        __nv_bfloat16 hi, lo; split_bf16(o, hi, lo);
        outr[d] = hi; outr[DIM_ + d] = lo; outr[2 * DIM_ + d] = hi;
    }
}

// ---------------- x -> x3 (A-side split) ----------------
__global__ void aconv_kernel(const float* __restrict__ X, __nv_bfloat16* __restrict__ X3) {
    int i = blockIdx.x * blockDim.x + threadIdx.x;
    if (i >= MTOT * DIM_) return;
    int r = i >> 10, c = i & (DIM_ - 1);
    float vv = X[i];
    __nv_bfloat16 hi, lo; split_bf16(vv, hi, lo);
    __nv_bfloat16* o = X3 + (size_t)r * KP;
    o[c] = hi; o[DIM_ + c] = lo; o[2 * DIM_ + c] = hi;
}

// ---------------- W [K=1024][N] -> W3T [N][KP] (B-side split, transposed) ----------------
__global__ void wconv_kernel(const float* __restrict__ W, __nv_bfloat16* __restrict__ W3T, int N) {
    __shared__ float t[32][33];
    int k0 = blockIdx.y * 32, n0 = blockIdx.x * 32;
    int tx = threadIdx.x, ty = threadIdx.y;   // 32 x 8
#pragma unroll
    for (int i = 0; i < 4; i++)
        t[ty + i * 8][tx] = W[(size_t)(k0 + ty + i * 8) * N + n0 + tx];
    __syncthreads();
#pragma unroll
    for (int i = 0; i < 4; i++) {
        int n = n0 + ty + i * 8;
        int k = k0 + tx;
        float w = t[tx][ty + i * 8];
        __nv_bfloat16 hi, lo; split_bf16(w, hi, lo);
        __nv_bfloat16* o = W3T + (size_t)n * KP;
        o[k] = hi; o[DIM_ + k] = hi; o[2 * DIM_ + k] = lo;
    }
}

// ---------------- bf16 HMMA GEMM: C[M,N] = A3[M,KP] @ B3T[N,KP]^T ----------------
#define BK 32
#define STRIDE 40
#define TSZ (128 * STRIDE)

__global__ void __launch_bounds__(256, 1) hgemm_kernel(
        const __nv_bfloat16* __restrict__ A,   // [M][KP]
        const __nv_bfloat16* __restrict__ BT,  // [N][KP]
        float* __restrict__ C, int M, int N) {
    __shared__ __nv_bfloat16 As[2 * TSZ];
    __shared__ __nv_bfloat16 Bs[2 * TSZ];

    const int tid  = threadIdx.x;
    const int wid  = tid >> 5, lane = tid & 31;
    const int wm   = wid & 1, wn = wid >> 1;      // warp tile 64(M) x 32(N)
    const int g    = lane >> 2, tig = lane & 3;

    const int row0 = blockIdx.y * 128;
    const int col0 = blockIdx.x * 128;

    // global loaders: 2 float4-rows per tile each
    const int lr = tid >> 2;              // 0..63
    const int lc = (tid & 3) * 8;         // 0,8,16,24
    const __nv_bfloat16* Ag = A  + (size_t)(row0 + lr) * KP + lc;
    const __nv_bfloat16* Bg = BT + (size_t)(col0 + lr) * KP + lc;

    float acc[4][4][4];
#pragma unroll
    for (int mi = 0; mi < 4; mi++)
#pragma unroll
        for (int ni = 0; ni < 4; ni++)
#pragma unroll
            for (int e = 0; e < 4; e++) acc[mi][ni][e] = 0.f;

    uint32_t a_base = (uint32_t)__cvta_generic_to_shared(As);
    uint32_t b_base = (uint32_t)__cvta_generic_to_shared(Bs);

    // ldmatrix per-lane offsets (elements)
    const int a_row_in = lane & 15;             // row within 16
    const int a_k_in   = (lane >> 4) << 3;      // 0 or 8
    const int b_row_in = lane & 7;
    const int b_k_in   = ((lane >> 3) & 1) << 3;

    // preload stage 0
    {
        uint4 ra0 = *(const uint4*)(Ag);
        uint4 ra1 = *(const uint4*)(Ag + (size_t)64 * KP);
        uint4 rb0 = *(const uint4*)(Bg);
        uint4 rb1 = *(const uint4*)(Bg + (size_t)64 * KP);
        *(uint4*)&As[lr * STRIDE + lc]        = ra0;
        *(uint4*)&As[(lr + 64) * STRIDE + lc] = ra1;
        *(uint4*)&Bs[lr * STRIDE + lc]        = rb0;
        *(uint4*)&Bs[(lr + 64) * STRIDE + lc] = rb1;
    }
    __syncthreads();

    int buf = 0;
    for (int kt = 0; kt < KP; kt += BK) {
        const bool has_next = (kt + BK) < KP;
        uint4 ra0, ra1, rb0, rb1;
        if (has_next) {
            ra0 = *(const uint4*)(Ag + kt + BK);
            ra1 = *(const uint4*)(Ag + (size_t)64 * KP + kt + BK);
            rb0 = *(const uint4*)(Bg + kt + BK);
            rb1 = *(const uint4*)(Bg + (size_t)64 * KP + kt + BK);
        }

        const uint32_t abuf = a_base + buf * (TSZ * 2);
        const uint32_t bbuf = b_base + buf * (TSZ * 2);
#pragma unroll
        for (int kk = 0; kk < BK; kk += 16) {
            uint32_t afr[4][4];
            uint32_t bfr[4][2];
#pragma unroll
            for (int mi = 0; mi < 4; mi++) {
                uint32_t a_addr = abuf +
                    (uint32_t)(((wm * 64 + mi * 16 + a_row_in) * STRIDE + kk + a_k_in) << 1);
                ldmx4(afr[mi], a_addr);
            }
#pragma unroll
            for (int ni = 0; ni < 4; ni++) {
                uint32_t b_addr = bbuf +
                    (uint32_t)(((wn * 32 + ni * 8 + b_row_in) * STRIDE + kk + b_k_in) << 1);
                ldmx2(bfr[ni], b_addr);
            }
#pragma unroll
            for (int mi = 0; mi < 4; mi++)
#pragma unroll
                for (int ni = 0; ni < 4; ni++)
                    mma16816(acc[mi][ni], afr[mi], bfr[ni]);
        }

        if (has_next) {
            __nv_bfloat16* as = &As[(buf ^ 1) * TSZ];
            __nv_bfloat16* bs = &Bs[(buf ^ 1) * TSZ];
            *(uint4*)&as[lr * STRIDE + lc]        = ra0;
            *(uint4*)&as[(lr + 64) * STRIDE + lc] = ra1;
            *(uint4*)&bs[lr * STRIDE + lc]        = rb0;
            *(uint4*)&bs[(lr + 64) * STRIDE + lc] = rb1;
            __syncthreads();
            buf ^= 1;
        }
    }

    // epilogue
#pragma unroll
    for (int mi = 0; mi < 4; mi++) {
        int r0 = row0 + wm * 64 + mi * 16 + g;
#pragma unroll
        for (int ni = 0; ni < 4; ni++) {
            int cc = col0 + wn * 32 + ni * 8 + tig * 2;
            float2 v0 = { acc[mi][ni][0], acc[mi][ni][1] };
            float2 v1 = { acc[mi][ni][2], acc[mi][ni][3] };
            *(float2*)&C[(size_t)r0 * N + cc]       = v0;
            *(float2*)&C[(size_t)(r0 + 8) * N + cc] = v1;
        }
    }
}

// ---------------- prep: build Qn (l2norm*q_scale), K (nulls + l2norm*k_scale), V ----------------
__global__ void prep_kernel(const float* __restrict__ q,
                            const float* __restrict__ kv,
                            const float* __restrict__ null_kv,
                            const float* __restrict__ q_scale,
                            const float* __restrict__ k_scale,
                            float* __restrict__ Qn,
                            float* __restrict__ Kk,
                            float* __restrict__ Vv) {
    int warp = (blockIdx.x * blockDim.x + threadIdx.x) >> 5;
    int lane = threadIdx.x & 31;
    if (warp >= B_ * H_ * J_) return;
    int bh = warp / J_;
    int j  = warp % J_;
    int b = bh / H_, h = bh % H_;
    int d0 = lane, d1 = lane + 32;

    float k0, k1, v0, v1;
    if (j < NNK_) {
        const float* nb = null_kv + ((size_t)(h * NNK_ + j) * 2) * DH_;
        k0 = nb[d0];        k1 = nb[d1];
        v0 = nb[DH_ + d0];  v1 = nb[DH_ + d1];
    } else {
        int n = j - NNK_;
        const float* base = kv + ((size_t)(b * N_ + n)) * (2 * DIM_) + h * DH_;
        k0 = base[d0];          k1 = base[d1];
        v0 = base[DIM_ + d0];   v1 = base[DIM_ + d1];
    }
    float ss = k0 * k0 + k1 * k1;
#pragma unroll
    for (int off = 16; off > 0; off >>= 1)
        ss += __shfl_xor_sync(0xffffffffu, ss, off);
    float inv = 1.0f / fmaxf(sqrtf(ss), 1e-12f);
    size_t kvo = ((size_t)bh * J_ + j) * DH_;
    Kk[kvo + d0] = k0 * inv * k_scale[d0];
    Kk[kvo + d1] = k1 * inv * k_scale[d1];
    Vv[kvo + d0] = v0;
    Vv[kvo + d1] = v1;

    if (j < N_) {
        int n = j;
        const float* qb = q + ((size_t)(b * N_ + n)) * DIM_ + h * DH_;
        float a0 = qb[d0], a1 = qb[d1];
        float qs2 = a0 * a0 + a1 * a1;
#pragma unroll
        for (int off = 16; off > 0; off >>= 1)
            qs2 += __shfl_xor_sync(0xffffffffu, qs2, off);
        float qinv = 1.0f / fmaxf(sqrtf(qs2), 1e-12f);
        size_t qo = ((size_t)bh * N_ + n) * DH_;
        Qn[qo + d0] = a0 * qinv * q_scale[d0];
        Qn[qo + d1] = a1 * qinv * q_scale[d1];
    }
}

// ---------------- flash attention: 64x64 tiles, online softmax, causal skip ----------------
#define SPAD 68
__global__ void __launch_bounds__(256) attn_kernel(
        const float* __restrict__ Qn, const float* __restrict__ Kk,
        const float* __restrict__ Vv, const float* __restrict__ bias,
        const int* __restrict__ mask,
        __nv_bfloat16* __restrict__ att3) {
    extern __shared__ float sh[];
    float* Qs  = sh;
    float* KsT = Qs  + 64 * SPAD;
    float* Vs  = KsT + 64 * SPAD;
    float* Ss  = Vs  + 64 * SPAD;

    const int tid = threadIdx.x;
    const int tx = tid & 15, ty = tid >> 4;
    const int ib = blockIdx.x;
    const int bh = blockIdx.y;
    const int b = bh >> 4, h = bh & 15;
    const int i0 = ib * 64;

    const float* Qbase = Qn + ((size_t)bh * N_ + i0) * DH_;
#pragma unroll
    for (int fi = tid; fi < 64 * 16; fi += 256) {
        int r = fi >> 4, c4 = (fi & 15) << 2;
        *(float4*)&Qs[r * SPAD + c4] = *(const float4*)(Qbase + (size_t)r * DH_ + c4);
    }

    float m[4], lsum[4], acc[4][4];
#pragma unroll
    for (int r = 0; r < 4; r++) {
        m[r] = -1e30f; lsum[r] = 0.f;
#pragma unroll
        for (int c = 0; c < 4; c++) acc[r][c] = 0.f;
    }

    const int jt_max = min(ib + 1, (J_ + 63) / 64 - 1);

    for (int jt = 0; jt <= jt_max; jt++) {
        const int j0 = jt * 64;
        __syncthreads();
        for (int fi = tid; fi < 64 * 16; fi += 256) {
            int r = fi >> 4, c4 = (fi & 15) << 2;
            int j = j0 + r;
            if (j < J_) {
                float4 k4 = *(const float4*)(Kk + ((size_t)bh * J_ + j) * DH_ + c4);
                KsT[(c4 + 0) * SPAD + r] = k4.x;
                KsT[(c4 + 1) * SPAD + r] = k4.y;
                KsT[(c4 + 2) * SPAD + r] = k4.z;
                KsT[(c4 + 3) * SPAD + r] = k4.w;
                *(float4*)&Vs[r * SPAD + c4] =
                    *(const float4*)(Vv + ((size_t)bh * J_ + j) * DH_ + c4);
            } else {
                KsT[(c4 + 0) * SPAD + r] = 0.f;
                KsT[(c4 + 1) * SPAD + r] = 0.f;
                KsT[(c4 + 2) * SPAD + r] = 0.f;
                KsT[(c4 + 3) * SPAD + r] = 0.f;
                float4 z = {0.f, 0.f, 0.f, 0.f};
                *(float4*)&Vs[r * SPAD + c4] = z;
            }
        }
        __syncthreads();

        float s[4][4];
#pragma unroll
        for (int r = 0; r < 4; r++)
#pragma unroll
            for (int c = 0; c < 4; c++) s[r][c] = 0.f;

#pragma unroll 4
        for (int d = 0; d < 64; d++) {
            float qr[4];
#pragma unroll
            for (int r = 0; r < 4; r++) qr[r] = Qs[(ty * 4 + r) * SPAD + d];
            float4 k4 = *(const float4*)&KsT[d * SPAD + tx * 4];
            float kr[4] = { k4.x, k4.y, k4.z, k4.w };
#pragma unroll
            for (int r = 0; r < 4; r++)
#pragma unroll
                for (int c = 0; c < 4; c++)
                    s[r][c] += qr[r] * kr[c];
        }

#pragma unroll
        for (int r = 0; r < 4; r++) {
            int ig = i0 + ty * 4 + r;
#pragma unroll
            for (int c = 0; c < 4; c++) {
                int jg = j0 + tx * 4 + c;
                float val = s[r][c] * SCALE_;
                bool ok = (jg < J_) && (jg <= ig + NNK_);
                if (jg >= NNK_ && ok) {
                    val += bias[((size_t)h * N_ + ig) * N_ + (jg - NNK_)];
                    ok = (mask[b * N_ + jg - NNK_] != 0);
                }
                s[r][c] = ok ? val : -1e30f;
            }
        }

#pragma unroll
        for (int r = 0; r < 4; r++) {
            float rmax = fmaxf(fmaxf(s[r][0], s[r][1]), fmaxf(s[r][2], s[r][3]));
#pragma unroll
            for (int off = 8; off > 0; off >>= 1)
                rmax = fmaxf(rmax, __shfl_xor_sync(0xffffffffu, rmax, off));
            float mn = fmaxf(m[r], rmax);
            float corr = __expf(m[r] - mn);
            m[r] = mn;
            float rs = 0.f;
#pragma unroll
            for (int c = 0; c < 4; c++) {
                float p = __expf(s[r][c] - mn);
                s[r][c] = p; rs += p;
            }
#pragma unroll
            for (int off = 8; off > 0; off >>= 1)
                rs += __shfl_xor_sync(0xffffffffu, rs, off);
            lsum[r] = lsum[r] * corr + rs;
#pragma unroll
            for (int c = 0; c < 4; c++) acc[r][c] *= corr;
#pragma unroll
            for (int c = 0; c < 4; c++)
                Ss[(ty * 4 + r) * SPAD + tx * 4 + c] = s[r][c];
        }
        __syncthreads();

#pragma unroll 4
        for (int jj = 0; jj < 64; jj++) {
            float pr[4];
#pragma unroll
            for (int r = 0; r < 4; r++) pr[r] = Ss[(ty * 4 + r) * SPAD + jj];
            float4 v4 = *(const float4*)&Vs[jj * SPAD + tx * 4];
            float vr[4] = { v4.x, v4.y, v4.z, v4.w };
#pragma unroll
            for (int r = 0; r < 4; r++)
#pragma unroll
                for (int c = 0; c < 4; c++)
                    acc[r][c] += pr[r] * vr[c];
        }
    }

    // write attention output into A-side split layout [row][KP]
#pragma unroll
    for (int r = 0; r < 4; r++) {
        int ig = i0 + ty * 4 + r;
        float invl = 1.0f / lsum[r];
        __nv_bfloat16* o3 = att3 + ((size_t)(b * N_ + ig)) * KP + h * DH_ + tx * 4;
        __nv_bfloat16 hi[4], lo[4];
#pragma unroll
        for (int c = 0; c < 4; c++) split_bf16(acc[r][c] * invl, hi[c], lo[c]);
        *(__nv_bfloat162*)&o3[0]            = __halves2bfloat162(hi[0], hi[1]);
        *(__nv_bfloat162*)&o3[2]            = __halves2bfloat162(hi[2], hi[3]);
        *(__nv_bfloat162*)&o3[DIM_]         = __halves2bfloat162(lo[0], lo[1]);
        *(__nv_bfloat162*)&o3[DIM_ + 2]     = __halves2bfloat162(lo[2], lo[3]);
        *(__nv_bfloat162*)&o3[2 * DIM_]     = __halves2bfloat162(hi[0], hi[1]);
        *(__nv_bfloat162*)&o3[2 * DIM_ + 2] = __halves2bfloat162(hi[2], hi[3]);
    }
}

// ---------------- launch ----------------
extern "C" void kernel_launch(void* const* d_in, const int* in_sizes, int n_in,
                              void* d_out, int out_size) {
    const float* x     = (const float*)d_in[0];
    const int*   mask  = (const int*)d_in[1];
    const float* bias  = (const float*)d_in[2];
    const float* gamma = (const float*)d_in[3];
    const float* nkv   = (const float*)d_in[4];
    const float* Wq    = (const float*)d_in[5];
    const float* Wkv   = (const float*)d_in[6];
    const float* qsc   = (const float*)d_in[7];
    const float* ksc   = (const float*)d_in[8];
    const float* Wo    = (const float*)d_in[9];
    float* out = (float*)d_out;

    __nv_bfloat16 *p_x3, *p_xn3, *p_att3, *p_Wq3T, *p_Wkv3T, *p_Wo3T;
    float *p_q, *p_kv, *p_Qn, *p_K, *p_V;
    cudaGetSymbolAddress((void**)&p_x3,    g_x3);
    cudaGetSymbolAddress((void**)&p_xn3,   g_xn3);
    cudaGetSymbolAddress((void**)&p_att3,  g_att3);
    cudaGetSymbolAddress((void**)&p_Wq3T,  g_Wq3T);
    cudaGetSymbolAddress((void**)&p_Wkv3T, g_Wkv3T);
    cudaGetSymbolAddress((void**)&p_Wo3T,  g_Wo3T);
    cudaGetSymbolAddress((void**)&p_q,     g_q);
    cudaGetSymbolAddress((void**)&p_kv,    g_kv);
    cudaGetSymbolAddress((void**)&p_Qn,    g_Qn);
    cudaGetSymbolAddress((void**)&p_K,     g_K);
    cudaGetSymbolAddress((void**)&p_V,     g_V);

    // weight conversions (transpose + hi/lo split)
    dim3 wb(32, 8);
    wconv_kernel<<<dim3(DIM_ / 32,     DIM_ / 32), wb>>>(Wq,  p_Wq3T,  DIM_);
    wconv_kernel<<<dim3(2 * DIM_ / 32, DIM_ / 32), wb>>>(Wkv, p_Wkv3T, 2 * DIM_);
    wconv_kernel<<<dim3(DIM_ / 32,     DIM_ / 32), wb>>>(Wo,  p_Wo3T,  DIM_);

    // activation conversions
    aconv_kernel<<<(MTOT * DIM_ + 255) / 256, 256>>>(x, p_x3);
    ln_kernel<<<MTOT, 256>>>(x, gamma, p_xn3);

    // projections via bf16-split HMMA
    dim3 gq(DIM_ / 128, MTOT / 128);
    hgemm_kernel<<<gq, 256>>>(p_xn3, p_Wq3T, p_q, MTOT, DIM_);
    dim3 gkv(2 * DIM_ / 128, MTOT / 128);
    hgemm_kernel<<<gkv, 256>>>(p_x3, p_Wkv3T, p_kv, MTOT, 2 * DIM_);

    // l2norm q/k, assemble K/V with null kv
    int nwarp = B_ * H_ * J_;
    prep_kernel<<<(nwarp + 7) / 8, 256>>>(p_q, p_kv, nkv, qsc, ksc, p_Qn, p_K, p_V);

    // attention (emits split layout directly)
    int smem = 4 * 64 * SPAD * (int)sizeof(float);
    cudaFuncSetAttribute(attn_kernel, cudaFuncAttributeMaxDynamicSharedMemorySize, smem);
    dim3 ga(N_ / 64, B_ * H_);
    attn_kernel<<<ga, 256, smem>>>(p_Qn, p_K, p_V, bias, mask, p_att3);

    // output projection
    hgemm_kernel<<<gq, 256>>>(p_att3, p_Wo3T, out, MTOT, DIM_);
}

// round 6
// speedup vs baseline: 1.3921x; 1.3921x over previous
#include <cuda_runtime.h>
#include <cuda_bf16.h>
#include <math.h>
#include <stdint.h>

// ---------------- problem constants ----------------
#define B_    2
#define N_    2048
#define DIM_  1024
#define H_    16
#define DH_   64
#define NNK_  2
#define J_    (N_ + NNK_)    // 2050
#define J_PAD 2112           // 33 tiles of 64
#define SCALE_ 8.0f
#define KP    3072           // split-K' = 3 * DIM_
#define MTOT  (B_ * N_)      // 4096

// ---------------- scratch (device globals; no allocs allowed) ----------------
__device__ __align__(16) __nv_bfloat16 g_x3   [MTOT * KP];      // [Ahi|Alo|Ahi] of x
__device__ __align__(16) __nv_bfloat16 g_xn3  [MTOT * KP];      // of layernorm(x)
__device__ __align__(16) __nv_bfloat16 g_att3 [MTOT * KP];      // of attention out
__device__ __align__(16) __nv_bfloat16 g_Wq3T [DIM_ * KP];      // [N=1024][Bhi|Bhi|Blo]
__device__ __align__(16) __nv_bfloat16 g_Wkv3T[2 * DIM_ * KP];  // [N=2048][...]
__device__ __align__(16) __nv_bfloat16 g_Wo3T [DIM_ * KP];
__device__ float g_q  [MTOT * DIM_];           // q projection (b,n,h*dh)
__device__ float g_kv [MTOT * 2 * DIM_];       // kv projection
// attention operands, pre-split bf16 (padding rows stay zero-initialized)
__device__ __align__(16) __nv_bfloat16 g_Q3 [B_ * H_ * N_ * 192];     // [Qhi|Qlo|Qhi]
__device__ __align__(16) __nv_bfloat16 g_K3 [B_ * H_ * J_PAD * 192];  // [Khi|Khi|Klo]
__device__ __align__(16) __nv_bfloat16 g_V3 [B_ * H_ * J_PAD * 128];  // [Vhi|Vlo]

// ---------------- helpers ----------------
__device__ __forceinline__ void split_bf16(float v, __nv_bfloat16& hi, __nv_bfloat16& lo) {
    hi = __float2bfloat16_rn(v);
    lo = __float2bfloat16_rn(v - __bfloat162float(hi));
}
__device__ __forceinline__ uint32_t bpack(__nv_bfloat16 a, __nv_bfloat16 b) {
    __nv_bfloat162 t = __halves2bfloat162(a, b);
    return *reinterpret_cast<uint32_t*>(&t);
}
__device__ __forceinline__ void ldmx4(uint32_t* r, uint32_t addr) {
    asm volatile("ldmatrix.sync.aligned.m8n8.x4.shared.b16 {%0,%1,%2,%3}, [%4];"
                 : "=r"(r[0]), "=r"(r[1]), "=r"(r[2]), "=r"(r[3]) : "r"(addr));
}
__device__ __forceinline__ void ldmx2(uint32_t* r, uint32_t addr) {
    asm volatile("ldmatrix.sync.aligned.m8n8.x2.shared.b16 {%0,%1}, [%2];"
                 : "=r"(r[0]), "=r"(r[1]) : "r"(addr));
}
__device__ __forceinline__ void ldmx2t(uint32_t* r, uint32_t addr) {
    asm volatile("ldmatrix.sync.aligned.m8n8.x2.trans.shared.b16 {%0,%1}, [%2];"
                 : "=r"(r[0]), "=r"(r[1]) : "r"(addr));
}
__device__ __forceinline__ void mma16816(float* d, const uint32_t* a, const uint32_t* b) {
    asm volatile("mma.sync.aligned.m16n8k16.row.col.f32.bf16.bf16.f32 {%0,%1,%2,%3},{%4,%5,%6,%7},{%8,%9},{%0,%1,%2,%3};"
                 : "+f"(d[0]), "+f"(d[1]), "+f"(d[2]), "+f"(d[3])
                 : "r"(a[0]), "r"(a[1]), "r"(a[2]), "r"(a[3]), "r"(b[0]), "r"(b[1]));
}
__device__ __forceinline__ void cp16(uint32_t saddr, const void* gptr) {
    asm volatile("cp.async.cg.shared.global [%0], [%1], 16;" :: "r"(saddr), "l"(gptr));
}
__device__ __forceinline__ void cp_commit() { asm volatile("cp.async.commit_group;"); }
__device__ __forceinline__ void cp_wait1() { asm volatile("cp.async.wait_group 1;"); }

// ---------------- LayerNorm -> xn3 (A-side split layout) ----------------
__global__ void ln_kernel(const float* __restrict__ x,
                          const float* __restrict__ gamma,
                          __nv_bfloat16* __restrict__ xn3) {
    int row = blockIdx.x;
    const float* xr = x + (size_t)row * DIM_;
    float v[4];
    float s = 0.f, sq = 0.f;
#pragma unroll
    for (int i = 0; i < 4; i++) {
        float t = xr[threadIdx.x + i * 256];
        v[i] = t; s += t; sq += t * t;
    }
#pragma unroll
    for (int off = 16; off > 0; off >>= 1) {
        s  += __shfl_xor_sync(0xffffffffu, s,  off);
        sq += __shfl_xor_sync(0xffffffffu, sq, off);
    }
    __shared__ float sa[8], sb[8];
    int w = threadIdx.x >> 5, l = threadIdx.x & 31;
    if (l == 0) { sa[w] = s; sb[w] = sq; }
    __syncthreads();
    if (threadIdx.x == 0) {
        float a = 0.f, bq = 0.f;
#pragma unroll
        for (int i = 0; i < 8; i++) { a += sa[i]; bq += sb[i]; }
        sa[0] = a; sb[0] = bq;
    }
    __syncthreads();
    float mean = sa[0] * (1.0f / DIM_);
    float var  = sb[0] * (1.0f / DIM_) - mean * mean;
    float rstd = rsqrtf(var + 1e-5f);
    __nv_bfloat16* outr = xn3 + (size_t)row * KP;
#pragma unroll
    for (int i = 0; i < 4; i++) {
        int d = threadIdx.x + i * 256;
        float o = (v[i] - mean) * rstd * gamma[d];
        __nv_bfloat16 hi, lo; split_bf16(o, hi, lo);
        outr[d] = hi; outr[DIM_ + d] = lo; outr[2 * DIM_ + d] = hi;
    }
}

// ---------------- x -> x3 (A-side split) ----------------
__global__ void aconv_kernel(const float* __restrict__ X, __nv_bfloat16* __restrict__ X3) {
    int i = blockIdx.x * blockDim.x + threadIdx.x;
    if (i >= MTOT * DIM_) return;
    int r = i >> 10, c = i & (DIM_ - 1);
    float vv = X[i];
    __nv_bfloat16 hi, lo; split_bf16(vv, hi, lo);
    __nv_bfloat16* o = X3 + (size_t)r * KP;
    o[c] = hi; o[DIM_ + c] = lo; o[2 * DIM_ + c] = hi;
}

// ---------------- W [K=1024][N] -> W3T [N][KP] (B-side split, transposed) ----------------
__global__ void wconv_kernel(const float* __restrict__ W, __nv_bfloat16* __restrict__ W3T, int N) {
    __shared__ float t[32][33];
    int k0 = blockIdx.y * 32, n0 = blockIdx.x * 32;
    int tx = threadIdx.x, ty = threadIdx.y;   // 32 x 8
#pragma unroll
    for (int i = 0; i < 4; i++)
        t[ty + i * 8][tx] = W[(size_t)(k0 + ty + i * 8) * N + n0 + tx];
    __syncthreads();
#pragma unroll
    for (int i = 0; i < 4; i++) {
        int n = n0 + ty + i * 8;
        int k = k0 + tx;
        float w = t[tx][ty + i * 8];
        __nv_bfloat16 hi, lo; split_bf16(w, hi, lo);
        __nv_bfloat16* o = W3T + (size_t)n * KP;
        o[k] = hi; o[DIM_ + k] = hi; o[2 * DIM_ + k] = lo;
    }
}

// ---------------- bf16 HMMA GEMM: C[M,N] = A3[M,KP] @ B3T[N,KP]^T ----------------
#define BK 32
#define STRIDE 40
#define TSZ (128 * STRIDE)

__global__ void __launch_bounds__(256, 1) hgemm_kernel(
        const __nv_bfloat16* __restrict__ A,   // [M][KP]
        const __nv_bfloat16* __restrict__ BT,  // [N][KP]
        float* __restrict__ C, int M, int N) {
    __shared__ __nv_bfloat16 As[2 * TSZ];
    __shared__ __nv_bfloat16 Bs[2 * TSZ];

    const int tid  = threadIdx.x;
    const int wid  = tid >> 5, lane = tid & 31;
    const int wm   = wid & 1, wn = wid >> 1;
    const int g    = lane >> 2, tig = lane & 3;

    const int row0 = blockIdx.y * 128;
    const int col0 = blockIdx.x * 128;

    const int lr = tid >> 2;
    const int lc = (tid & 3) * 8;
    const __nv_bfloat16* Ag = A  + (size_t)(row0 + lr) * KP + lc;
    const __nv_bfloat16* Bg = BT + (size_t)(col0 + lr) * KP + lc;

    float acc[4][4][4];
#pragma unroll
    for (int mi = 0; mi < 4; mi++)
#pragma unroll
        for (int ni = 0; ni < 4; ni++)
#pragma unroll
            for (int e = 0; e < 4; e++) acc[mi][ni][e] = 0.f;

    uint32_t a_base = (uint32_t)__cvta_generic_to_shared(As);
    uint32_t b_base = (uint32_t)__cvta_generic_to_shared(Bs);

    const int a_row_in = lane & 15;
    const int a_k_in   = (lane >> 4) << 3;
    const int b_row_in = lane & 7;
    const int b_k_in   = ((lane >> 3) & 1) << 3;

    {
        uint4 ra0 = *(const uint4*)(Ag);
        uint4 ra1 = *(const uint4*)(Ag + (size_t)64 * KP);
        uint4 rb0 = *(const uint4*)(Bg);
        uint4 rb1 = *(const uint4*)(Bg + (size_t)64 * KP);
        *(uint4*)&As[lr * STRIDE + lc]        = ra0;
        *(uint4*)&As[(lr + 64) * STRIDE + lc] = ra1;
        *(uint4*)&Bs[lr * STRIDE + lc]        = rb0;
        *(uint4*)&Bs[(lr + 64) * STRIDE + lc] = rb1;
    }
    __syncthreads();

    int buf = 0;
    for (int kt = 0; kt < KP; kt += BK) {
        const bool has_next = (kt + BK) < KP;
        uint4 ra0, ra1, rb0, rb1;
        if (has_next) {
            ra0 = *(const uint4*)(Ag + kt + BK);
            ra1 = *(const uint4*)(Ag + (size_t)64 * KP + kt + BK);
            rb0 = *(const uint4*)(Bg + kt + BK);
            rb1 = *(const uint4*)(Bg + (size_t)64 * KP + kt + BK);
        }

        const uint32_t abuf = a_base + buf * (TSZ * 2);
        const uint32_t bbuf = b_base + buf * (TSZ * 2);
#pragma unroll
        for (int kk = 0; kk < BK; kk += 16) {
            uint32_t afr[4][4];
            uint32_t bfr[4][2];
#pragma unroll
            for (int mi = 0; mi < 4; mi++) {
                uint32_t a_addr = abuf +
                    (uint32_t)(((wm * 64 + mi * 16 + a_row_in) * STRIDE + kk + a_k_in) << 1);
                ldmx4(afr[mi], a_addr);
            }
#pragma unroll
            for (int ni = 0; ni < 4; ni++) {
                uint32_t b_addr = bbuf +
                    (uint32_t)(((wn * 32 + ni * 8 + b_row_in) * STRIDE + kk + b_k_in) << 1);
                ldmx2(bfr[ni], b_addr);
            }
#pragma unroll
            for (int mi = 0; mi < 4; mi++)
#pragma unroll
                for (int ni = 0; ni < 4; ni++)
                    mma16816(acc[mi][ni], afr[mi], bfr[ni]);
        }

        if (has_next) {
            __nv_bfloat16* as = &As[(buf ^ 1) * TSZ];
            __nv_bfloat16* bs = &Bs[(buf ^ 1) * TSZ];
            *(uint4*)&as[lr * STRIDE + lc]        = ra0;
            *(uint4*)&as[(lr + 64) * STRIDE + lc] = ra1;
            *(uint4*)&bs[lr * STRIDE + lc]        = rb0;
            *(uint4*)&bs[(lr + 64) * STRIDE + lc] = rb1;
            __syncthreads();
            buf ^= 1;
        }
    }

#pragma unroll
    for (int mi = 0; mi < 4; mi++) {
        int r0 = row0 + wm * 64 + mi * 16 + g;
#pragma unroll
        for (int ni = 0; ni < 4; ni++) {
            int cc = col0 + wn * 32 + ni * 8 + tig * 2;
            float2 v0 = { acc[mi][ni][0], acc[mi][ni][1] };
            float2 v1 = { acc[mi][ni][2], acc[mi][ni][3] };
            *(float2*)&C[(size_t)r0 * N + cc]       = v0;
            *(float2*)&C[(size_t)(r0 + 8) * N + cc] = v1;
        }
    }
}

// ---------------- prep: emit pre-split bf16 Q3/K3/V3 ----------------
__global__ void prep_kernel(const float* __restrict__ q,
                            const float* __restrict__ kv,
                            const float* __restrict__ null_kv,
                            const float* __restrict__ q_scale,
                            const float* __restrict__ k_scale,
                            __nv_bfloat16* __restrict__ Q3,
                            __nv_bfloat16* __restrict__ K3,
                            __nv_bfloat16* __restrict__ V3) {
    int warp = (blockIdx.x * blockDim.x + threadIdx.x) >> 5;
    int lane = threadIdx.x & 31;
    if (warp >= B_ * H_ * J_) return;
    int bh = warp / J_;
    int j  = warp % J_;
    int b = bh / H_, h = bh % H_;
    int d0 = lane, d1 = lane + 32;

    float k0, k1, v0, v1;
    if (j < NNK_) {
        const float* nb = null_kv + ((size_t)(h * NNK_ + j) * 2) * DH_;
        k0 = nb[d0];        k1 = nb[d1];
        v0 = nb[DH_ + d0];  v1 = nb[DH_ + d1];
    } else {
        int n = j - NNK_;
        const float* base = kv + ((size_t)(b * N_ + n)) * (2 * DIM_) + h * DH_;
        k0 = base[d0];          k1 = base[d1];
        v0 = base[DIM_ + d0];   v1 = base[DIM_ + d1];
    }
    float ss = k0 * k0 + k1 * k1;
#pragma unroll
    for (int off = 16; off > 0; off >>= 1)
        ss += __shfl_xor_sync(0xffffffffu, ss, off);
    float inv = 1.0f / fmaxf(sqrtf(ss), 1e-12f);
    float ks0 = k0 * inv * k_scale[d0];
    float ks1 = k1 * inv * k_scale[d1];

    __nv_bfloat16 h0, l0, h1, l1;
    size_t ko = ((size_t)bh * J_PAD + j) * 192;
    split_bf16(ks0, h0, l0); split_bf16(ks1, h1, l1);
    K3[ko + d0] = h0; K3[ko + 64 + d0] = h0; K3[ko + 128 + d0] = l0;
    K3[ko + d1] = h1; K3[ko + 64 + d1] = h1; K3[ko + 128 + d1] = l1;

    size_t vo = ((size_t)bh * J_PAD + j) * 128;
    split_bf16(v0, h0, l0); split_bf16(v1, h1, l1);
    V3[vo + d0] = h0; V3[vo + 64 + d0] = l0;
    V3[vo + d1] = h1; V3[vo + 64 + d1] = l1;

    if (j < N_) {
        int n = j;
        const float* qb = q + ((size_t)(b * N_ + n)) * DIM_ + h * DH_;
        float a0 = qb[d0], a1 = qb[d1];
        float qs2 = a0 * a0 + a1 * a1;
#pragma unroll
        for (int off = 16; off > 0; off >>= 1)
            qs2 += __shfl_xor_sync(0xffffffffu, qs2, off);
        float qinv = 1.0f / fmaxf(sqrtf(qs2), 1e-12f);
        float q0 = a0 * qinv * q_scale[d0];
        float q1 = a1 * qinv * q_scale[d1];
        size_t qo = ((size_t)bh * N_ + n) * 192;
        split_bf16(q0, h0, l0); split_bf16(q1, h1, l1);
        Q3[qo + d0] = h0; Q3[qo + 64 + d0] = l0; Q3[qo + 128 + d0] = h0;
        Q3[qo + d1] = h1; Q3[qo + 64 + d1] = l1; Q3[qo + 128 + d1] = h1;
    }
}

// ---------------- HMMA flash attention ----------------
// block: 256 thr = 8 warps, 128 i-rows (16 per warp), j-tiles of 64.
// smem layout (bytes): Qs[128][200] @0 (51200), Ks[2][64][200] @51200 (2x25600),
//                      Vs[2][64][136] @102400 (2x17408), mmul[2][64] @137216 (512)
#define QS_OFF   0
#define KS_OFF   51200
#define KS_SZ    25600
#define VS_OFF   102400
#define VS_SZ    17408
#define MM_OFF   137216
#define SMEM_ATT 137728

__device__ __forceinline__ float softel(float s, int ig, int jg, int h,
                                        const float* __restrict__ bias) {
    bool ok = (jg <= ig + NNK_) && (jg < J_);
    float bv = 0.f;
    if (ok && jg >= NNK_) bv = __ldg(bias + ((size_t)h * N_ + ig) * N_ + (jg - NNK_));
    float t = fmaf(s, 11.541560327111707f, fmaf(bv, 1.4426950408889634f, -23.083120654223414f));
    float r;
    asm("ex2.approx.f32 %0, %1;" : "=f"(r) : "f"(t));
    return ok ? r : 0.f;
}

__device__ __forceinline__ void load_tile(int stage, int j0, int bh, int b, int tid,
        uint32_t sbase, char* smx,
        const __nv_bfloat16* __restrict__ K3, const __nv_bfloat16* __restrict__ V3,
        const int* __restrict__ mask) {
    uint32_t ks = sbase + KS_OFF + stage * KS_SZ;
    uint32_t vs = sbase + VS_OFF + stage * VS_SZ;
#pragma unroll
    for (int i = 0; i < 6; i++) {
        int idx = i * 256 + tid;
        int row = idx / 24, c = idx % 24;
        const void* src = K3 + ((size_t)bh * J_PAD + j0 + row) * 192 + c * 8;
        cp16(ks + (uint32_t)((row * 200 + c * 8) * 2), src);
    }
#pragma unroll
    for (int i = 0; i < 4; i++) {
        int idx = i * 256 + tid;
        int row = idx / 16, c = idx % 16;
        const void* src = V3 + ((size_t)bh * J_PAD + j0 + row) * 128 + c * 8;
        cp16(vs + (uint32_t)((row * 136 + c * 8) * 2), src);
    }
    if (tid < 64) {
        int jg = j0 + tid;
        float mm = 1.f;
        if (jg >= NNK_) mm = (jg < J_ && mask[b * N_ + jg - NNK_] != 0) ? 1.f : 0.f;
        ((float*)(smx + MM_OFF))[stage * 64 + tid] = mm;
    }
}

__global__ void __launch_bounds__(256, 1) attn_mma_kernel(
        const __nv_bfloat16* __restrict__ Q3, const __nv_bfloat16* __restrict__ K3,
        const __nv_bfloat16* __restrict__ V3, const float* __restrict__ bias,
        const int* __restrict__ mask, __nv_bfloat16* __restrict__ att3) {
    extern __shared__ char smx[];
    const uint32_t sbase = (uint32_t)__cvta_generic_to_shared(smx);

    const int tid = threadIdx.x;
    const int w = tid >> 5, lane = tid & 31;
    const int g = lane >> 2, tig = lane & 3;
    const int i0 = blockIdx.x * 128;
    const int bh = blockIdx.y, b = bh >> 4, h = bh & 15;
    const int iw = i0 + w * 16;
    const int ig0 = iw + g, ig1 = ig0 + 8;

    const int jtmax = min((i0 + 129) >> 6, J_PAD / 64 - 1);

    // Q loads (group 0, along with tile 0)
#pragma unroll
    for (int i = 0; i < 12; i++) {
        int idx = i * 256 + tid;
        int row = idx / 24, c = idx % 24;
        const void* src = Q3 + ((size_t)bh * N_ + i0 + row) * 192 + c * 8;
        cp16(sbase + QS_OFF + (uint32_t)((row * 200 + c * 8) * 2), src);
    }
    load_tile(0, 0, bh, b, tid, sbase, smx, K3, V3, mask);
    cp_commit();

    float oacc[8][4];
#pragma unroll
    for (int d = 0; d < 8; d++)
#pragma unroll
        for (int e = 0; e < 4; e++) oacc[d][e] = 0.f;
    float lsum0 = 0.f, lsum1 = 0.f;

    int buf = 0;
    for (int jt = 0; jt <= jtmax; jt++) {
        const int j0 = jt * 64;
        if (jt < jtmax)
            load_tile(buf ^ 1, j0 + 64, bh, b, tid, sbase, smx, K3, V3, mask);
        cp_commit();
        cp_wait1();
        __syncthreads();

        const bool active = (j0 <= iw + 15 + NNK_);
        if (active) {
            const uint32_t ks = sbase + KS_OFF + buf * KS_SZ;
            const uint32_t vs = sbase + VS_OFF + buf * VS_SZ;
            const float* mm = (const float*)(smx + MM_OFF) + buf * 64;

            // ---- S = Q @ K^T over K'=192 ----
            float sacc[8][4];
#pragma unroll
            for (int jf = 0; jf < 8; jf++)
#pragma unroll
                for (int e = 0; e < 4; e++) sacc[jf][e] = 0.f;

            const int a_row = w * 16 + (lane & 15);
            const int a_kin = (lane >> 4) << 3;
            const int b_row = lane & 7;
            const int b_kin = ((lane >> 3) & 1) << 3;
            for (int kc = 0; kc < 12; kc++) {
                uint32_t a[4];
                ldmx4(a, sbase + QS_OFF + (uint32_t)(((a_row) * 200 + kc * 16 + a_kin) << 1));
#pragma unroll
                for (int jf = 0; jf < 8; jf++) {
                    uint32_t bb[2];
                    ldmx2(bb, ks + (uint32_t)(((jf * 8 + b_row) * 200 + kc * 16 + b_kin) << 1));
                    mma16816(sacc[jf], a, bb);
                }
            }

            // ---- softmax (fixed offset) + split P to bf16 hi/lo frags ----
            uint32_t phi2[8][2], plo2[8][2];
#pragma unroll
            for (int jf = 0; jf < 8; jf++) {
                int jc = j0 + jf * 8 + tig * 2;
                float m0 = mm[jf * 8 + tig * 2];
                float m1 = mm[jf * 8 + tig * 2 + 1];
                float p0 = softel(sacc[jf][0], ig0, jc,     h, bias) * m0;
                float p1 = softel(sacc[jf][1], ig0, jc + 1, h, bias) * m1;
                float p2 = softel(sacc[jf][2], ig1, jc,     h, bias) * m0;
                float p3 = softel(sacc[jf][3], ig1, jc + 1, h, bias) * m1;
                lsum0 += p0 + p1;
                lsum1 += p2 + p3;
                __nv_bfloat16 h0, l0, h1, l1, h2, l2, h3, l3;
                split_bf16(p0, h0, l0); split_bf16(p1, h1, l1);
                split_bf16(p2, h2, l2); split_bf16(p3, h3, l3);
                phi2[jf][0] = bpack(h0, h1); phi2[jf][1] = bpack(h2, h3);
                plo2[jf][0] = bpack(l0, l1); plo2[jf][1] = bpack(l2, l3);
            }

            // ---- O += P @ V (3-term) ----
#pragma unroll
            for (int kc2 = 0; kc2 < 4; kc2++) {
                uint32_t ah[4] = { phi2[2 * kc2][0], phi2[2 * kc2][1],
                                   phi2[2 * kc2 + 1][0], phi2[2 * kc2 + 1][1] };
                uint32_t al[4] = { plo2[2 * kc2][0], plo2[2 * kc2][1],
                                   plo2[2 * kc2 + 1][0], plo2[2 * kc2 + 1][1] };
#pragma unroll
                for (int df = 0; df < 8; df++) {
                    uint32_t bh2[2], bl2[2];
                    uint32_t va = vs + (uint32_t)((((kc2 * 16 + (lane & 15)) * 136) + df * 8) << 1);
                    ldmx2t(bh2, va);
                    ldmx2t(bl2, va + 128);
                    mma16816(oacc[df], ah, bh2);
                    mma16816(oacc[df], al, bh2);
                    mma16816(oacc[df], ah, bl2);
                }
            }
        }
        __syncthreads();
        buf ^= 1;
    }

    // ---- finalize: reduce lsum over quad, write split output ----
    lsum0 += __shfl_xor_sync(0xffffffffu, lsum0, 1);
    lsum0 += __shfl_xor_sync(0xffffffffu, lsum0, 2);
    lsum1 += __shfl_xor_sync(0xffffffffu, lsum1, 1);
    lsum1 += __shfl_xor_sync(0xffffffffu, lsum1, 2);
    float inv0 = 1.0f / lsum0;
    float inv1 = 1.0f / lsum1;

#pragma unroll
    for (int df = 0; df < 8; df++) {
        float o0 = oacc[df][0] * inv0, o1 = oacc[df][1] * inv0;
        float o2 = oacc[df][2] * inv1, o3 = oacc[df][3] * inv1;
        __nv_bfloat16 h0, l0, h1, l1, h2, l2, h3, l3;
        split_bf16(o0, h0, l0); split_bf16(o1, h1, l1);
        split_bf16(o2, h2, l2); split_bf16(o3, h3, l3);
        {
            __nv_bfloat16* p = att3 + ((size_t)(b * N_ + ig0)) * KP + h * DH_ + df * 8 + tig * 2;
            *(uint32_t*)(p)             = bpack(h0, h1);
            *(uint32_t*)(p + DIM_)      = bpack(l0, l1);
            *(uint32_t*)(p + 2 * DIM_)  = bpack(h0, h1);
        }
        {
            __nv_bfloat16* p = att3 + ((size_t)(b * N_ + ig1)) * KP + h * DH_ + df * 8 + tig * 2;
            *(uint32_t*)(p)             = bpack(h2, h3);
            *(uint32_t*)(p + DIM_)      = bpack(l2, l3);
            *(uint32_t*)(p + 2 * DIM_)  = bpack(h2, h3);
        }
    }
}

// ---------------- launch ----------------
extern "C" void kernel_launch(void* const* d_in, const int* in_sizes, int n_in,
                              void* d_out, int out_size) {
    const float* x     = (const float*)d_in[0];
    const int*   mask  = (const int*)d_in[1];
    const float* bias  = (const float*)d_in[2];
    const float* gamma = (const float*)d_in[3];
    const float* nkv   = (const float*)d_in[4];
    const float* Wq    = (const float*)d_in[5];
    const float* Wkv   = (const float*)d_in[6];
    const float* qsc   = (const float*)d_in[7];
    const float* ksc   = (const float*)d_in[8];
    const float* Wo    = (const float*)d_in[9];
    float* out = (float*)d_out;

    __nv_bfloat16 *p_x3, *p_xn3, *p_att3, *p_Wq3T, *p_Wkv3T, *p_Wo3T, *p_Q3, *p_K3, *p_V3;
    float *p_q, *p_kv;
    cudaGetSymbolAddress((void**)&p_x3,    g_x3);
    cudaGetSymbolAddress((void**)&p_xn3,   g_xn3);
    cudaGetSymbolAddress((void**)&p_att3,  g_att3);
    cudaGetSymbolAddress((void**)&p_Wq3T,  g_Wq3T);
    cudaGetSymbolAddress((void**)&p_Wkv3T, g_Wkv3T);
    cudaGetSymbolAddress((void**)&p_Wo3T,  g_Wo3T);
    cudaGetSymbolAddress((void**)&p_q,     g_q);
    cudaGetSymbolAddress((void**)&p_kv,    g_kv);
    cudaGetSymbolAddress((void**)&p_Q3,    g_Q3);
    cudaGetSymbolAddress((void**)&p_K3,    g_K3);
    cudaGetSymbolAddress((void**)&p_V3,    g_V3);

    // weight conversions (transpose + hi/lo split)
    dim3 wb(32, 8);
    wconv_kernel<<<dim3(DIM_ / 32,     DIM_ / 32), wb>>>(Wq,  p_Wq3T,  DIM_);
    wconv_kernel<<<dim3(2 * DIM_ / 32, DIM_ / 32), wb>>>(Wkv, p_Wkv3T, 2 * DIM_);
    wconv_kernel<<<dim3(DIM_ / 32,     DIM_ / 32), wb>>>(Wo,  p_Wo3T,  DIM_);

    // activation conversions
    aconv_kernel<<<(MTOT * DIM_ + 255) / 256, 256>>>(x, p_x3);
    ln_kernel<<<MTOT, 256>>>(x, gamma, p_xn3);

    // projections via bf16-split HMMA
    dim3 gq(DIM_ / 128, MTOT / 128);
    hgemm_kernel<<<gq, 256>>>(p_xn3, p_Wq3T, p_q, MTOT, DIM_);
    dim3 gkv(2 * DIM_ / 128, MTOT / 128);
    hgemm_kernel<<<gkv, 256>>>(p_x3, p_Wkv3T, p_kv, MTOT, 2 * DIM_);

    // l2norm q/k, emit pre-split bf16 attention operands
    int nwarp = B_ * H_ * J_;
    prep_kernel<<<(nwarp + 7) / 8, 256>>>(p_q, p_kv, nkv, qsc, ksc, p_Q3, p_K3, p_V3);

    // HMMA flash attention
    cudaFuncSetAttribute(attn_mma_kernel, cudaFuncAttributeMaxDynamicSharedMemorySize, SMEM_ATT);
    dim3 ga(N_ / 128, B_ * H_);
    attn_mma_kernel<<<ga, 256, SMEM_ATT>>>(p_Q3, p_K3, p_V3, bias, mask, p_att3);

    // output projection
    hgemm_kernel<<<gq, 256>>>(p_att3, p_Wo3T, out, MTOT, DIM_);
}

// round 7
// speedup vs baseline: 1.4184x; 1.0189x over previous
#include <cuda_runtime.h>
#include <cuda_bf16.h>
#include <math.h>
#include <stdint.h>

// ---------------- problem constants ----------------
#define B_    2
#define N_    2048
#define DIM_  1024
#define H_    16
#define DH_   64
#define NNK_  2
#define J_    (N_ + NNK_)    // 2050
#define J_PAD 2112           // 33 tiles of 64
#define SCALE_ 8.0f
#define KP    3072           // split-K' = 3 * DIM_
#define MTOT  (B_ * N_)      // 4096

// ---------------- scratch (device globals; no allocs allowed) ----------------
__device__ __align__(16) __nv_bfloat16 g_x3   [MTOT * KP];      // [Ahi|Alo|Ahi] of x
__device__ __align__(16) __nv_bfloat16 g_xn3  [MTOT * KP];      // of layernorm(x)
__device__ __align__(16) __nv_bfloat16 g_att3 [MTOT * KP];      // of attention out
__device__ __align__(16) __nv_bfloat16 g_Wq3T [DIM_ * KP];      // [N=1024][Bhi|Bhi|Blo]
__device__ __align__(16) __nv_bfloat16 g_Wkv3T[2 * DIM_ * KP];  // [N=2048][...]
__device__ __align__(16) __nv_bfloat16 g_Wo3T [DIM_ * KP];
__device__ float g_q  [MTOT * DIM_];           // q projection (b,n,h*dh)
__device__ float g_kv [MTOT * 2 * DIM_];       // kv projection
// attention operands, pre-split bf16 (padding rows stay zero-initialized)
__device__ __align__(16) __nv_bfloat16 g_Q3 [B_ * H_ * N_ * 192];     // [Qhi|Qlo|Qhi]
__device__ __align__(16) __nv_bfloat16 g_K3 [B_ * H_ * J_PAD * 192];  // [Khi|Khi|Klo]
__device__ __align__(16) __nv_bfloat16 g_V3 [B_ * H_ * J_PAD * 128];  // [Vhi|Vlo]

// ---------------- helpers ----------------
__device__ __forceinline__ void split_bf16(float v, __nv_bfloat16& hi, __nv_bfloat16& lo) {
    hi = __float2bfloat16_rn(v);
    lo = __float2bfloat16_rn(v - __bfloat162float(hi));
}
__device__ __forceinline__ uint32_t bpack(__nv_bfloat16 a, __nv_bfloat16 b) {
    __nv_bfloat162 t = __halves2bfloat162(a, b);
    return *reinterpret_cast<uint32_t*>(&t);
}
__device__ __forceinline__ void ldmx4(uint32_t* r, uint32_t addr) {
    asm volatile("ldmatrix.sync.aligned.m8n8.x4.shared.b16 {%0,%1,%2,%3}, [%4];"
                 : "=r"(r[0]), "=r"(r[1]), "=r"(r[2]), "=r"(r[3]) : "r"(addr));
}
__device__ __forceinline__ void ldmx2(uint32_t* r, uint32_t addr) {
    asm volatile("ldmatrix.sync.aligned.m8n8.x2.shared.b16 {%0,%1}, [%2];"
                 : "=r"(r[0]), "=r"(r[1]) : "r"(addr));
}
__device__ __forceinline__ void ldmx2t(uint32_t* r, uint32_t addr) {
    asm volatile("ldmatrix.sync.aligned.m8n8.x2.trans.shared.b16 {%0,%1}, [%2];"
                 : "=r"(r[0]), "=r"(r[1]) : "r"(addr));
}
__device__ __forceinline__ void mma16816(float* d, const uint32_t* a, const uint32_t* b) {
    asm volatile("mma.sync.aligned.m16n8k16.row.col.f32.bf16.bf16.f32 {%0,%1,%2,%3},{%4,%5,%6,%7},{%8,%9},{%0,%1,%2,%3};"
                 : "+f"(d[0]), "+f"(d[1]), "+f"(d[2]), "+f"(d[3])
                 : "r"(a[0]), "r"(a[1]), "r"(a[2]), "r"(a[3]), "r"(b[0]), "r"(b[1]));
}
__device__ __forceinline__ void cp16(uint32_t saddr, const void* gptr) {
    asm volatile("cp.async.cg.shared.global [%0], [%1], 16;" :: "r"(saddr), "l"(gptr));
}
__device__ __forceinline__ void cp_commit() { asm volatile("cp.async.commit_group;"); }
__device__ __forceinline__ void cp_wait1() { asm volatile("cp.async.wait_group 1;"); }
__device__ __forceinline__ void cp_wait2() { asm volatile("cp.async.wait_group 2;"); }

// ---------------- LayerNorm -> xn3, and x -> x3 (fused) ----------------
__global__ void ln_kernel(const float* __restrict__ x,
                          const float* __restrict__ gamma,
                          __nv_bfloat16* __restrict__ xn3,
                          __nv_bfloat16* __restrict__ x3) {
    int row = blockIdx.x;
    const float* xr = x + (size_t)row * DIM_;
    float v[4];
    float s = 0.f, sq = 0.f;
#pragma unroll
    for (int i = 0; i < 4; i++) {
        float t = xr[threadIdx.x + i * 256];
        v[i] = t; s += t; sq += t * t;
    }
#pragma unroll
    for (int off = 16; off > 0; off >>= 1) {
        s  += __shfl_xor_sync(0xffffffffu, s,  off);
        sq += __shfl_xor_sync(0xffffffffu, sq, off);
    }
    __shared__ float sa[8], sb[8];
    int w = threadIdx.x >> 5, l = threadIdx.x & 31;
    if (l == 0) { sa[w] = s; sb[w] = sq; }
    __syncthreads();
    if (threadIdx.x == 0) {
        float a = 0.f, bq = 0.f;
#pragma unroll
        for (int i = 0; i < 8; i++) { a += sa[i]; bq += sb[i]; }
        sa[0] = a; sb[0] = bq;
    }
    __syncthreads();
    float mean = sa[0] * (1.0f / DIM_);
    float var  = sb[0] * (1.0f / DIM_) - mean * mean;
    float rstd = rsqrtf(var + 1e-5f);
    __nv_bfloat16* outr = xn3 + (size_t)row * KP;
    __nv_bfloat16* xo   = x3  + (size_t)row * KP;
#pragma unroll
    for (int i = 0; i < 4; i++) {
        int d = threadIdx.x + i * 256;
        float o = (v[i] - mean) * rstd * gamma[d];
        __nv_bfloat16 hi, lo; split_bf16(o, hi, lo);
        outr[d] = hi; outr[DIM_ + d] = lo; outr[2 * DIM_ + d] = hi;
        split_bf16(v[i], hi, lo);
        xo[d] = hi; xo[DIM_ + d] = lo; xo[2 * DIM_ + d] = hi;
    }
}

// ---------------- W [K=1024][N] -> W3T [N][KP] (B-side split, transposed) ----------------
__global__ void wconv_kernel(const float* __restrict__ W, __nv_bfloat16* __restrict__ W3T, int N) {
    __shared__ float t[32][33];
    int k0 = blockIdx.y * 32, n0 = blockIdx.x * 32;
    int tx = threadIdx.x, ty = threadIdx.y;   // 32 x 8
#pragma unroll
    for (int i = 0; i < 4; i++)
        t[ty + i * 8][tx] = W[(size_t)(k0 + ty + i * 8) * N + n0 + tx];
    __syncthreads();
#pragma unroll
    for (int i = 0; i < 4; i++) {
        int n = n0 + ty + i * 8;
        int k = k0 + tx;
        float w = t[tx][ty + i * 8];
        __nv_bfloat16 hi, lo; split_bf16(w, hi, lo);
        __nv_bfloat16* o = W3T + (size_t)n * KP;
        o[k] = hi; o[DIM_ + k] = hi; o[2 * DIM_ + k] = lo;
    }
}

// ---------------- bf16 HMMA GEMM, 4-stage cp.async: C = A3[M,KP] @ B3T[N,KP]^T ----------------
#define STAGES 4
#define BK 32
#define STRIDE 40
#define STG_ELEM (128 * STRIDE)   // 5120 bf16 per matrix per stage
#define NKTILES (KP / BK)         // 96

__global__ void __launch_bounds__(256, 1) hgemm_kernel(
        const __nv_bfloat16* __restrict__ A,   // [M][KP]
        const __nv_bfloat16* __restrict__ BT,  // [N][KP]
        float* __restrict__ C, int M, int N) {
    __shared__ __nv_bfloat16 As[STAGES * STG_ELEM];
    __shared__ __nv_bfloat16 Bs[STAGES * STG_ELEM];

    const int tid  = threadIdx.x;
    const int wid  = tid >> 5, lane = tid & 31;
    const int wm   = wid & 1, wn = wid >> 1;
    const int g    = lane >> 2, tig = lane & 3;

    const int row0 = blockIdx.y * 128;
    const int col0 = blockIdx.x * 128;

    // loader mapping: each thread fills one row-chunk (2x cp16 per matrix per stage)
    const int lrow = tid >> 1;            // 0..127
    const int lcol = (tid & 1) << 4;      // 0 or 16
    const __nv_bfloat16* Ag = A  + (size_t)(row0 + lrow) * KP + lcol;
    const __nv_bfloat16* Bg = BT + (size_t)(col0 + lrow) * KP + lcol;

    const uint32_t a_base = (uint32_t)__cvta_generic_to_shared(As);
    const uint32_t b_base = (uint32_t)__cvta_generic_to_shared(Bs);
    const uint32_t a_dst = a_base + (uint32_t)((lrow * STRIDE + lcol) * 2);
    const uint32_t b_dst = b_base + (uint32_t)((lrow * STRIDE + lcol) * 2);

    float acc[4][4][4];
#pragma unroll
    for (int mi = 0; mi < 4; mi++)
#pragma unroll
        for (int ni = 0; ni < 4; ni++)
#pragma unroll
            for (int e = 0; e < 4; e++) acc[mi][ni][e] = 0.f;

    const int a_row_in = lane & 15;
    const int a_k_in   = (lane >> 4) << 3;
    const int b_row_in = lane & 7;
    const int b_k_in   = ((lane >> 3) & 1) << 3;

    // prologue: issue stages 0..2
#pragma unroll
    for (int s = 0; s < STAGES - 1; s++) {
        uint32_t so = (uint32_t)(s * STG_ELEM * 2);
        cp16(a_dst + so,      Ag + s * BK);
        cp16(a_dst + so + 16, Ag + s * BK + 8);
        cp16(b_dst + so,      Bg + s * BK);
        cp16(b_dst + so + 16, Bg + s * BK + 8);
        cp_commit();
    }

    for (int t = 0; t < NKTILES; t++) {
        cp_wait2();
        __syncthreads();

        // issue stage t+3 (overwrites buffer (t-1)%4, fenced by the barrier above)
        if (t + STAGES - 1 < NKTILES) {
            uint32_t so = (uint32_t)(((t + STAGES - 1) % STAGES) * STG_ELEM * 2);
            const __nv_bfloat16* ap = Ag + (t + STAGES - 1) * BK;
            const __nv_bfloat16* bp = Bg + (t + STAGES - 1) * BK;
            cp16(a_dst + so,      ap);
            cp16(a_dst + so + 16, ap + 8);
            cp16(b_dst + so,      bp);
            cp16(b_dst + so + 16, bp + 8);
        }
        cp_commit();

        const uint32_t abuf = a_base + (uint32_t)((t % STAGES) * STG_ELEM * 2);
        const uint32_t bbuf = b_base + (uint32_t)((t % STAGES) * STG_ELEM * 2);
#pragma unroll
        for (int kk = 0; kk < BK; kk += 16) {
            uint32_t afr[4][4];
            uint32_t bfr[4][2];
#pragma unroll
            for (int mi = 0; mi < 4; mi++) {
                uint32_t a_addr = abuf +
                    (uint32_t)(((wm * 64 + mi * 16 + a_row_in) * STRIDE + kk + a_k_in) << 1);
                ldmx4(afr[mi], a_addr);
            }
#pragma unroll
            for (int ni = 0; ni < 4; ni++) {
                uint32_t b_addr = bbuf +
                    (uint32_t)(((wn * 32 + ni * 8 + b_row_in) * STRIDE + kk + b_k_in) << 1);
                ldmx2(bfr[ni], b_addr);
            }
#pragma unroll
            for (int mi = 0; mi < 4; mi++)
#pragma unroll
                for (int ni = 0; ni < 4; ni++)
                    mma16816(acc[mi][ni], afr[mi], bfr[ni]);
        }
    }

#pragma unroll
    for (int mi = 0; mi < 4; mi++) {
        int r0 = row0 + wm * 64 + mi * 16 + g;
#pragma unroll
        for (int ni = 0; ni < 4; ni++) {
            int cc = col0 + wn * 32 + ni * 8 + tig * 2;
            float2 v0 = { acc[mi][ni][0], acc[mi][ni][1] };
            float2 v1 = { acc[mi][ni][2], acc[mi][ni][3] };
            *(float2*)&C[(size_t)r0 * N + cc]       = v0;
            *(float2*)&C[(size_t)(r0 + 8) * N + cc] = v1;
        }
    }
}

// ---------------- prep: emit pre-split bf16 Q3/K3/V3 ----------------
__global__ void prep_kernel(const float* __restrict__ q,
                            const float* __restrict__ kv,
                            const float* __restrict__ null_kv,
                            const float* __restrict__ q_scale,
                            const float* __restrict__ k_scale,
                            __nv_bfloat16* __restrict__ Q3,
                            __nv_bfloat16* __restrict__ K3,
                            __nv_bfloat16* __restrict__ V3) {
    int warp = (blockIdx.x * blockDim.x + threadIdx.x) >> 5;
    int lane = threadIdx.x & 31;
    if (warp >= B_ * H_ * J_) return;
    int bh = warp / J_;
    int j  = warp % J_;
    int b = bh / H_, h = bh % H_;
    int d0 = lane, d1 = lane + 32;

    float k0, k1, v0, v1;
    if (j < NNK_) {
        const float* nb = null_kv + ((size_t)(h * NNK_ + j) * 2) * DH_;
        k0 = nb[d0];        k1 = nb[d1];
        v0 = nb[DH_ + d0];  v1 = nb[DH_ + d1];
    } else {
        int n = j - NNK_;
        const float* base = kv + ((size_t)(b * N_ + n)) * (2 * DIM_) + h * DH_;
        k0 = base[d0];          k1 = base[d1];
        v0 = base[DIM_ + d0];   v1 = base[DIM_ + d1];
    }
    float ss = k0 * k0 + k1 * k1;
#pragma unroll
    for (int off = 16; off > 0; off >>= 1)
        ss += __shfl_xor_sync(0xffffffffu, ss, off);
    float inv = 1.0f / fmaxf(sqrtf(ss), 1e-12f);
    float ks0 = k0 * inv * k_scale[d0];
    float ks1 = k1 * inv * k_scale[d1];

    __nv_bfloat16 h0, l0, h1, l1;
    size_t ko = ((size_t)bh * J_PAD + j) * 192;
    split_bf16(ks0, h0, l0); split_bf16(ks1, h1, l1);
    K3[ko + d0] = h0; K3[ko + 64 + d0] = h0; K3[ko + 128 + d0] = l0;
    K3[ko + d1] = h1; K3[ko + 64 + d1] = h1; K3[ko + 128 + d1] = l1;

    size_t vo = ((size_t)bh * J_PAD + j) * 128;
    split_bf16(v0, h0, l0); split_bf16(v1, h1, l1);
    V3[vo + d0] = h0; V3[vo + 64 + d0] = l0;
    V3[vo + d1] = h1; V3[vo + 64 + d1] = l1;

    if (j < N_) {
        int n = j;
        const float* qb = q + ((size_t)(b * N_ + n)) * DIM_ + h * DH_;
        float a0 = qb[d0], a1 = qb[d1];
        float qs2 = a0 * a0 + a1 * a1;
#pragma unroll
        for (int off = 16; off > 0; off >>= 1)
            qs2 += __shfl_xor_sync(0xffffffffu, qs2, off);
        float qinv = 1.0f / fmaxf(sqrtf(qs2), 1e-12f);
        float q0 = a0 * qinv * q_scale[d0];
        float q1 = a1 * qinv * q_scale[d1];
        size_t qo = ((size_t)bh * N_ + n) * 192;
        split_bf16(q0, h0, l0); split_bf16(q1, h1, l1);
        Q3[qo + d0] = h0; Q3[qo + 64 + d0] = l0; Q3[qo + 128 + d0] = h0;
        Q3[qo + d1] = h1; Q3[qo + 64 + d1] = l1; Q3[qo + 128 + d1] = h1;
    }
}

// ---------------- HMMA flash attention ----------------
#define QS_OFF   0
#define KS_OFF   51200
#define KS_SZ    25600
#define VS_OFF   102400
#define VS_SZ    17408
#define MM_OFF   137216
#define SMEM_ATT 137728

__device__ __forceinline__ float softel(float s, int ig, int jg, int h,
                                        const float* __restrict__ bias) {
    bool ok = (jg <= ig + NNK_) && (jg < J_);
    float bv = 0.f;
    if (ok && jg >= NNK_) bv = __ldg(bias + ((size_t)h * N_ + ig) * N_ + (jg - NNK_));
    float t = fmaf(s, 11.541560327111707f, fmaf(bv, 1.4426950408889634f, -23.083120654223414f));
    float r;
    asm("ex2.approx.f32 %0, %1;" : "=f"(r) : "f"(t));
    return ok ? r : 0.f;
}

__device__ __forceinline__ void load_tile(int stage, int j0, int bh, int b, int tid,
        uint32_t sbase, char* smx,
        const __nv_bfloat16* __restrict__ K3, const __nv_bfloat16* __restrict__ V3,
        const int* __restrict__ mask) {
    uint32_t ks = sbase + KS_OFF + stage * KS_SZ;
    uint32_t vs = sbase + VS_OFF + stage * VS_SZ;
#pragma unroll
    for (int i = 0; i < 6; i++) {
        int idx = i * 256 + tid;
        int row = idx / 24, c = idx % 24;
        const void* src = K3 + ((size_t)bh * J_PAD + j0 + row) * 192 + c * 8;
        cp16(ks + (uint32_t)((row * 200 + c * 8) * 2), src);
    }
#pragma unroll
    for (int i = 0; i < 4; i++) {
        int idx = i * 256 + tid;
        int row = idx / 16, c = idx % 16;
        const void* src = V3 + ((size_t)bh * J_PAD + j0 + row) * 128 + c * 8;
        cp16(vs + (uint32_t)((row * 136 + c * 8) * 2), src);
    }
    if (tid < 64) {
        int jg = j0 + tid;
        float mm = 1.f;
        if (jg >= NNK_) mm = (jg < J_ && mask[b * N_ + jg - NNK_] != 0) ? 1.f : 0.f;
        ((float*)(smx + MM_OFF))[stage * 64 + tid] = mm;
    }
}

__global__ void __launch_bounds__(256, 1) attn_mma_kernel(
        const __nv_bfloat16* __restrict__ Q3, const __nv_bfloat16* __restrict__ K3,
        const __nv_bfloat16* __restrict__ V3, const float* __restrict__ bias,
        const int* __restrict__ mask, __nv_bfloat16* __restrict__ att3) {
    extern __shared__ char smx[];
    const uint32_t sbase = (uint32_t)__cvta_generic_to_shared(smx);

    const int tid = threadIdx.x;
    const int w = tid >> 5, lane = tid & 31;
    const int g = lane >> 2, tig = lane & 3;
    const int i0 = blockIdx.x * 128;
    const int bh = blockIdx.y, b = bh >> 4, h = bh & 15;
    const int iw = i0 + w * 16;
    const int ig0 = iw + g, ig1 = ig0 + 8;

    const int jtmax = min((i0 + 129) >> 6, J_PAD / 64 - 1);

#pragma unroll
    for (int i = 0; i < 12; i++) {
        int idx = i * 256 + tid;
        int row = idx / 24, c = idx % 24;
        const void* src = Q3 + ((size_t)bh * N_ + i0 + row) * 192 + c * 8;
        cp16(sbase + QS_OFF + (uint32_t)((row * 200 + c * 8) * 2), src);
    }
    load_tile(0, 0, bh, b, tid, sbase, smx, K3, V3, mask);
    cp_commit();

    float oacc[8][4];
#pragma unroll
    for (int d = 0; d < 8; d++)
#pragma unroll
        for (int e = 0; e < 4; e++) oacc[d][e] = 0.f;
    float lsum0 = 0.f, lsum1 = 0.f;

    int buf = 0;
    for (int jt = 0; jt <= jtmax; jt++) {
        const int j0 = jt * 64;
        if (jt < jtmax)
            load_tile(buf ^ 1, j0 + 64, bh, b, tid, sbase, smx, K3, V3, mask);
        cp_commit();
        cp_wait1();
        __syncthreads();

        const bool active = (j0 <= iw + 15 + NNK_);
        if (active) {
            const uint32_t ks = sbase + KS_OFF + buf * KS_SZ;
            const uint32_t vs = sbase + VS_OFF + buf * VS_SZ;
            const float* mm = (const float*)(smx + MM_OFF) + buf * 64;

            float sacc[8][4];
#pragma unroll
            for (int jf = 0; jf < 8; jf++)
#pragma unroll
                for (int e = 0; e < 4; e++) sacc[jf][e] = 0.f;

            const int a_row = w * 16 + (lane & 15);
            const int a_kin = (lane >> 4) << 3;
            const int b_row = lane & 7;
            const int b_kin = ((lane >> 3) & 1) << 3;
            for (int kc = 0; kc < 12; kc++) {
                uint32_t a[4];
                ldmx4(a, sbase + QS_OFF + (uint32_t)(((a_row) * 200 + kc * 16 + a_kin) << 1));
#pragma unroll
                for (int jf = 0; jf < 8; jf++) {
                    uint32_t bb[2];
                    ldmx2(bb, ks + (uint32_t)(((jf * 8 + b_row) * 200 + kc * 16 + b_kin) << 1));
                    mma16816(sacc[jf], a, bb);
                }
            }

            uint32_t phi2[8][2], plo2[8][2];
#pragma unroll
            for (int jf = 0; jf < 8; jf++) {
                int jc = j0 + jf * 8 + tig * 2;
                float m0 = mm[jf * 8 + tig * 2];
                float m1 = mm[jf * 8 + tig * 2 + 1];
                float p0 = softel(sacc[jf][0], ig0, jc,     h, bias) * m0;
                float p1 = softel(sacc[jf][1], ig0, jc + 1, h, bias) * m1;
                float p2 = softel(sacc[jf][2], ig1, jc,     h, bias) * m0;
                float p3 = softel(sacc[jf][3], ig1, jc + 1, h, bias) * m1;
                lsum0 += p0 + p1;
                lsum1 += p2 + p3;
                __nv_bfloat16 h0, l0, h1, l1, h2, l2, h3, l3;
                split_bf16(p0, h0, l0); split_bf16(p1, h1, l1);
                split_bf16(p2, h2, l2); split_bf16(p3, h3, l3);
                phi2[jf][0] = bpack(h0, h1); phi2[jf][1] = bpack(h2, h3);
                plo2[jf][0] = bpack(l0, l1); plo2[jf][1] = bpack(l2, l3);
            }

#pragma unroll
            for (int kc2 = 0; kc2 < 4; kc2++) {
                uint32_t ah[4] = { phi2[2 * kc2][0], phi2[2 * kc2][1],
                                   phi2[2 * kc2 + 1][0], phi2[2 * kc2 + 1][1] };
                uint32_t al[4] = { plo2[2 * kc2][0], plo2[2 * kc2][1],
                                   plo2[2 * kc2 + 1][0], plo2[2 * kc2 + 1][1] };
#pragma unroll
                for (int df = 0; df < 8; df++) {
                    uint32_t bh2[2], bl2[2];
                    uint32_t va = vs + (uint32_t)((((kc2 * 16 + (lane & 15)) * 136) + df * 8) << 1);
                    ldmx2t(bh2, va);
                    ldmx2t(bl2, va + 128);
                    mma16816(oacc[df], ah, bh2);
                    mma16816(oacc[df], al, bh2);
                    mma16816(oacc[df], ah, bl2);
                }
            }
        }
        __syncthreads();
        buf ^= 1;
    }

    lsum0 += __shfl_xor_sync(0xffffffffu, lsum0, 1);
    lsum0 += __shfl_xor_sync(0xffffffffu, lsum0, 2);
    lsum1 += __shfl_xor_sync(0xffffffffu, lsum1, 1);
    lsum1 += __shfl_xor_sync(0xffffffffu, lsum1, 2);
    float inv0 = 1.0f / lsum0;
    float inv1 = 1.0f / lsum1;

#pragma unroll
    for (int df = 0; df < 8; df++) {
        float o0 = oacc[df][0] * inv0, o1 = oacc[df][1] * inv0;
        float o2 = oacc[df][2] * inv1, o3 = oacc[df][3] * inv1;
        __nv_bfloat16 h0, l0, h1, l1, h2, l2, h3, l3;
        split_bf16(o0, h0, l0); split_bf16(o1, h1, l1);
        split_bf16(o2, h2, l2); split_bf16(o3, h3, l3);
        {
            __nv_bfloat16* p = att3 + ((size_t)(b * N_ + ig0)) * KP + h * DH_ + df * 8 + tig * 2;
            *(uint32_t*)(p)             = bpack(h0, h1);
            *(uint32_t*)(p + DIM_)      = bpack(l0, l1);
            *(uint32_t*)(p + 2 * DIM_)  = bpack(h0, h1);
        }
        {
            __nv_bfloat16* p = att3 + ((size_t)(b * N_ + ig1)) * KP + h * DH_ + df * 8 + tig * 2;
            *(uint32_t*)(p)             = bpack(h2, h3);
            *(uint32_t*)(p + DIM_)      = bpack(l2, l3);
            *(uint32_t*)(p + 2 * DIM_)  = bpack(h2, h3);
        }
    }
}

// ---------------- launch ----------------
extern "C" void kernel_launch(void* const* d_in, const int* in_sizes, int n_in,
                              void* d_out, int out_size) {
    const float* x     = (const float*)d_in[0];
    const int*   mask  = (const int*)d_in[1];
    const float* bias  = (const float*)d_in[2];
    const float* gamma = (const float*)d_in[3];
    const float* nkv   = (const float*)d_in[4];
    const float* Wq    = (const float*)d_in[5];
    const float* Wkv   = (const float*)d_in[6];
    const float* qsc   = (const float*)d_in[7];
    const float* ksc   = (const float*)d_in[8];
    const float* Wo    = (const float*)d_in[9];
    float* out = (float*)d_out;

    __nv_bfloat16 *p_x3, *p_xn3, *p_att3, *p_Wq3T, *p_Wkv3T, *p_Wo3T, *p_Q3, *p_K3, *p_V3;
    float *p_q, *p_kv;
    cudaGetSymbolAddress((void**)&p_x3,    g_x3);
    cudaGetSymbolAddress((void**)&p_xn3,   g_xn3);
    cudaGetSymbolAddress((void**)&p_att3,  g_att3);
    cudaGetSymbolAddress((void**)&p_Wq3T,  g_Wq3T);
    cudaGetSymbolAddress((void**)&p_Wkv3T, g_Wkv3T);
    cudaGetSymbolAddress((void**)&p_Wo3T,  g_Wo3T);
    cudaGetSymbolAddress((void**)&p_q,     g_q);
    cudaGetSymbolAddress((void**)&p_kv,    g_kv);
    cudaGetSymbolAddress((void**)&p_Q3,    g_Q3);
    cudaGetSymbolAddress((void**)&p_K3,    g_K3);
    cudaGetSymbolAddress((void**)&p_V3,    g_V3);

    // weight conversions (transpose + hi/lo split)
    dim3 wb(32, 8);
    wconv_kernel<<<dim3(DIM_ / 32,     DIM_ / 32), wb>>>(Wq,  p_Wq3T,  DIM_);
    wconv_kernel<<<dim3(2 * DIM_ / 32, DIM_ / 32), wb>>>(Wkv, p_Wkv3T, 2 * DIM_);
    wconv_kernel<<<dim3(DIM_ / 32,     DIM_ / 32), wb>>>(Wo,  p_Wo3T,  DIM_);

    // layernorm + x split (fused)
    ln_kernel<<<MTOT, 256>>>(x, gamma, p_xn3, p_x3);

    // projections via bf16-split HMMA (cp.async 4-stage)
    dim3 gq(DIM_ / 128, MTOT / 128);
    hgemm_kernel<<<gq, 256>>>(p_xn3, p_Wq3T, p_q, MTOT, DIM_);
    dim3 gkv(2 * DIM_ / 128, MTOT / 128);
    hgemm_kernel<<<gkv, 256>>>(p_x3, p_Wkv3T, p_kv, MTOT, 2 * DIM_);

    // l2norm q/k, emit pre-split bf16 attention operands
    int nwarp = B_ * H_ * J_;
    prep_kernel<<<(nwarp + 7) / 8, 256>>>(p_q, p_kv, nkv, qsc, ksc, p_Q3, p_K3, p_V3);

    // HMMA flash attention
    cudaFuncSetAttribute(attn_mma_kernel, cudaFuncAttributeMaxDynamicSharedMemorySize, SMEM_ATT);
    dim3 ga(N_ / 128, B_ * H_);
    attn_mma_kernel<<<ga, 256, SMEM_ATT>>>(p_Q3, p_K3, p_V3, bias, mask, p_att3);

    // output projection
    hgemm_kernel<<<gq, 256>>>(p_att3, p_Wo3T, out, MTOT, DIM_);
}

// round 10
// speedup vs baseline: 1.7522x; 1.2354x over previous
#include <cuda_runtime.h>
#include <cuda_fp16.h>
#include <cuda_bf16.h>
#include <math.h>
#include <stdint.h>

// ---------------- problem constants ----------------
#define B_    2
#define N_    2048
#define DIM_  1024
#define H_    16
#define DH_   64
#define NNK_  2
#define J_    (N_ + NNK_)    // 2050
#define J_PAD 2112           // 33 tiles of 64
#define KP2   2048           // fp16 2-term split K' (GEMMs)
#define MTOT  (B_ * N_)      // 4096

// ---------------- scratch (device globals; no allocs allowed) ----------------
__device__ __align__(16) __half g_x2   [MTOT * KP2];      // [xhi|xlo]
__device__ __align__(16) __half g_xn2  [MTOT * KP2];      // layernorm(x) split
__device__ __align__(16) __half g_att2 [MTOT * KP2];      // attention out split
__device__ __align__(16) __half g_Wq2T [DIM_ * KP2];      // [N][Whi|Whi]
__device__ __align__(16) __half g_Wkv2T[2 * DIM_ * KP2];
__device__ __align__(16) __half g_Wo2T [DIM_ * KP2];
__device__ float g_q  [MTOT * DIM_];
__device__ float g_kv [MTOT * 2 * DIM_];
// attention operands: bf16 3-term split (proven R6 path); padding rows stay zero
__device__ __align__(16) __nv_bfloat16 g_Q3 [B_ * H_ * N_ * 192];     // [Qhi|Qlo|Qhi]
__device__ __align__(16) __nv_bfloat16 g_K3 [B_ * H_ * J_PAD * 192];  // [Khi|Khi|Klo]
__device__ __align__(16) __nv_bfloat16 g_V3 [B_ * H_ * J_PAD * 128];  // [Vhi|Vlo]

// ---------------- helpers ----------------
__device__ __forceinline__ void split_f16(float v, __half& hi, __half& lo) {
    hi = __float2half_rn(v);
    lo = __float2half_rn(v - __half2float(hi));
}
__device__ __forceinline__ void split_bf16(float v, __nv_bfloat16& hi, __nv_bfloat16& lo) {
    hi = __float2bfloat16_rn(v);
    lo = __float2bfloat16_rn(v - __bfloat162float(hi));
}
__device__ __forceinline__ uint32_t hpack(__half a, __half b) {
    __half2 t = __halves2half2(a, b);
    return *reinterpret_cast<uint32_t*>(&t);
}
__device__ __forceinline__ uint32_t bpack(__nv_bfloat16 a, __nv_bfloat16 b) {
    __nv_bfloat162 t = __halves2bfloat162(a, b);
    return *reinterpret_cast<uint32_t*>(&t);
}
__device__ __forceinline__ void ldmx4(uint32_t* r, uint32_t addr) {
    asm volatile("ldmatrix.sync.aligned.m8n8.x4.shared.b16 {%0,%1,%2,%3}, [%4];"
                 : "=r"(r[0]), "=r"(r[1]), "=r"(r[2]), "=r"(r[3]) : "r"(addr));
}
__device__ __forceinline__ void ldmx2(uint32_t* r, uint32_t addr) {
    asm volatile("ldmatrix.sync.aligned.m8n8.x2.shared.b16 {%0,%1}, [%2];"
                 : "=r"(r[0]), "=r"(r[1]) : "r"(addr));
}
__device__ __forceinline__ void ldmx2t(uint32_t* r, uint32_t addr) {
    asm volatile("ldmatrix.sync.aligned.m8n8.x2.trans.shared.b16 {%0,%1}, [%2];"
                 : "=r"(r[0]), "=r"(r[1]) : "r"(addr));
}
__device__ __forceinline__ void mma16816h(float* d, const uint32_t* a, const uint32_t* b) {
    asm volatile("mma.sync.aligned.m16n8k16.row.col.f32.f16.f16.f32 {%0,%1,%2,%3},{%4,%5,%6,%7},{%8,%9},{%0,%1,%2,%3};"
                 : "+f"(d[0]), "+f"(d[1]), "+f"(d[2]), "+f"(d[3])
                 : "r"(a[0]), "r"(a[1]), "r"(a[2]), "r"(a[3]), "r"(b[0]), "r"(b[1]));
}
__device__ __forceinline__ void mma16816(float* d, const uint32_t* a, const uint32_t* b) {
    asm volatile("mma.sync.aligned.m16n8k16.row.col.f32.bf16.bf16.f32 {%0,%1,%2,%3},{%4,%5,%6,%7},{%8,%9},{%0,%1,%2,%3};"
                 : "+f"(d[0]), "+f"(d[1]), "+f"(d[2]), "+f"(d[3])
                 : "r"(a[0]), "r"(a[1]), "r"(a[2]), "r"(a[3]), "r"(b[0]), "r"(b[1]));
}
__device__ __forceinline__ void cp16(uint32_t saddr, const void* gptr) {
    asm volatile("cp.async.cg.shared.global [%0], [%1], 16;" :: "r"(saddr), "l"(gptr));
}
__device__ __forceinline__ void cp_commit() { asm volatile("cp.async.commit_group;"); }
__device__ __forceinline__ void cp_wait1() { asm volatile("cp.async.wait_group 1;"); }
__device__ __forceinline__ void cp_wait2() { asm volatile("cp.async.wait_group 2;"); }

// ---------------- LayerNorm -> xn2, and x -> x2 (fused, fp16 splits) ----------------
__global__ void ln_kernel(const float* __restrict__ x,
                          const float* __restrict__ gamma,
                          __half* __restrict__ xn2,
                          __half* __restrict__ x2) {
    int row = blockIdx.x;
    const float* xr = x + (size_t)row * DIM_;
    float v[4];
    float s = 0.f, sq = 0.f;
#pragma unroll
    for (int i = 0; i < 4; i++) {
        float t = xr[threadIdx.x + i * 256];
        v[i] = t; s += t; sq += t * t;
    }
#pragma unroll
    for (int off = 16; off > 0; off >>= 1) {
        s  += __shfl_xor_sync(0xffffffffu, s,  off);
        sq += __shfl_xor_sync(0xffffffffu, sq, off);
    }
    __shared__ float sa[8], sb[8];
    int w = threadIdx.x >> 5, l = threadIdx.x & 31;
    if (l == 0) { sa[w] = s; sb[w] = sq; }
    __syncthreads();
    if (threadIdx.x == 0) {
        float a = 0.f, bq = 0.f;
#pragma unroll
        for (int i = 0; i < 8; i++) { a += sa[i]; bq += sb[i]; }
        sa[0] = a; sb[0] = bq;
    }
    __syncthreads();
    float mean = sa[0] * (1.0f / DIM_);
    float var  = sb[0] * (1.0f / DIM_) - mean * mean;
    float rstd = rsqrtf(var + 1e-5f);
    __half* outr = xn2 + (size_t)row * KP2;
    __half* xo   = x2  + (size_t)row * KP2;
#pragma unroll
    for (int i = 0; i < 4; i++) {
        int d = threadIdx.x + i * 256;
        float o = (v[i] - mean) * rstd * gamma[d];
        __half hi, lo; split_f16(o, hi, lo);
        outr[d] = hi; outr[DIM_ + d] = lo;
        split_f16(v[i], hi, lo);
        xo[d] = hi; xo[DIM_ + d] = lo;
    }
}

// ---------------- W [K=1024][N] -> W2T [N][2048] = [Whi|Whi] ----------------
__global__ void wconv_kernel(const float* __restrict__ W, __half* __restrict__ W2T, int N) {
    __shared__ float t[32][33];
    int k0 = blockIdx.y * 32, n0 = blockIdx.x * 32;
    int tx = threadIdx.x, ty = threadIdx.y;   // 32 x 8
#pragma unroll
    for (int i = 0; i < 4; i++)
        t[ty + i * 8][tx] = W[(size_t)(k0 + ty + i * 8) * N + n0 + tx];
    __syncthreads();
#pragma unroll
    for (int i = 0; i < 4; i++) {
        int n = n0 + ty + i * 8;
        int k = k0 + tx;
        __half hi = __float2half_rn(t[tx][ty + i * 8]);
        __half* o = W2T + (size_t)n * KP2;
        o[k] = hi; o[DIM_ + k] = hi;
    }
}

// ---------------- fp16 HMMA GEMM, 4-stage cp.async: C = A2[M,KP2] @ B2T[N,KP2]^T ----------------
#define STAGES 4
#define BK 32
#define STRIDE 40
#define STG_ELEM (128 * STRIDE)
#define NKTILES (KP2 / BK)        // 64

__global__ void __launch_bounds__(256, 1) hgemm_kernel(
        const __half* __restrict__ A,   // [M][KP2]
        const __half* __restrict__ BT,  // [N][KP2]
        float* __restrict__ C, int M, int N) {
    __shared__ __half As[STAGES * STG_ELEM];
    __shared__ __half Bs[STAGES * STG_ELEM];

    const int tid  = threadIdx.x;
    const int wid  = tid >> 5, lane = tid & 31;
    const int wm   = wid & 1, wn = wid >> 1;
    const int g    = lane >> 2, tig = lane & 3;

    const int row0 = blockIdx.y * 128;
    const int col0 = blockIdx.x * 128;

    const int lrow = tid >> 1;
    const int lcol = (tid & 1) << 4;
    const __half* Ag = A  + (size_t)(row0 + lrow) * KP2 + lcol;
    const __half* Bg = BT + (size_t)(col0 + lrow) * KP2 + lcol;

    const uint32_t a_base = (uint32_t)__cvta_generic_to_shared(As);
    const uint32_t b_base = (uint32_t)__cvta_generic_to_shared(Bs);
    const uint32_t a_dst = a_base + (uint32_t)((lrow * STRIDE + lcol) * 2);
    const uint32_t b_dst = b_base + (uint32_t)((lrow * STRIDE + lcol) * 2);

    float acc[4][4][4];
#pragma unroll
    for (int mi = 0; mi < 4; mi++)
#pragma unroll
        for (int ni = 0; ni < 4; ni++)
#pragma unroll
            for (int e = 0; e < 4; e++) acc[mi][ni][e] = 0.f;

    const int a_row_in = lane & 15;
    const int a_k_in   = (lane >> 4) << 3;
    const int b_row_in = lane & 7;
    const int b_k_in   = ((lane >> 3) & 1) << 3;

#pragma unroll
    for (int s = 0; s < STAGES - 1; s++) {
        uint32_t so = (uint32_t)(s * STG_ELEM * 2);
        cp16(a_dst + so,      Ag + s * BK);
        cp16(a_dst + so + 16, Ag + s * BK + 8);
        cp16(b_dst + so,      Bg + s * BK);
        cp16(b_dst + so + 16, Bg + s * BK + 8);
        cp_commit();
    }

    for (int t = 0; t < NKTILES; t++) {
        cp_wait2();
        __syncthreads();

        if (t + STAGES - 1 < NKTILES) {
            uint32_t so = (uint32_t)(((t + STAGES - 1) % STAGES) * STG_ELEM * 2);
            const __half* ap = Ag + (t + STAGES - 1) * BK;
            const __half* bp = Bg + (t + STAGES - 1) * BK;
            cp16(a_dst + so,      ap);
            cp16(a_dst + so + 16, ap + 8);
            cp16(b_dst + so,      bp);
            cp16(b_dst + so + 16, bp + 8);
        }
        cp_commit();

        const uint32_t abuf = a_base + (uint32_t)((t % STAGES) * STG_ELEM * 2);
        const uint32_t bbuf = b_base + (uint32_t)((t % STAGES) * STG_ELEM * 2);
#pragma unroll
        for (int kk = 0; kk < BK; kk += 16) {
            uint32_t afr[4][4];
            uint32_t bfr[4][2];
#pragma unroll
            for (int mi = 0; mi < 4; mi++) {
                uint32_t a_addr = abuf +
                    (uint32_t)(((wm * 64 + mi * 16 + a_row_in) * STRIDE + kk + a_k_in) << 1);
                ldmx4(afr[mi], a_addr);
            }
#pragma unroll
            for (int ni = 0; ni < 4; ni++) {
                uint32_t b_addr = bbuf +
                    (uint32_t)(((wn * 32 + ni * 8 + b_row_in) * STRIDE + kk + b_k_in) << 1);
                ldmx2(bfr[ni], b_addr);
            }
#pragma unroll
            for (int mi = 0; mi < 4; mi++)
#pragma unroll
                for (int ni = 0; ni < 4; ni++)
                    mma16816h(acc[mi][ni], afr[mi], bfr[ni]);
        }
    }

#pragma unroll
    for (int mi = 0; mi < 4; mi++) {
        int r0 = row0 + wm * 64 + mi * 16 + g;
#pragma unroll
        for (int ni = 0; ni < 4; ni++) {
            int cc = col0 + wn * 32 + ni * 8 + tig * 2;
            float2 v0 = { acc[mi][ni][0], acc[mi][ni][1] };
            float2 v1 = { acc[mi][ni][2], acc[mi][ni][3] };
            *(float2*)&C[(size_t)r0 * N + cc]       = v0;
            *(float2*)&C[(size_t)(r0 + 8) * N + cc] = v1;
        }
    }
}

// ---------------- prep: emit pre-split bf16 Q3/K3/V3 (R6-proven) ----------------
__global__ void prep_kernel(const float* __restrict__ q,
                            const float* __restrict__ kv,
                            const float* __restrict__ null_kv,
                            const float* __restrict__ q_scale,
                            const float* __restrict__ k_scale,
                            __nv_bfloat16* __restrict__ Q3,
                            __nv_bfloat16* __restrict__ K3,
                            __nv_bfloat16* __restrict__ V3) {
    int warp = (blockIdx.x * blockDim.x + threadIdx.x) >> 5;
    int lane = threadIdx.x & 31;
    if (warp >= B_ * H_ * J_) return;
    int bh = warp / J_;
    int j  = warp % J_;
    int b = bh / H_, h = bh % H_;
    int d0 = lane, d1 = lane + 32;

    float k0, k1, v0, v1;
    if (j < NNK_) {
        const float* nb = null_kv + ((size_t)(h * NNK_ + j) * 2) * DH_;
        k0 = nb[d0];        k1 = nb[d1];
        v0 = nb[DH_ + d0];  v1 = nb[DH_ + d1];
    } else {
        int n = j - NNK_;
        const float* base = kv + ((size_t)(b * N_ + n)) * (2 * DIM_) + h * DH_;
        k0 = base[d0];          k1 = base[d1];
        v0 = base[DIM_ + d0];   v1 = base[DIM_ + d1];
    }
    float ss = k0 * k0 + k1 * k1;
#pragma unroll
    for (int off = 16; off > 0; off >>= 1)
        ss += __shfl_xor_sync(0xffffffffu, ss, off);
    float inv = 1.0f / fmaxf(sqrtf(ss), 1e-12f);
    float ks0 = k0 * inv * k_scale[d0];
    float ks1 = k1 * inv * k_scale[d1];

    __nv_bfloat16 h0, l0, h1, l1;
    size_t ko = ((size_t)bh * J_PAD + j) * 192;
    split_bf16(ks0, h0, l0); split_bf16(ks1, h1, l1);
    K3[ko + d0] = h0; K3[ko + 64 + d0] = h0; K3[ko + 128 + d0] = l0;
    K3[ko + d1] = h1; K3[ko + 64 + d1] = h1; K3[ko + 128 + d1] = l1;

    size_t vo = ((size_t)bh * J_PAD + j) * 128;
    split_bf16(v0, h0, l0); split_bf16(v1, h1, l1);
    V3[vo + d0] = h0; V3[vo + 64 + d0] = l0;
    V3[vo + d1] = h1; V3[vo + 64 + d1] = l1;

    if (j < N_) {
        int n = j;
        const float* qb = q + ((size_t)(b * N_ + n)) * DIM_ + h * DH_;
        float a0 = qb[d0], a1 = qb[d1];
        float qs2 = a0 * a0 + a1 * a1;
#pragma unroll
        for (int off = 16; off > 0; off >>= 1)
            qs2 += __shfl_xor_sync(0xffffffffu, qs2, off);
        float qinv = 1.0f / fmaxf(sqrtf(qs2), 1e-12f);
        float q0 = a0 * qinv * q_scale[d0];
        float q1 = a1 * qinv * q_scale[d1];
        size_t qo = ((size_t)bh * N_ + n) * 192;
        split_bf16(q0, h0, l0); split_bf16(q1, h1, l1);
        Q3[qo + d0] = h0; Q3[qo + 64 + d0] = l0; Q3[qo + 128 + d0] = h0;
        Q3[qo + d1] = h1; Q3[qo + 64 + d1] = l1; Q3[qo + 128 + d1] = h1;
    }
}

// ---------------- bf16 HMMA flash attention (R6-proven) ----------------
#define QS_OFF   0
#define KS_OFF   51200
#define KS_SZ    25600
#define VS_OFF   102400
#define VS_SZ    17408
#define MM_OFF   137216
#define SMEM_ATT 137728

__device__ __forceinline__ float softel(float s, int ig, int jg, int h,
                                        const float* __restrict__ bias) {
    bool ok = (jg <= ig + NNK_) && (jg < J_);
    float bv = 0.f;
    if (ok && jg >= NNK_) bv = __ldg(bias + ((size_t)h * N_ + ig) * N_ + (jg - NNK_));
    float t = fmaf(s, 11.541560327111707f, fmaf(bv, 1.4426950408889634f, -23.083120654223414f));
    float r;
    asm("ex2.approx.f32 %0, %1;" : "=f"(r) : "f"(t));
    return ok ? r : 0.f;
}

__device__ __forceinline__ void load_tile(int stage, int j0, int bh, int b, int tid,
        uint32_t sbase, char* smx,
        const __nv_bfloat16* __restrict__ K3, const __nv_bfloat16* __restrict__ V3,
        const int* __restrict__ mask) {
    uint32_t ks = sbase + KS_OFF + stage * KS_SZ;
    uint32_t vs = sbase + VS_OFF + stage * VS_SZ;
#pragma unroll
    for (int i = 0; i < 6; i++) {
        int idx = i * 256 + tid;
        int row = idx / 24, c = idx % 24;
        const void* src = K3 + ((size_t)bh * J_PAD + j0 + row) * 192 + c * 8;
        cp16(ks + (uint32_t)((row * 200 + c * 8) * 2), src);
    }
#pragma unroll
    for (int i = 0; i < 4; i++) {
        int idx = i * 256 + tid;
        int row = idx / 16, c = idx % 16;
        const void* src = V3 + ((size_t)bh * J_PAD + j0 + row) * 128 + c * 8;
        cp16(vs + (uint32_t)((row * 136 + c * 8) * 2), src);
    }
    if (tid < 64) {
        int jg = j0 + tid;
        float mm = 1.f;
        if (jg >= NNK_) mm = (jg < J_ && mask[b * N_ + jg - NNK_] != 0) ? 1.f : 0.f;
        ((float*)(smx + MM_OFF))[stage * 64 + tid] = mm;
    }
}

__global__ void __launch_bounds__(256, 1) attn_mma_kernel(
        const __nv_bfloat16* __restrict__ Q3, const __nv_bfloat16* __restrict__ K3,
        const __nv_bfloat16* __restrict__ V3, const float* __restrict__ bias,
        const int* __restrict__ mask, __half* __restrict__ att2) {
    extern __shared__ char smx[];
    const uint32_t sbase = (uint32_t)__cvta_generic_to_shared(smx);

    const int tid = threadIdx.x;
    const int w = tid >> 5, lane = tid & 31;
    const int g = lane >> 2, tig = lane & 3;
    const int i0 = blockIdx.x * 128;
    const int bh = blockIdx.y, b = bh >> 4, h = bh & 15;
    const int iw = i0 + w * 16;
    const int ig0 = iw + g, ig1 = ig0 + 8;

    const int jtmax = min((i0 + 129) >> 6, J_PAD / 64 - 1);

#pragma unroll
    for (int i = 0; i < 12; i++) {
        int idx = i * 256 + tid;
        int row = idx / 24, c = idx % 24;
        const void* src = Q3 + ((size_t)bh * N_ + i0 + row) * 192 + c * 8;
        cp16(sbase + QS_OFF + (uint32_t)((row * 200 + c * 8) * 2), src);
    }
    load_tile(0, 0, bh, b, tid, sbase, smx, K3, V3, mask);
    cp_commit();

    float oacc[8][4];
#pragma unroll
    for (int d = 0; d < 8; d++)
#pragma unroll
        for (int e = 0; e < 4; e++) oacc[d][e] = 0.f;
    float lsum0 = 0.f, lsum1 = 0.f;

    int buf = 0;
    for (int jt = 0; jt <= jtmax; jt++) {
        const int j0 = jt * 64;
        if (jt < jtmax)
            load_tile(buf ^ 1, j0 + 64, bh, b, tid, sbase, smx, K3, V3, mask);
        cp_commit();
        cp_wait1();
        __syncthreads();

        const bool active = (j0 <= iw + 15 + NNK_);
        if (active) {
            const uint32_t ks = sbase + KS_OFF + buf * KS_SZ;
            const uint32_t vs = sbase + VS_OFF + buf * VS_SZ;
            const float* mm = (const float*)(smx + MM_OFF) + buf * 64;

            float sacc[8][4];
#pragma unroll
            for (int jf = 0; jf < 8; jf++)
#pragma unroll
                for (int e = 0; e < 4; e++) sacc[jf][e] = 0.f;

            const int a_row = w * 16 + (lane & 15);
            const int a_kin = (lane >> 4) << 3;
            const int b_row = lane & 7;
            const int b_kin = ((lane >> 3) & 1) << 3;
            for (int kc = 0; kc < 12; kc++) {
                uint32_t a[4];
                ldmx4(a, sbase + QS_OFF + (uint32_t)(((a_row) * 200 + kc * 16 + a_kin) << 1));
#pragma unroll
                for (int jf = 0; jf < 8; jf++) {
                    uint32_t bb[2];
                    ldmx2(bb, ks + (uint32_t)(((jf * 8 + b_row) * 200 + kc * 16 + b_kin) << 1));
                    mma16816(sacc[jf], a, bb);
                }
            }

            uint32_t phi2[8][2], plo2[8][2];
#pragma unroll
            for (int jf = 0; jf < 8; jf++) {
                int jc = j0 + jf * 8 + tig * 2;
                float m0 = mm[jf * 8 + tig * 2];
                float m1 = mm[jf * 8 + tig * 2 + 1];
                float p0 = softel(sacc[jf][0], ig0, jc,     h, bias) * m0;
                float p1 = softel(sacc[jf][1], ig0, jc + 1, h, bias) * m1;
                float p2 = softel(sacc[jf][2], ig1, jc,     h, bias) * m0;
                float p3 = softel(sacc[jf][3], ig1, jc + 1, h, bias) * m1;
                lsum0 += p0 + p1;
                lsum1 += p2 + p3;
                __nv_bfloat16 h0, l0, h1, l1, h2, l2, h3, l3;
                split_bf16(p0, h0, l0); split_bf16(p1, h1, l1);
                split_bf16(p2, h2, l2); split_bf16(p3, h3, l3);
                phi2[jf][0] = bpack(h0, h1); phi2[jf][1] = bpack(h2, h3);
                plo2[jf][0] = bpack(l0, l1); plo2[jf][1] = bpack(l2, l3);
            }

#pragma unroll
            for (int kc2 = 0; kc2 < 4; kc2++) {
                uint32_t ah[4] = { phi2[2 * kc2][0], phi2[2 * kc2][1],
                                   phi2[2 * kc2 + 1][0], phi2[2 * kc2 + 1][1] };
                uint32_t al[4] = { plo2[2 * kc2][0], plo2[2 * kc2][1],
                                   plo2[2 * kc2 + 1][0], plo2[2 * kc2 + 1][1] };
#pragma unroll
                for (int df = 0; df < 8; df++) {
                    uint32_t bh2[2], bl2[2];
                    uint32_t va = vs + (uint32_t)((((kc2 * 16 + (lane & 15)) * 136) + df * 8) << 1);
                    ldmx2t(bh2, va);
                    ldmx2t(bl2, va + 128);
                    mma16816(oacc[df], ah, bh2);
                    mma16816(oacc[df], al, bh2);
                    mma16816(oacc[df], ah, bl2);
                }
            }
        }
        __syncthreads();
        buf ^= 1;
    }

    lsum0 += __shfl_xor_sync(0xffffffffu, lsum0, 1);
    lsum0 += __shfl_xor_sync(0xffffffffu, lsum0, 2);
    lsum1 += __shfl_xor_sync(0xffffffffu, lsum1, 1);
    lsum1 += __shfl_xor_sync(0xffffffffu, lsum1, 2);
    float inv0 = 1.0f / lsum0;
    float inv1 = 1.0f / lsum1;

    // epilogue: fp16 [hi|lo] rows for the fp16 output GEMM
#pragma unroll
    for (int df = 0; df < 8; df++) {
        float o0 = oacc[df][0] * inv0, o1 = oacc[df][1] * inv0;
        float o2 = oacc[df][2] * inv1, o3 = oacc[df][3] * inv1;
        __half h0, l0, h1, l1, h2, l2, h3, l3;
        split_f16(o0, h0, l0); split_f16(o1, h1, l1);
        split_f16(o2, h2, l2); split_f16(o3, h3, l3);
        {
            __half* p = att2 + ((size_t)(b * N_ + ig0)) * KP2 + h * DH_ + df * 8 + tig * 2;
            *(uint32_t*)(p)        = hpack(h0, h1);
            *(uint32_t*)(p + DIM_) = hpack(l0, l1);
        }
        {
            __half* p = att2 + ((size_t)(b * N_ + ig1)) * KP2 + h * DH_ + df * 8 + tig * 2;
            *(uint32_t*)(p)        = hpack(h2, h3);
            *(uint32_t*)(p + DIM_) = hpack(l2, l3);
        }
    }
}

// ---------------- launch ----------------
extern "C" void kernel_launch(void* const* d_in, const int* in_sizes, int n_in,
                              void* d_out, int out_size) {
    const float* x     = (const float*)d_in[0];
    const int*   mask  = (const int*)d_in[1];
    const float* bias  = (const float*)d_in[2];
    const float* gamma = (const float*)d_in[3];
    const float* nkv   = (const float*)d_in[4];
    const float* Wq    = (const float*)d_in[5];
    const float* Wkv   = (const float*)d_in[6];
    const float* qsc   = (const float*)d_in[7];
    const float* ksc   = (const float*)d_in[8];
    const float* Wo    = (const float*)d_in[9];
    float* out = (float*)d_out;

    __half *p_x2, *p_xn2, *p_att2, *p_Wq2T, *p_Wkv2T, *p_Wo2T;
    __nv_bfloat16 *p_Q3, *p_K3, *p_V3;
    float *p_q, *p_kv;
    cudaGetSymbolAddress((void**)&p_x2,    g_x2);
    cudaGetSymbolAddress((void**)&p_xn2,   g_xn2);
    cudaGetSymbolAddress((void**)&p_att2,  g_att2);
    cudaGetSymbolAddress((void**)&p_Wq2T,  g_Wq2T);
    cudaGetSymbolAddress((void**)&p_Wkv2T, g_Wkv2T);
    cudaGetSymbolAddress((void**)&p_Wo2T,  g_Wo2T);
    cudaGetSymbolAddress((void**)&p_q,     g_q);
    cudaGetSymbolAddress((void**)&p_kv,    g_kv);
    cudaGetSymbolAddress((void**)&p_Q3,    g_Q3);
    cudaGetSymbolAddress((void**)&p_K3,    g_K3);
    cudaGetSymbolAddress((void**)&p_V3,    g_V3);

    dim3 wb(32, 8);
    ln_kernel<<<MTOT, 256>>>(x, gamma, p_xn2, p_x2);                                  // 1
    wconv_kernel<<<dim3(DIM_ / 32,     DIM_ / 32), wb>>>(Wq,  p_Wq2T,  DIM_);         // 2
    wconv_kernel<<<dim3(2 * DIM_ / 32, DIM_ / 32), wb>>>(Wkv, p_Wkv2T, 2 * DIM_);     // 3

    dim3 gq(DIM_ / 128, MTOT / 128);
    hgemm_kernel<<<gq, 256>>>(p_xn2, p_Wq2T, p_q, MTOT, DIM_);                        // 4 (profiled)
    dim3 gkv(2 * DIM_ / 128, MTOT / 128);
    hgemm_kernel<<<gkv, 256>>>(p_x2, p_Wkv2T, p_kv, MTOT, 2 * DIM_);                  // 5

    wconv_kernel<<<dim3(DIM_ / 32,     DIM_ / 32), wb>>>(Wo,  p_Wo2T,  DIM_);         // 6

    int nwarp = B_ * H_ * J_;
    prep_kernel<<<(nwarp + 7) / 8, 256>>>(p_q, p_kv, nkv, qsc, ksc, p_Q3, p_K3, p_V3);// 7

    cudaFuncSetAttribute(attn_mma_kernel, cudaFuncAttributeMaxDynamicSharedMemorySize, SMEM_ATT);
    dim3 ga(N_ / 128, B_ * H_);
    attn_mma_kernel<<<ga, 256, SMEM_ATT>>>(p_Q3, p_K3, p_V3, bias, mask, p_att2);     // 8

    hgemm_kernel<<<gq, 256>>>(p_att2, p_Wo2T, out, MTOT, DIM_);                       // 9
}

// round 11
// speedup vs baseline: 1.9812x; 1.1307x over previous
#include <cuda_runtime.h>
#include <cuda_fp16.h>
#include <cuda_bf16.h>
#include <math.h>
#include <stdint.h>

// ---------------- problem constants ----------------
#define B_    2
#define N_    2048
#define DIM_  1024
#define H_    16
#define DH_   64
#define NNK_  2
#define J_    (N_ + NNK_)    // 2050
#define J_PAD 2112           // 33 tiles of 64
#define KP2   2048           // fp16 2-term split K' (GEMMs)
#define MTOT  (B_ * N_)      // 4096

// ---------------- scratch (device globals; no allocs allowed) ----------------
__device__ __align__(16) __half g_x2   [MTOT * KP2];      // [xhi|xlo]
__device__ __align__(16) __half g_xn2  [MTOT * KP2];      // layernorm(x) split
__device__ __align__(16) __half g_att2 [MTOT * KP2];      // attention out split
__device__ __align__(16) __half g_Wq2T [DIM_ * KP2];      // [N][Whi|Whi]
__device__ __align__(16) __half g_Wkv2T[2 * DIM_ * KP2];
__device__ __align__(16) __half g_Wo2T [DIM_ * KP2];
__device__ float g_q  [MTOT * DIM_];
__device__ float g_kv [MTOT * 2 * DIM_];
// attention operands: bf16 hi/lo pairs (3-term math via frag reuse); padding stays zero
__device__ __align__(16) __nv_bfloat16 g_Q3 [B_ * H_ * N_ * 128];     // [Qhi|Qlo]
__device__ __align__(16) __nv_bfloat16 g_K3 [B_ * H_ * J_PAD * 128];  // [Khi|Klo]
__device__ __align__(16) __nv_bfloat16 g_V3 [B_ * H_ * J_PAD * 128];  // [Vhi|Vlo]

// ---------------- helpers ----------------
__device__ __forceinline__ void split_f16(float v, __half& hi, __half& lo) {
    hi = __float2half_rn(v);
    lo = __float2half_rn(v - __half2float(hi));
}
__device__ __forceinline__ void split_bf16(float v, __nv_bfloat16& hi, __nv_bfloat16& lo) {
    hi = __float2bfloat16_rn(v);
    lo = __float2bfloat16_rn(v - __bfloat162float(hi));
}
__device__ __forceinline__ uint32_t hpack(__half a, __half b) {
    __half2 t = __halves2half2(a, b);
    return *reinterpret_cast<uint32_t*>(&t);
}
__device__ __forceinline__ uint32_t bpack(__nv_bfloat16 a, __nv_bfloat16 b) {
    __nv_bfloat162 t = __halves2bfloat162(a, b);
    return *reinterpret_cast<uint32_t*>(&t);
}
__device__ __forceinline__ void ldmx4(uint32_t* r, uint32_t addr) {
    asm volatile("ldmatrix.sync.aligned.m8n8.x4.shared.b16 {%0,%1,%2,%3}, [%4];"
                 : "=r"(r[0]), "=r"(r[1]), "=r"(r[2]), "=r"(r[3]) : "r"(addr));
}
__device__ __forceinline__ void ldmx2(uint32_t* r, uint32_t addr) {
    asm volatile("ldmatrix.sync.aligned.m8n8.x2.shared.b16 {%0,%1}, [%2];"
                 : "=r"(r[0]), "=r"(r[1]) : "r"(addr));
}
__device__ __forceinline__ void ldmx2t(uint32_t* r, uint32_t addr) {
    asm volatile("ldmatrix.sync.aligned.m8n8.x2.trans.shared.b16 {%0,%1}, [%2];"
                 : "=r"(r[0]), "=r"(r[1]) : "r"(addr));
}
__device__ __forceinline__ void mma16816h(float* d, const uint32_t* a, const uint32_t* b) {
    asm volatile("mma.sync.aligned.m16n8k16.row.col.f32.f16.f16.f32 {%0,%1,%2,%3},{%4,%5,%6,%7},{%8,%9},{%0,%1,%2,%3};"
                 : "+f"(d[0]), "+f"(d[1]), "+f"(d[2]), "+f"(d[3])
                 : "r"(a[0]), "r"(a[1]), "r"(a[2]), "r"(a[3]), "r"(b[0]), "r"(b[1]));
}
__device__ __forceinline__ void mma16816(float* d, const uint32_t* a, const uint32_t* b) {
    asm volatile("mma.sync.aligned.m16n8k16.row.col.f32.bf16.bf16.f32 {%0,%1,%2,%3},{%4,%5,%6,%7},{%8,%9},{%0,%1,%2,%3};"
                 : "+f"(d[0]), "+f"(d[1]), "+f"(d[2]), "+f"(d[3])
                 : "r"(a[0]), "r"(a[1]), "r"(a[2]), "r"(a[3]), "r"(b[0]), "r"(b[1]));
}
__device__ __forceinline__ void cp16(uint32_t saddr, const void* gptr) {
    asm volatile("cp.async.cg.shared.global [%0], [%1], 16;" :: "r"(saddr), "l"(gptr));
}
__device__ __forceinline__ void cp_commit() { asm volatile("cp.async.commit_group;"); }
__device__ __forceinline__ void cp_wait1() { asm volatile("cp.async.wait_group 1;"); }

// ---------------- LayerNorm -> xn2, and x -> x2 (fused, fp16 splits) ----------------
__global__ void ln_kernel(const float* __restrict__ x,
                          const float* __restrict__ gamma,
                          __half* __restrict__ xn2,
                          __half* __restrict__ x2) {
    int row = blockIdx.x;
    const float* xr = x + (size_t)row * DIM_;
    float v[4];
    float s = 0.f, sq = 0.f;
#pragma unroll
    for (int i = 0; i < 4; i++) {
        float t = xr[threadIdx.x + i * 256];
        v[i] = t; s += t; sq += t * t;
    }
#pragma unroll
    for (int off = 16; off > 0; off >>= 1) {
        s  += __shfl_xor_sync(0xffffffffu, s,  off);
        sq += __shfl_xor_sync(0xffffffffu, sq, off);
    }
    __shared__ float sa[8], sb[8];
    int w = threadIdx.x >> 5, l = threadIdx.x & 31;
    if (l == 0) { sa[w] = s; sb[w] = sq; }
    __syncthreads();
    if (threadIdx.x == 0) {
        float a = 0.f, bq = 0.f;
#pragma unroll
        for (int i = 0; i < 8; i++) { a += sa[i]; bq += sb[i]; }
        sa[0] = a; sb[0] = bq;
    }
    __syncthreads();
    float mean = sa[0] * (1.0f / DIM_);
    float var  = sb[0] * (1.0f / DIM_) - mean * mean;
    float rstd = rsqrtf(var + 1e-5f);
    __half* outr = xn2 + (size_t)row * KP2;
    __half* xo   = x2  + (size_t)row * KP2;
#pragma unroll
    for (int i = 0; i < 4; i++) {
        int d = threadIdx.x + i * 256;
        float o = (v[i] - mean) * rstd * gamma[d];
        __half hi, lo; split_f16(o, hi, lo);
        outr[d] = hi; outr[DIM_ + d] = lo;
        split_f16(v[i], hi, lo);
        xo[d] = hi; xo[DIM_ + d] = lo;
    }
}

// ---------------- W [K=1024][N] -> W2T [N][2048] = [Whi|Whi] ----------------
__global__ void wconv_kernel(const float* __restrict__ W, __half* __restrict__ W2T, int N) {
    __shared__ float t[32][33];
    int k0 = blockIdx.y * 32, n0 = blockIdx.x * 32;
    int tx = threadIdx.x, ty = threadIdx.y;   // 32 x 8
#pragma unroll
    for (int i = 0; i < 4; i++)
        t[ty + i * 8][tx] = W[(size_t)(k0 + ty + i * 8) * N + n0 + tx];
    __syncthreads();
#pragma unroll
    for (int i = 0; i < 4; i++) {
        int n = n0 + ty + i * 8;
        int k = k0 + tx;
        __half hi = __float2half_rn(t[tx][ty + i * 8]);
        __half* o = W2T + (size_t)n * KP2;
        o[k] = hi; o[DIM_ + k] = hi;
    }
}

// ---------------- fp16 HMMA GEMM, 3-stage cp.async, 2 CTAs/SM ----------------
#define STAGES 3
#define BK 32
#define STRIDE 40
#define STG_ELEM (128 * STRIDE)
#define NKTILES (KP2 / BK)        // 64

__global__ void __launch_bounds__(256, 2) hgemm_kernel(
        const __half* __restrict__ A,   // [M][KP2]
        const __half* __restrict__ BT,  // [N][KP2]
        float* __restrict__ C, int M, int N) {
    __shared__ __half As[STAGES * STG_ELEM];
    __shared__ __half Bs[STAGES * STG_ELEM];

    const int tid  = threadIdx.x;
    const int wid  = tid >> 5, lane = tid & 31;
    const int wm   = wid & 1, wn = wid >> 1;
    const int g    = lane >> 2, tig = lane & 3;

    const int row0 = blockIdx.y * 128;
    const int col0 = blockIdx.x * 128;

    const int lrow = tid >> 1;
    const int lcol = (tid & 1) << 4;
    const __half* Ag = A  + (size_t)(row0 + lrow) * KP2 + lcol;
    const __half* Bg = BT + (size_t)(col0 + lrow) * KP2 + lcol;

    const uint32_t a_base = (uint32_t)__cvta_generic_to_shared(As);
    const uint32_t b_base = (uint32_t)__cvta_generic_to_shared(Bs);
    const uint32_t a_dst = a_base + (uint32_t)((lrow * STRIDE + lcol) * 2);
    const uint32_t b_dst = b_base + (uint32_t)((lrow * STRIDE + lcol) * 2);

    float acc[4][4][4];
#pragma unroll
    for (int mi = 0; mi < 4; mi++)
#pragma unroll
        for (int ni = 0; ni < 4; ni++)
#pragma unroll
            for (int e = 0; e < 4; e++) acc[mi][ni][e] = 0.f;

    const int a_row_in = lane & 15;
    const int a_k_in   = (lane >> 4) << 3;
    const int b_row_in = lane & 7;
    const int b_k_in   = ((lane >> 3) & 1) << 3;

    // prologue: issue stages 0..1
#pragma unroll
    for (int s = 0; s < STAGES - 1; s++) {
        uint32_t so = (uint32_t)(s * STG_ELEM * 2);
        cp16(a_dst + so,      Ag + s * BK);
        cp16(a_dst + so + 16, Ag + s * BK + 8);
        cp16(b_dst + so,      Bg + s * BK);
        cp16(b_dst + so + 16, Bg + s * BK + 8);
        cp_commit();
    }

    for (int t = 0; t < NKTILES; t++) {
        cp_wait1();
        __syncthreads();

        // issue stage t+2 (overwrites buffer (t-1)%3, fenced by the barrier above)
        if (t + STAGES - 1 < NKTILES) {
            uint32_t so = (uint32_t)(((t + STAGES - 1) % STAGES) * STG_ELEM * 2);
            const __half* ap = Ag + (t + STAGES - 1) * BK;
            const __half* bp = Bg + (t + STAGES - 1) * BK;
            cp16(a_dst + so,      ap);
            cp16(a_dst + so + 16, ap + 8);
            cp16(b_dst + so,      bp);
            cp16(b_dst + so + 16, bp + 8);
        }
        cp_commit();

        const uint32_t abuf = a_base + (uint32_t)((t % STAGES) * STG_ELEM * 2);
        const uint32_t bbuf = b_base + (uint32_t)((t % STAGES) * STG_ELEM * 2);
#pragma unroll
        for (int kk = 0; kk < BK; kk += 16) {
            uint32_t afr[4][4];
            uint32_t bfr[4][2];
#pragma unroll
            for (int mi = 0; mi < 4; mi++) {
                uint32_t a_addr = abuf +
                    (uint32_t)(((wm * 64 + mi * 16 + a_row_in) * STRIDE + kk + a_k_in) << 1);
                ldmx4(afr[mi], a_addr);
            }
#pragma unroll
            for (int ni = 0; ni < 4; ni++) {
                uint32_t b_addr = bbuf +
                    (uint32_t)(((wn * 32 + ni * 8 + b_row_in) * STRIDE + kk + b_k_in) << 1);
                ldmx2(bfr[ni], b_addr);
            }
#pragma unroll
            for (int mi = 0; mi < 4; mi++)
#pragma unroll
                for (int ni = 0; ni < 4; ni++)
                    mma16816h(acc[mi][ni], afr[mi], bfr[ni]);
        }
    }

#pragma unroll
    for (int mi = 0; mi < 4; mi++) {
        int r0 = row0 + wm * 64 + mi * 16 + g;
#pragma unroll
        for (int ni = 0; ni < 4; ni++) {
            int cc = col0 + wn * 32 + ni * 8 + tig * 2;
            float2 v0 = { acc[mi][ni][0], acc[mi][ni][1] };
            float2 v1 = { acc[mi][ni][2], acc[mi][ni][3] };
            *(float2*)&C[(size_t)r0 * N + cc]       = v0;
            *(float2*)&C[(size_t)(r0 + 8) * N + cc] = v1;
        }
    }
}

// ---------------- prep: emit bf16 hi/lo pairs Q3/K3/V3 ----------------
__global__ void prep_kernel(const float* __restrict__ q,
                            const float* __restrict__ kv,
                            const float* __restrict__ null_kv,
                            const float* __restrict__ q_scale,
                            const float* __restrict__ k_scale,
                            __nv_bfloat16* __restrict__ Q3,
                            __nv_bfloat16* __restrict__ K3,
                            __nv_bfloat16* __restrict__ V3) {
    int warp = (blockIdx.x * blockDim.x + threadIdx.x) >> 5;
    int lane = threadIdx.x & 31;
    if (warp >= B_ * H_ * J_) return;
    int bh = warp / J_;
    int j  = warp % J_;
    int b = bh / H_, h = bh % H_;
    int d0 = lane, d1 = lane + 32;

    float k0, k1, v0, v1;
    if (j < NNK_) {
        const float* nb = null_kv + ((size_t)(h * NNK_ + j) * 2) * DH_;
        k0 = nb[d0];        k1 = nb[d1];
        v0 = nb[DH_ + d0];  v1 = nb[DH_ + d1];
    } else {
        int n = j - NNK_;
        const float* base = kv + ((size_t)(b * N_ + n)) * (2 * DIM_) + h * DH_;
        k0 = base[d0];          k1 = base[d1];
        v0 = base[DIM_ + d0];   v1 = base[DIM_ + d1];
    }
    float ss = k0 * k0 + k1 * k1;
#pragma unroll
    for (int off = 16; off > 0; off >>= 1)
        ss += __shfl_xor_sync(0xffffffffu, ss, off);
    float inv = 1.0f / fmaxf(sqrtf(ss), 1e-12f);
    float ks0 = k0 * inv * k_scale[d0];
    float ks1 = k1 * inv * k_scale[d1];

    __nv_bfloat16 h0, l0, h1, l1;
    size_t ko = ((size_t)bh * J_PAD + j) * 128;
    split_bf16(ks0, h0, l0); split_bf16(ks1, h1, l1);
    K3[ko + d0] = h0; K3[ko + 64 + d0] = l0;
    K3[ko + d1] = h1; K3[ko + 64 + d1] = l1;

    split_bf16(v0, h0, l0); split_bf16(v1, h1, l1);
    V3[ko + d0] = h0; V3[ko + 64 + d0] = l0;
    V3[ko + d1] = h1; V3[ko + 64 + d1] = l1;

    if (j < N_) {
        int n = j;
        const float* qb = q + ((size_t)(b * N_ + n)) * DIM_ + h * DH_;
        float a0 = qb[d0], a1 = qb[d1];
        float qs2 = a0 * a0 + a1 * a1;
#pragma unroll
        for (int off = 16; off > 0; off >>= 1)
            qs2 += __shfl_xor_sync(0xffffffffu, qs2, off);
        float qinv = 1.0f / fmaxf(sqrtf(qs2), 1e-12f);
        float q0 = a0 * qinv * q_scale[d0];
        float q1 = a1 * qinv * q_scale[d1];
        size_t qo = ((size_t)bh * N_ + n) * 128;
        split_bf16(q0, h0, l0); split_bf16(q1, h1, l1);
        Q3[qo + d0] = h0; Q3[qo + 64 + d0] = l0;
        Q3[qo + d1] = h1; Q3[qo + 64 + d1] = l1;
    }
}

// ---------------- bf16 HMMA flash attention (3-term via frag reuse, 2 CTAs/SM) ----------------
// smem (bytes): Qs[128][136] @0 (34816), Ks[2][64][136] @34816 (2x17408),
//               Vs[2][64][136] @69632 (2x17408), mm[2][64] @104448 (512)
#define QS_OFF   0
#define KS_OFF   34816
#define KS_SZ    17408
#define VS_OFF   69632
#define VS_SZ    17408
#define MM_OFF   104448
#define SMEM_ATT 104960

__device__ __forceinline__ float softel(float s, int ig, int jg, int h,
                                        const float* __restrict__ bias) {
    bool ok = (jg <= ig + NNK_) && (jg < J_);
    float bv = 0.f;
    if (ok && jg >= NNK_) bv = __ldg(bias + ((size_t)h * N_ + ig) * N_ + (jg - NNK_));
    float t = fmaf(s, 11.541560327111707f, fmaf(bv, 1.4426950408889634f, -23.083120654223414f));
    float r;
    asm("ex2.approx.f32 %0, %1;" : "=f"(r) : "f"(t));
    return ok ? r : 0.f;
}

__device__ __forceinline__ void load_tile(int stage, int j0, int bh, int b, int tid,
        uint32_t sbase, char* smx,
        const __nv_bfloat16* __restrict__ K3, const __nv_bfloat16* __restrict__ V3,
        const int* __restrict__ mask) {
    uint32_t ks = sbase + KS_OFF + stage * KS_SZ;
    uint32_t vs = sbase + VS_OFF + stage * VS_SZ;
#pragma unroll
    for (int i = 0; i < 4; i++) {
        int idx = i * 256 + tid;
        int row = idx >> 4, c = idx & 15;
        uint32_t doff = (uint32_t)((row * 136 + c * 8) * 2);
        size_t soff = ((size_t)bh * J_PAD + j0 + row) * 128 + c * 8;
        cp16(ks + doff, K3 + soff);
        cp16(vs + doff, V3 + soff);
    }
    if (tid < 64) {
        int jg = j0 + tid;
        float mm = 1.f;
        if (jg >= NNK_) mm = (jg < J_ && mask[b * N_ + jg - NNK_] != 0) ? 1.f : 0.f;
        ((float*)(smx + MM_OFF))[stage * 64 + tid] = mm;
    }
}

__global__ void __launch_bounds__(256, 2) attn_mma_kernel(
        const __nv_bfloat16* __restrict__ Q3, const __nv_bfloat16* __restrict__ K3,
        const __nv_bfloat16* __restrict__ V3, const float* __restrict__ bias,
        const int* __restrict__ mask, __half* __restrict__ att2) {
    extern __shared__ char smx[];
    const uint32_t sbase = (uint32_t)__cvta_generic_to_shared(smx);

    const int tid = threadIdx.x;
    const int w = tid >> 5, lane = tid & 31;
    const int g = lane >> 2, tig = lane & 3;
    const int i0 = blockIdx.x * 128;
    const int bh = blockIdx.y, b = bh >> 4, h = bh & 15;
    const int iw = i0 + w * 16;
    const int ig0 = iw + g, ig1 = ig0 + 8;

    const int jtmax = min((i0 + 129) >> 6, J_PAD / 64 - 1);

    // Q tile: 128 rows x 128 bf16 [Qhi|Qlo]
#pragma unroll
    for (int i = 0; i < 8; i++) {
        int idx = i * 256 + tid;
        int row = idx >> 4, c = idx & 15;
        cp16(sbase + QS_OFF + (uint32_t)((row * 136 + c * 8) * 2),
             Q3 + ((size_t)bh * N_ + i0 + row) * 128 + c * 8);
    }
    load_tile(0, 0, bh, b, tid, sbase, smx, K3, V3, mask);
    cp_commit();

    float oacc[8][4];
#pragma unroll
    for (int d = 0; d < 8; d++)
#pragma unroll
        for (int e = 0; e < 4; e++) oacc[d][e] = 0.f;
    float lsum0 = 0.f, lsum1 = 0.f;

    int buf = 0;
    for (int jt = 0; jt <= jtmax; jt++) {
        const int j0 = jt * 64;
        if (jt < jtmax)
            load_tile(buf ^ 1, j0 + 64, bh, b, tid, sbase, smx, K3, V3, mask);
        cp_commit();
        cp_wait1();
        __syncthreads();

        const bool active = (j0 <= iw + 15 + NNK_);
        if (active) {
            const uint32_t ks = sbase + KS_OFF + buf * KS_SZ;
            const uint32_t vs = sbase + VS_OFF + buf * VS_SZ;
            const float* mm = (const float*)(smx + MM_OFF) + buf * 64;

            float sacc[8][4];
#pragma unroll
            for (int jf = 0; jf < 8; jf++)
#pragma unroll
                for (int e = 0; e < 4; e++) sacc[jf][e] = 0.f;

            const int a_row = w * 16 + (lane & 15);
            const int a_kin = (lane >> 4) << 3;
            const int b_row = lane & 7;
            const int b_kin = ((lane >> 3) & 1) << 3;
            // S = Qhi*Khi + Qlo*Khi + Qhi*Klo (frag reuse)
#pragma unroll
            for (int kc = 0; kc < 4; kc++) {
                uint32_t ah[4], al[4];
                ldmx4(ah, sbase + QS_OFF + (uint32_t)((a_row * 136 + kc * 16 + a_kin) << 1));
                ldmx4(al, sbase + QS_OFF + (uint32_t)((a_row * 136 + 64 + kc * 16 + a_kin) << 1));
#pragma unroll
                for (int jf = 0; jf < 8; jf++) {
                    uint32_t kh[2], kl[2];
                    uint32_t ka = ks + (uint32_t)(((jf * 8 + b_row) * 136 + kc * 16 + b_kin) << 1);
                    ldmx2(kh, ka);
                    ldmx2(kl, ka + 128);
                    mma16816(sacc[jf], ah, kh);
                    mma16816(sacc[jf], al, kh);
                    mma16816(sacc[jf], ah, kl);
                }
            }

            uint32_t phi2[8][2], plo2[8][2];
#pragma unroll
            for (int jf = 0; jf < 8; jf++) {
                int jc = j0 + jf * 8 + tig * 2;
                float m0 = mm[jf * 8 + tig * 2];
                float m1 = mm[jf * 8 + tig * 2 + 1];
                float p0 = softel(sacc[jf][0], ig0, jc,     h, bias) * m0;
                float p1 = softel(sacc[jf][1], ig0, jc + 1, h, bias) * m1;
                float p2 = softel(sacc[jf][2], ig1, jc,     h, bias) * m0;
                float p3 = softel(sacc[jf][3], ig1, jc + 1, h, bias) * m1;
                lsum0 += p0 + p1;
                lsum1 += p2 + p3;
                __nv_bfloat16 h0, l0, h1, l1, h2, l2, h3, l3;
                split_bf16(p0, h0, l0); split_bf16(p1, h1, l1);
                split_bf16(p2, h2, l2); split_bf16(p3, h3, l3);
                phi2[jf][0] = bpack(h0, h1); phi2[jf][1] = bpack(h2, h3);
                plo2[jf][0] = bpack(l0, l1); plo2[jf][1] = bpack(l2, l3);
            }

            // O += Phi*Vhi + Plo*Vhi + Phi*Vlo (frag reuse)
#pragma unroll
            for (int kc2 = 0; kc2 < 4; kc2++) {
                uint32_t ah[4] = { phi2[2 * kc2][0], phi2[2 * kc2][1],
                                   phi2[2 * kc2 + 1][0], phi2[2 * kc2 + 1][1] };
                uint32_t al[4] = { plo2[2 * kc2][0], plo2[2 * kc2][1],
                                   plo2[2 * kc2 + 1][0], plo2[2 * kc2 + 1][1] };
#pragma unroll
                for (int df = 0; df < 8; df++) {
                    uint32_t vh[2], vl[2];
                    uint32_t va = vs + (uint32_t)((((kc2 * 16 + (lane & 15)) * 136) + df * 8) << 1);
                    ldmx2t(vh, va);
                    ldmx2t(vl, va + 128);
                    mma16816(oacc[df], ah, vh);
                    mma16816(oacc[df], al, vh);
                    mma16816(oacc[df], ah, vl);
                }
            }
        }
        __syncthreads();
        buf ^= 1;
    }

    lsum0 += __shfl_xor_sync(0xffffffffu, lsum0, 1);
    lsum0 += __shfl_xor_sync(0xffffffffu, lsum0, 2);
    lsum1 += __shfl_xor_sync(0xffffffffu, lsum1, 1);
    lsum1 += __shfl_xor_sync(0xffffffffu, lsum1, 2);
    float inv0 = 1.0f / lsum0;
    float inv1 = 1.0f / lsum1;

    // epilogue: fp16 [hi|lo] rows for the fp16 output GEMM
#pragma unroll
    for (int df = 0; df < 8; df++) {
        float o0 = oacc[df][0] * inv0, o1 = oacc[df][1] * inv0;
        float o2 = oacc[df][2] * inv1, o3 = oacc[df][3] * inv1;
        __half h0, l0, h1, l1, h2, l2, h3, l3;
        split_f16(o0, h0, l0); split_f16(o1, h1, l1);
        split_f16(o2, h2, l2); split_f16(o3, h3, l3);
        {
            __half* p = att2 + ((size_t)(b * N_ + ig0)) * KP2 + h * DH_ + df * 8 + tig * 2;
            *(uint32_t*)(p)        = hpack(h0, h1);
            *(uint32_t*)(p + DIM_) = hpack(l0, l1);
        }
        {
            __half* p = att2 + ((size_t)(b * N_ + ig1)) * KP2 + h * DH_ + df * 8 + tig * 2;
            *(uint32_t*)(p)        = hpack(h2, h3);
            *(uint32_t*)(p + DIM_) = hpack(l2, l3);
        }
    }
}

// ---------------- launch ----------------
extern "C" void kernel_launch(void* const* d_in, const int* in_sizes, int n_in,
                              void* d_out, int out_size) {
    const float* x     = (const float*)d_in[0];
    const int*   mask  = (const int*)d_in[1];
    const float* bias  = (const float*)d_in[2];
    const float* gamma = (const float*)d_in[3];
    const float* nkv   = (const float*)d_in[4];
    const float* Wq    = (const float*)d_in[5];
    const float* Wkv   = (const float*)d_in[6];
    const float* qsc   = (const float*)d_in[7];
    const float* ksc   = (const float*)d_in[8];
    const float* Wo    = (const float*)d_in[9];
    float* out = (float*)d_out;

    __half *p_x2, *p_xn2, *p_att2, *p_Wq2T, *p_Wkv2T, *p_Wo2T;
    __nv_bfloat16 *p_Q3, *p_K3, *p_V3;
    float *p_q, *p_kv;
    cudaGetSymbolAddress((void**)&p_x2,    g_x2);
    cudaGetSymbolAddress((void**)&p_xn2,   g_xn2);
    cudaGetSymbolAddress((void**)&p_att2,  g_att2);
    cudaGetSymbolAddress((void**)&p_Wq2T,  g_Wq2T);
    cudaGetSymbolAddress((void**)&p_Wkv2T, g_Wkv2T);
    cudaGetSymbolAddress((void**)&p_Wo2T,  g_Wo2T);
    cudaGetSymbolAddress((void**)&p_q,     g_q);
    cudaGetSymbolAddress((void**)&p_kv,    g_kv);
    cudaGetSymbolAddress((void**)&p_Q3,    g_Q3);
    cudaGetSymbolAddress((void**)&p_K3,    g_K3);
    cudaGetSymbolAddress((void**)&p_V3,    g_V3);

    dim3 wb(32, 8);
    ln_kernel<<<MTOT, 256>>>(x, gamma, p_xn2, p_x2);                                  // 1
    wconv_kernel<<<dim3(DIM_ / 32,     DIM_ / 32), wb>>>(Wq,  p_Wq2T,  DIM_);         // 2
    wconv_kernel<<<dim3(2 * DIM_ / 32, DIM_ / 32), wb>>>(Wkv, p_Wkv2T, 2 * DIM_);     // 3

    dim3 gq(DIM_ / 128, MTOT / 128);
    hgemm_kernel<<<gq, 256>>>(p_xn2, p_Wq2T, p_q, MTOT, DIM_);                        // 4 (profiled)
    dim3 gkv(2 * DIM_ / 128, MTOT / 128);
    hgemm_kernel<<<gkv, 256>>>(p_x2, p_Wkv2T, p_kv, MTOT, 2 * DIM_);                  // 5

    wconv_kernel<<<dim3(DIM_ / 32,     DIM_ / 32), wb>>>(Wo,  p_Wo2T,  DIM_);         // 6

    int nwarp = B_ * H_ * J_;
    prep_kernel<<<(nwarp + 7) / 8, 256>>>(p_q, p_kv, nkv, qsc, ksc, p_Q3, p_K3, p_V3);// 7

    cudaFuncSetAttribute(attn_mma_kernel, cudaFuncAttributeMaxDynamicSharedMemorySize, SMEM_ATT);
    dim3 ga(N_ / 128, B_ * H_);
    attn_mma_kernel<<<ga, 256, SMEM_ATT>>>(p_Q3, p_K3, p_V3, bias, mask, p_att2);     // 8

    hgemm_kernel<<<gq, 256>>>(p_att2, p_Wo2T, out, MTOT, DIM_);                       // 9
}

// round 12
// speedup vs baseline: 2.4058x; 1.2143x over previous
#include <cuda_runtime.h>
#include <cuda_fp16.h>
#include <cuda_bf16.h>
#include <math.h>
#include <stdint.h>

// ---------------- problem constants ----------------
#define B_    2
#define N_    2048
#define DIM_  1024
#define H_    16
#define DH_   64
#define NNK_  2
#define J_    (N_ + NNK_)    // 2050
#define J_PAD 2112           // 33 tiles of 64
#define KP2   2048           // fp16 2-term split K' (row stride)
#define MTOT  (B_ * N_)      // 4096

// ---------------- scratch (device globals; no allocs allowed) ----------------
__device__ __align__(16) __half g_x2   [MTOT * KP2];      // [xhi|xlo]
__device__ __align__(16) __half g_xn2  [MTOT * KP2];      // layernorm(x) split
__device__ __align__(16) __half g_att2 [MTOT * KP2];      // attention out split
__device__ __align__(16) __half g_Wq2T [DIM_ * KP2];      // [N][Whi|Whi]
__device__ __align__(16) __half g_Wkv2T[2 * DIM_ * KP2];
__device__ __align__(16) __half g_Wo2T [DIM_ * KP2];
__device__ float g_q  [MTOT * DIM_];
__device__ float g_kv [MTOT * 2 * DIM_];
// attention operands: bf16 hi/lo pairs (3-term math via frag reuse); padding stays zero
__device__ __align__(16) __nv_bfloat16 g_Q3 [B_ * H_ * N_ * 128];     // [Qhi|Qlo]
__device__ __align__(16) __nv_bfloat16 g_K3 [B_ * H_ * J_PAD * 128];  // [Khi|Klo]
__device__ __align__(16) __nv_bfloat16 g_V3 [B_ * H_ * J_PAD * 128];  // [Vhi|Vlo]

// ---------------- helpers ----------------
__device__ __forceinline__ void split_f16(float v, __half& hi, __half& lo) {
    hi = __float2half_rn(v);
    lo = __float2half_rn(v - __half2float(hi));
}
__device__ __forceinline__ void split_bf16(float v, __nv_bfloat16& hi, __nv_bfloat16& lo) {
    hi = __float2bfloat16_rn(v);
    lo = __float2bfloat16_rn(v - __bfloat162float(hi));
}
__device__ __forceinline__ uint32_t hpack(__half a, __half b) {
    __half2 t = __halves2half2(a, b);
    return *reinterpret_cast<uint32_t*>(&t);
}
__device__ __forceinline__ uint32_t bpack(__nv_bfloat16 a, __nv_bfloat16 b) {
    __nv_bfloat162 t = __halves2bfloat162(a, b);
    return *reinterpret_cast<uint32_t*>(&t);
}
__device__ __forceinline__ void ldmx4(uint32_t* r, uint32_t addr) {
    asm volatile("ldmatrix.sync.aligned.m8n8.x4.shared.b16 {%0,%1,%2,%3}, [%4];"
                 : "=r"(r[0]), "=r"(r[1]), "=r"(r[2]), "=r"(r[3]) : "r"(addr));
}
__device__ __forceinline__ void ldmx2(uint32_t* r, uint32_t addr) {
    asm volatile("ldmatrix.sync.aligned.m8n8.x2.shared.b16 {%0,%1}, [%2];"
                 : "=r"(r[0]), "=r"(r[1]) : "r"(addr));
}
__device__ __forceinline__ void ldmx2t(uint32_t* r, uint32_t addr) {
    asm volatile("ldmatrix.sync.aligned.m8n8.x2.trans.shared.b16 {%0,%1}, [%2];"
                 : "=r"(r[0]), "=r"(r[1]) : "r"(addr));
}
__device__ __forceinline__ void mma16816h(float* d, const uint32_t* a, const uint32_t* b) {
    asm volatile("mma.sync.aligned.m16n8k16.row.col.f32.f16.f16.f32 {%0,%1,%2,%3},{%4,%5,%6,%7},{%8,%9},{%0,%1,%2,%3};"
                 : "+f"(d[0]), "+f"(d[1]), "+f"(d[2]), "+f"(d[3])
                 : "r"(a[0]), "r"(a[1]), "r"(a[2]), "r"(a[3]), "r"(b[0]), "r"(b[1]));
}
__device__ __forceinline__ void mma16816(float* d, const uint32_t* a, const uint32_t* b) {
    asm volatile("mma.sync.aligned.m16n8k16.row.col.f32.bf16.bf16.f32 {%0,%1,%2,%3},{%4,%5,%6,%7},{%8,%9},{%0,%1,%2,%3};"
                 : "+f"(d[0]), "+f"(d[1]), "+f"(d[2]), "+f"(d[3])
                 : "r"(a[0]), "r"(a[1]), "r"(a[2]), "r"(a[3]), "r"(b[0]), "r"(b[1]));
}
__device__ __forceinline__ void cp16(uint32_t saddr, const void* gptr) {
    asm volatile("cp.async.cg.shared.global [%0], [%1], 16;" :: "r"(saddr), "l"(gptr));
}
__device__ __forceinline__ void cp_commit() { asm volatile("cp.async.commit_group;"); }
__device__ __forceinline__ void cp_wait1() { asm volatile("cp.async.wait_group 1;"); }

// ---------------- LayerNorm -> xn2, and x -> x2 (fused, fp16 splits) ----------------
__global__ void ln_kernel(const float* __restrict__ x,
                          const float* __restrict__ gamma,
                          __half* __restrict__ xn2,
                          __half* __restrict__ x2) {
    int row = blockIdx.x;
    const float* xr = x + (size_t)row * DIM_;
    float v[4];
    float s = 0.f, sq = 0.f;
#pragma unroll
    for (int i = 0; i < 4; i++) {
        float t = xr[threadIdx.x + i * 256];
        v[i] = t; s += t; sq += t * t;
    }
#pragma unroll
    for (int off = 16; off > 0; off >>= 1) {
        s  += __shfl_xor_sync(0xffffffffu, s,  off);
        sq += __shfl_xor_sync(0xffffffffu, sq, off);
    }
    __shared__ float sa[8], sb[8];
    int w = threadIdx.x >> 5, l = threadIdx.x & 31;
    if (l == 0) { sa[w] = s; sb[w] = sq; }
    __syncthreads();
    if (threadIdx.x == 0) {
        float a = 0.f, bq = 0.f;
#pragma unroll
        for (int i = 0; i < 8; i++) { a += sa[i]; bq += sb[i]; }
        sa[0] = a; sb[0] = bq;
    }
    __syncthreads();
    float mean = sa[0] * (1.0f / DIM_);
    float var  = sb[0] * (1.0f / DIM_) - mean * mean;
    float rstd = rsqrtf(var + 1e-5f);
    __half* outr = xn2 + (size_t)row * KP2;
    __half* xo   = x2  + (size_t)row * KP2;
#pragma unroll
    for (int i = 0; i < 4; i++) {
        int d = threadIdx.x + i * 256;
        float o = (v[i] - mean) * rstd * gamma[d];
        __half hi, lo; split_f16(o, hi, lo);
        outr[d] = hi; outr[DIM_ + d] = lo;
        split_f16(v[i], hi, lo);
        xo[d] = hi; xo[DIM_ + d] = lo;
    }
}

// ---------------- W [K=1024][N] -> W2T [N][2048] = [Whi|Whi] ----------------
__global__ void wconv_kernel(const float* __restrict__ W, __half* __restrict__ W2T, int N) {
    __shared__ float t[32][33];
    int k0 = blockIdx.y * 32, n0 = blockIdx.x * 32;
    int tx = threadIdx.x, ty = threadIdx.y;   // 32 x 8
#pragma unroll
    for (int i = 0; i < 4; i++)
        t[ty + i * 8][tx] = W[(size_t)(k0 + ty + i * 8) * N + n0 + tx];
    __syncthreads();
#pragma unroll
    for (int i = 0; i < 4; i++) {
        int n = n0 + ty + i * 8;
        int k = k0 + tx;
        __half hi = __float2half_rn(t[tx][ty + i * 8]);
        __half* o = W2T + (size_t)n * KP2;
        o[k] = hi; o[DIM_ + k] = hi;
    }
}

// ---------------- fp16 HMMA GEMM, 3-stage cp.async, 2 CTAs/SM ----------------
// Row stride fixed at KP2; nkt selects K-depth: nkt=32 -> 1-term (hi only),
// nkt=64 -> 2-term (full [hi|lo] x [Whi|Whi]).
#define STAGES 3
#define BK 32
#define STRIDE 40
#define STG_ELEM (128 * STRIDE)

__global__ void __launch_bounds__(256, 2) hgemm_kernel(
        const __half* __restrict__ A,   // [M][KP2]
        const __half* __restrict__ BT,  // [N][KP2]
        float* __restrict__ C, int M, int N, int nkt) {
    __shared__ __half As[STAGES * STG_ELEM];
    __shared__ __half Bs[STAGES * STG_ELEM];

    const int tid  = threadIdx.x;
    const int wid  = tid >> 5, lane = tid & 31;
    const int wm   = wid & 1, wn = wid >> 1;
    const int g    = lane >> 2, tig = lane & 3;

    const int row0 = blockIdx.y * 128;
    const int col0 = blockIdx.x * 128;

    const int lrow = tid >> 1;
    const int lcol = (tid & 1) << 4;
    const __half* Ag = A  + (size_t)(row0 + lrow) * KP2 + lcol;
    const __half* Bg = BT + (size_t)(col0 + lrow) * KP2 + lcol;

    const uint32_t a_base = (uint32_t)__cvta_generic_to_shared(As);
    const uint32_t b_base = (uint32_t)__cvta_generic_to_shared(Bs);
    const uint32_t a_dst = a_base + (uint32_t)((lrow * STRIDE + lcol) * 2);
    const uint32_t b_dst = b_base + (uint32_t)((lrow * STRIDE + lcol) * 2);

    float acc[4][4][4];
#pragma unroll
    for (int mi = 0; mi < 4; mi++)
#pragma unroll
        for (int ni = 0; ni < 4; ni++)
#pragma unroll
            for (int e = 0; e < 4; e++) acc[mi][ni][e] = 0.f;

    const int a_row_in = lane & 15;
    const int a_k_in   = (lane >> 4) << 3;
    const int b_row_in = lane & 7;
    const int b_k_in   = ((lane >> 3) & 1) << 3;

    // prologue: issue stages 0..1
#pragma unroll
    for (int s = 0; s < STAGES - 1; s++) {
        uint32_t so = (uint32_t)(s * STG_ELEM * 2);
        cp16(a_dst + so,      Ag + s * BK);
        cp16(a_dst + so + 16, Ag + s * BK + 8);
        cp16(b_dst + so,      Bg + s * BK);
        cp16(b_dst + so + 16, Bg + s * BK + 8);
        cp_commit();
    }

    for (int t = 0; t < nkt; t++) {
        cp_wait1();
        __syncthreads();

        if (t + STAGES - 1 < nkt) {
            uint32_t so = (uint32_t)(((t + STAGES - 1) % STAGES) * STG_ELEM * 2);
            const __half* ap = Ag + (t + STAGES - 1) * BK;
            const __half* bp = Bg + (t + STAGES - 1) * BK;
            cp16(a_dst + so,      ap);
            cp16(a_dst + so + 16, ap + 8);
            cp16(b_dst + so,      bp);
            cp16(b_dst + so + 16, bp + 8);
        }
        cp_commit();

        const uint32_t abuf = a_base + (uint32_t)((t % STAGES) * STG_ELEM * 2);
        const uint32_t bbuf = b_base + (uint32_t)((t % STAGES) * STG_ELEM * 2);
#pragma unroll
        for (int kk = 0; kk < BK; kk += 16) {
            uint32_t afr[4][4];
            uint32_t bfr[4][2];
#pragma unroll
            for (int mi = 0; mi < 4; mi++) {
                uint32_t a_addr = abuf +
                    (uint32_t)(((wm * 64 + mi * 16 + a_row_in) * STRIDE + kk + a_k_in) << 1);
                ldmx4(afr[mi], a_addr);
            }
#pragma unroll
            for (int ni = 0; ni < 4; ni++) {
                uint32_t b_addr = bbuf +
                    (uint32_t)(((wn * 32 + ni * 8 + b_row_in) * STRIDE + kk + b_k_in) << 1);
                ldmx2(bfr[ni], b_addr);
            }
#pragma unroll
            for (int mi = 0; mi < 4; mi++)
#pragma unroll
                for (int ni = 0; ni < 4; ni++)
                    mma16816h(acc[mi][ni], afr[mi], bfr[ni]);
        }
    }

#pragma unroll
    for (int mi = 0; mi < 4; mi++) {
        int r0 = row0 + wm * 64 + mi * 16 + g;
#pragma unroll
        for (int ni = 0; ni < 4; ni++) {
            int cc = col0 + wn * 32 + ni * 8 + tig * 2;
            float2 v0 = { acc[mi][ni][0], acc[mi][ni][1] };
            float2 v1 = { acc[mi][ni][2], acc[mi][ni][3] };
            *(float2*)&C[(size_t)r0 * N + cc]       = v0;
            *(float2*)&C[(size_t)(r0 + 8) * N + cc] = v1;
        }
    }
}

// ---------------- prep: emit bf16 hi/lo pairs Q3/K3/V3 ----------------
__global__ void prep_kernel(const float* __restrict__ q,
                            const float* __restrict__ kv,
                            const float* __restrict__ null_kv,
                            const float* __restrict__ q_scale,
                            const float* __restrict__ k_scale,
                            __nv_bfloat16* __restrict__ Q3,
                            __nv_bfloat16* __restrict__ K3,
                            __nv_bfloat16* __restrict__ V3) {
    int warp = (blockIdx.x * blockDim.x + threadIdx.x) >> 5;
    int lane = threadIdx.x & 31;
    if (warp >= B_ * H_ * J_) return;
    int bh = warp / J_;
    int j  = warp % J_;
    int b = bh / H_, h = bh % H_;
    int d0 = lane, d1 = lane + 32;

    float k0, k1, v0, v1;
    if (j < NNK_) {
        const float* nb = null_kv + ((size_t)(h * NNK_ + j) * 2) * DH_;
        k0 = nb[d0];        k1 = nb[d1];
        v0 = nb[DH_ + d0];  v1 = nb[DH_ + d1];
    } else {
        int n = j - NNK_;
        const float* base = kv + ((size_t)(b * N_ + n)) * (2 * DIM_) + h * DH_;
        k0 = base[d0];          k1 = base[d1];
        v0 = base[DIM_ + d0];   v1 = base[DIM_ + d1];
    }
    float ss = k0 * k0 + k1 * k1;
#pragma unroll
    for (int off = 16; off > 0; off >>= 1)
        ss += __shfl_xor_sync(0xffffffffu, ss, off);
    float inv = 1.0f / fmaxf(sqrtf(ss), 1e-12f);
    float ks0 = k0 * inv * k_scale[d0];
    float ks1 = k1 * inv * k_scale[d1];

    __nv_bfloat16 h0, l0, h1, l1;
    size_t ko = ((size_t)bh * J_PAD + j) * 128;
    split_bf16(ks0, h0, l0); split_bf16(ks1, h1, l1);
    K3[ko + d0] = h0; K3[ko + 64 + d0] = l0;
    K3[ko + d1] = h1; K3[ko + 64 + d1] = l1;

    split_bf16(v0, h0, l0); split_bf16(v1, h1, l1);
    V3[ko + d0] = h0; V3[ko + 64 + d0] = l0;
    V3[ko + d1] = h1; V3[ko + 64 + d1] = l1;

    if (j < N_) {
        int n = j;
        const float* qb = q + ((size_t)(b * N_ + n)) * DIM_ + h * DH_;
        float a0 = qb[d0], a1 = qb[d1];
        float qs2 = a0 * a0 + a1 * a1;
#pragma unroll
        for (int off = 16; off > 0; off >>= 1)
            qs2 += __shfl_xor_sync(0xffffffffu, qs2, off);
        float qinv = 1.0f / fmaxf(sqrtf(qs2), 1e-12f);
        float q0 = a0 * qinv * q_scale[d0];
        float q1 = a1 * qinv * q_scale[d1];
        size_t qo = ((size_t)bh * N_ + n) * 128;
        split_bf16(q0, h0, l0); split_bf16(q1, h1, l1);
        Q3[qo + d0] = h0; Q3[qo + 64 + d0] = l0;
        Q3[qo + d1] = h1; Q3[qo + 64 + d1] = l1;
    }
}

// ---------------- bf16 HMMA flash attention (3-term via frag reuse, 2 CTAs/SM) ----------------
#define QS_OFF   0
#define KS_OFF   34816
#define KS_SZ    17408
#define VS_OFF   69632
#define VS_SZ    17408
#define MM_OFF   104448
#define SMEM_ATT 104960

__device__ __forceinline__ float softel(float s, int ig, int jg, int h,
                                        const float* __restrict__ bias) {
    bool ok = (jg <= ig + NNK_) && (jg < J_);
    float bv = 0.f;
    if (ok && jg >= NNK_) bv = __ldg(bias + ((size_t)h * N_ + ig) * N_ + (jg - NNK_));
    float t = fmaf(s, 11.541560327111707f, fmaf(bv, 1.4426950408889634f, -23.083120654223414f));
    float r;
    asm("ex2.approx.f32 %0, %1;" : "=f"(r) : "f"(t));
    return ok ? r : 0.f;
}

__device__ __forceinline__ void load_tile(int stage, int j0, int bh, int b, int tid,
        uint32_t sbase, char* smx,
        const __nv_bfloat16* __restrict__ K3, const __nv_bfloat16* __restrict__ V3,
        const int* __restrict__ mask) {
    uint32_t ks = sbase + KS_OFF + stage * KS_SZ;
    uint32_t vs = sbase + VS_OFF + stage * VS_SZ;
#pragma unroll
    for (int i = 0; i < 4; i++) {
        int idx = i * 256 + tid;
        int row = idx >> 4, c = idx & 15;
        uint32_t doff = (uint32_t)((row * 136 + c * 8) * 2);
        size_t soff = ((size_t)bh * J_PAD + j0 + row) * 128 + c * 8;
        cp16(ks + doff, K3 + soff);
        cp16(vs + doff, V3 + soff);
    }
    if (tid < 64) {
        int jg = j0 + tid;
        float mm = 1.f;
        if (jg >= NNK_) mm = (jg < J_ && mask[b * N_ + jg - NNK_] != 0) ? 1.f : 0.f;
        ((float*)(smx + MM_OFF))[stage * 64 + tid] = mm;
    }
}

__global__ void __launch_bounds__(256, 2) attn_mma_kernel(
        const __nv_bfloat16* __restrict__ Q3, const __nv_bfloat16* __restrict__ K3,
        const __nv_bfloat16* __restrict__ V3, const float* __restrict__ bias,
        const int* __restrict__ mask, __half* __restrict__ att2) {
    extern __shared__ char smx[];
    const uint32_t sbase = (uint32_t)__cvta_generic_to_shared(smx);

    const int tid = threadIdx.x;
    const int w = tid >> 5, lane = tid & 31;
    const int g = lane >> 2, tig = lane & 3;
    // heavy CTAs (large ib -> more j-tiles) first for better wave packing
    const int ib = (int)gridDim.x - 1 - (int)blockIdx.x;
    const int i0 = ib * 128;
    const int bh = blockIdx.y, b = bh >> 4, h = bh & 15;
    const int iw = i0 + w * 16;
    const int ig0 = iw + g, ig1 = ig0 + 8;

    const int jtmax = min((i0 + 129) >> 6, J_PAD / 64 - 1);

    // Q tile: 128 rows x 128 bf16 [Qhi|Qlo]
#pragma unroll
    for (int i = 0; i < 8; i++) {
        int idx = i * 256 + tid;
        int row = idx >> 4, c = idx & 15;
        cp16(sbase + QS_OFF + (uint32_t)((row * 136 + c * 8) * 2),
             Q3 + ((size_t)bh * N_ + i0 + row) * 128 + c * 8);
    }
    load_tile(0, 0, bh, b, tid, sbase, smx, K3, V3, mask);
    cp_commit();

    float oacc[8][4];
#pragma unroll
    for (int d = 0; d < 8; d++)
#pragma unroll
        for (int e = 0; e < 4; e++) oacc[d][e] = 0.f;
    float lsum0 = 0.f, lsum1 = 0.f;

    int buf = 0;
    for (int jt = 0; jt <= jtmax; jt++) {
        const int j0 = jt * 64;
        if (jt < jtmax)
            load_tile(buf ^ 1, j0 + 64, bh, b, tid, sbase, smx, K3, V3, mask);
        cp_commit();
        cp_wait1();
        __syncthreads();

        const bool active = (j0 <= iw + 15 + NNK_);
        if (active) {
            const uint32_t ks = sbase + KS_OFF + buf * KS_SZ;
            const uint32_t vs = sbase + VS_OFF + buf * VS_SZ;
            const float* mm = (const float*)(smx + MM_OFF) + buf * 64;

            float sacc[8][4];
#pragma unroll
            for (int jf = 0; jf < 8; jf++)
#pragma unroll
                for (int e = 0; e < 4; e++) sacc[jf][e] = 0.f;

            const int a_row = w * 16 + (lane & 15);
            const int a_kin = (lane >> 4) << 3;
            const int b_row = lane & 7;
            const int b_kin = ((lane >> 3) & 1) << 3;
            // S = Qhi*Khi + Qlo*Khi + Qhi*Klo (frag reuse)
#pragma unroll
            for (int kc = 0; kc < 4; kc++) {
                uint32_t ah[4], al[4];
                ldmx4(ah, sbase + QS_OFF + (uint32_t)((a_row * 136 + kc * 16 + a_kin) << 1));
                ldmx4(al, sbase + QS_OFF + (uint32_t)((a_row * 136 + 64 + kc * 16 + a_kin) << 1));
#pragma unroll
                for (int jf = 0; jf < 8; jf++) {
                    uint32_t kh[2], kl[2];
                    uint32_t ka = ks + (uint32_t)(((jf * 8 + b_row) * 136 + kc * 16 + b_kin) << 1);
                    ldmx2(kh, ka);
                    ldmx2(kl, ka + 128);
                    mma16816(sacc[jf], ah, kh);
                    mma16816(sacc[jf], al, kh);
                    mma16816(sacc[jf], ah, kl);
                }
            }

            uint32_t phi2[8][2], plo2[8][2];
#pragma unroll
            for (int jf = 0; jf < 8; jf++) {
                int jc = j0 + jf * 8 + tig * 2;
                float m0 = mm[jf * 8 + tig * 2];
                float m1 = mm[jf * 8 + tig * 2 + 1];
                float p0 = softel(sacc[jf][0], ig0, jc,     h, bias) * m0;
                float p1 = softel(sacc[jf][1], ig0, jc + 1, h, bias) * m1;
                float p2 = softel(sacc[jf][2], ig1, jc,     h, bias) * m0;
                float p3 = softel(sacc[jf][3], ig1, jc + 1, h, bias) * m1;
                lsum0 += p0 + p1;
                lsum1 += p2 + p3;
                __nv_bfloat16 h0, l0, h1, l1, h2, l2, h3, l3;
                split_bf16(p0, h0, l0); split_bf16(p1, h1, l1);
                split_bf16(p2, h2, l2); split_bf16(p3, h3, l3);
                phi2[jf][0] = bpack(h0, h1); phi2[jf][1] = bpack(h2, h3);
                plo2[jf][0] = bpack(l0, l1); plo2[jf][1] = bpack(l2, l3);
            }

            // O += Phi*Vhi + Plo*Vhi + Phi*Vlo (frag reuse)
#pragma unroll
            for (int kc2 = 0; kc2 < 4; kc2++) {
                uint32_t ah[4] = { phi2[2 * kc2][0], phi2[2 * kc2][1],
                                   phi2[2 * kc2 + 1][0], phi2[2 * kc2 + 1][1] };
                uint32_t al[4] = { plo2[2 * kc2][0], plo2[2 * kc2][1],
                                   plo2[2 * kc2 + 1][0], plo2[2 * kc2 + 1][1] };
#pragma unroll
                for (int df = 0; df < 8; df++) {
                    uint32_t vh[2], vl[2];
                    uint32_t va = vs + (uint32_t)((((kc2 * 16 + (lane & 15)) * 136) + df * 8) << 1);
                    ldmx2t(vh, va);
                    ldmx2t(vl, va + 128);
                    mma16816(oacc[df], ah, vh);
                    mma16816(oacc[df], al, vh);
                    mma16816(oacc[df], ah, vl);
                }
            }
        }
        __syncthreads();
        buf ^= 1;
    }

    lsum0 += __shfl_xor_sync(0xffffffffu, lsum0, 1);
    lsum0 += __shfl_xor_sync(0xffffffffu, lsum0, 2);
    lsum1 += __shfl_xor_sync(0xffffffffu, lsum1, 1);
    lsum1 += __shfl_xor_sync(0xffffffffu, lsum1, 2);
    float inv0 = 1.0f / lsum0;
    float inv1 = 1.0f / lsum1;

    // epilogue: fp16 [hi|lo] rows for the fp16 output GEMM
#pragma unroll
    for (int df = 0; df < 8; df++) {
        float o0 = oacc[df][0] * inv0, o1 = oacc[df][1] * inv0;
        float o2 = oacc[df][2] * inv1, o3 = oacc[df][3] * inv1;
        __half h0, l0, h1, l1, h2, l2, h3, l3;
        split_f16(o0, h0, l0); split_f16(o1, h1, l1);
        split_f16(o2, h2, l2); split_f16(o3, h3, l3);
        {
            __half* p = att2 + ((size_t)(b * N_ + ig0)) * KP2 + h * DH_ + df * 8 + tig * 2;
            *(uint32_t*)(p)        = hpack(h0, h1);
            *(uint32_t*)(p + DIM_) = hpack(l0, l1);
        }
        {
            __half* p = att2 + ((size_t)(b * N_ + ig1)) * KP2 + h * DH_ + df * 8 + tig * 2;
            *(uint32_t*)(p)        = hpack(h2, h3);
            *(uint32_t*)(p + DIM_) = hpack(l2, l3);
        }
    }
}

// ---------------- launch ----------------
extern "C" void kernel_launch(void* const* d_in, const int* in_sizes, int n_in,
                              void* d_out, int out_size) {
    const float* x     = (const float*)d_in[0];
    const int*   mask  = (const int*)d_in[1];
    const float* bias  = (const float*)d_in[2];
    const float* gamma = (const float*)d_in[3];
    const float* nkv   = (const float*)d_in[4];
    const float* Wq    = (const float*)d_in[5];
    const float* Wkv   = (const float*)d_in[6];
    const float* qsc   = (const float*)d_in[7];
    const float* ksc   = (const float*)d_in[8];
    const float* Wo    = (const float*)d_in[9];
    float* out = (float*)d_out;

    __half *p_x2, *p_xn2, *p_att2, *p_Wq2T, *p_Wkv2T, *p_Wo2T;
    __nv_bfloat16 *p_Q3, *p_K3, *p_V3;
    float *p_q, *p_kv;
    cudaGetSymbolAddress((void**)&p_x2,    g_x2);
    cudaGetSymbolAddress((void**)&p_xn2,   g_xn2);
    cudaGetSymbolAddress((void**)&p_att2,  g_att2);
    cudaGetSymbolAddress((void**)&p_Wq2T,  g_Wq2T);
    cudaGetSymbolAddress((void**)&p_Wkv2T, g_Wkv2T);
    cudaGetSymbolAddress((void**)&p_Wo2T,  g_Wo2T);
    cudaGetSymbolAddress((void**)&p_q,     g_q);
    cudaGetSymbolAddress((void**)&p_kv,    g_kv);
    cudaGetSymbolAddress((void**)&p_Q3,    g_Q3);
    cudaGetSymbolAddress((void**)&p_K3,    g_K3);
    cudaGetSymbolAddress((void**)&p_V3,    g_V3);

    dim3 wb(32, 8);
    ln_kernel<<<MTOT, 256>>>(x, gamma, p_xn2, p_x2);                                  // 1
    wconv_kernel<<<dim3(DIM_ / 32,     DIM_ / 32), wb>>>(Wq,  p_Wq2T,  DIM_);         // 2
    wconv_kernel<<<dim3(2 * DIM_ / 32, DIM_ / 32), wb>>>(Wkv, p_Wkv2T, 2 * DIM_);     // 3

    dim3 gq(DIM_ / 128, MTOT / 128);
    // Q and KV projections: 1-term fp16 (hi halves only, nkt = 32)
    hgemm_kernel<<<gq, 256>>>(p_xn2, p_Wq2T, p_q, MTOT, DIM_, DIM_ / BK);             // 4 (profiled)
    dim3 gkv(2 * DIM_ / 128, MTOT / 128);
    hgemm_kernel<<<gkv, 256>>>(p_x2, p_Wkv2T, p_kv, MTOT, 2 * DIM_, DIM_ / BK);       // 5

    wconv_kernel<<<dim3(DIM_ / 32,     DIM_ / 32), wb>>>(Wo,  p_Wo2T,  DIM_);         // 6

    int nwarp = B_ * H_ * J_;
    prep_kernel<<<(nwarp + 7) / 8, 256>>>(p_q, p_kv, nkv, qsc, ksc, p_Q3, p_K3, p_V3);// 7

    cudaFuncSetAttribute(attn_mma_kernel, cudaFuncAttributeMaxDynamicSharedMemorySize, SMEM_ATT);
    dim3 ga(N_ / 128, B_ * H_);
    attn_mma_kernel<<<ga, 256, SMEM_ATT>>>(p_Q3, p_K3, p_V3, bias, mask, p_att2);     // 8

    // output projection: 2-term (nkt = 64)
    hgemm_kernel<<<gq, 256>>>(p_att2, p_Wo2T, out, MTOT, DIM_, KP2 / BK);             // 9
}

// round 13
// speedup vs baseline: 2.6704x; 1.1100x over previous
#include <cuda_runtime.h>
#include <cuda_fp16.h>
#include <cuda_bf16.h>
#include <math.h>
#include <stdint.h>

// ---------------- problem constants ----------------
#define B_    2
#define N_    2048
#define DIM_  1024
#define H_    16
#define DH_   64
#define NNK_  2
#define J_    (N_ + NNK_)    // 2050
#define J_PAD 2112           // 33 tiles of 64
#define KP2   2048           // fp16 2-term split K' (row stride)
#define MTOT  (B_ * N_)      // 4096

// ---------------- scratch (device globals; no allocs allowed) ----------------
__device__ __align__(16) __half g_x2   [MTOT * KP2];      // [xhi|xlo]
__device__ __align__(16) __half g_xn2  [MTOT * KP2];      // layernorm(x) split
__device__ __align__(16) __half g_att2 [MTOT * KP2];      // attention out split
__device__ __align__(16) __half g_Wq2T [DIM_ * KP2];      // [N][Whi|Whi]
__device__ __align__(16) __half g_Wkv2T[2 * DIM_ * KP2];
__device__ __align__(16) __half g_Wo2T [DIM_ * KP2];
__device__ float g_q  [MTOT * DIM_];
__device__ float g_kv [MTOT * 2 * DIM_];
// attention operands: bf16 hi/lo pairs (3-term math via frag reuse); padding stays zero
__device__ __align__(16) __nv_bfloat16 g_Q3 [B_ * H_ * N_ * 128];     // [Qhi|Qlo]
__device__ __align__(16) __nv_bfloat16 g_K3 [B_ * H_ * J_PAD * 128];  // [Khi|Klo]
__device__ __align__(16) __nv_bfloat16 g_V3 [B_ * H_ * J_PAD * 128];  // [Vhi|Vlo]

// ---------------- helpers ----------------
__device__ __forceinline__ void split_f16(float v, __half& hi, __half& lo) {
    hi = __float2half_rn(v);
    lo = __float2half_rn(v - __half2float(hi));
}
__device__ __forceinline__ void split_bf16(float v, __nv_bfloat16& hi, __nv_bfloat16& lo) {
    hi = __float2bfloat16_rn(v);
    lo = __float2bfloat16_rn(v - __bfloat162float(hi));
}
__device__ __forceinline__ uint32_t hpack(__half a, __half b) {
    __half2 t = __halves2half2(a, b);
    return *reinterpret_cast<uint32_t*>(&t);
}
__device__ __forceinline__ uint32_t bpack(__nv_bfloat16 a, __nv_bfloat16 b) {
    __nv_bfloat162 t = __halves2bfloat162(a, b);
    return *reinterpret_cast<uint32_t*>(&t);
}
__device__ __forceinline__ void ldmx4(uint32_t* r, uint32_t addr) {
    asm volatile("ldmatrix.sync.aligned.m8n8.x4.shared.b16 {%0,%1,%2,%3}, [%4];"
                 : "=r"(r[0]), "=r"(r[1]), "=r"(r[2]), "=r"(r[3]) : "r"(addr));
}
__device__ __forceinline__ void ldmx2(uint32_t* r, uint32_t addr) {
    asm volatile("ldmatrix.sync.aligned.m8n8.x2.shared.b16 {%0,%1}, [%2];"
                 : "=r"(r[0]), "=r"(r[1]) : "r"(addr));
}
__device__ __forceinline__ void ldmx2t(uint32_t* r, uint32_t addr) {
    asm volatile("ldmatrix.sync.aligned.m8n8.x2.trans.shared.b16 {%0,%1}, [%2];"
                 : "=r"(r[0]), "=r"(r[1]) : "r"(addr));
}
__device__ __forceinline__ void mma16816h(float* d, const uint32_t* a, const uint32_t* b) {
    asm volatile("mma.sync.aligned.m16n8k16.row.col.f32.f16.f16.f32 {%0,%1,%2,%3},{%4,%5,%6,%7},{%8,%9},{%0,%1,%2,%3};"
                 : "+f"(d[0]), "+f"(d[1]), "+f"(d[2]), "+f"(d[3])
                 : "r"(a[0]), "r"(a[1]), "r"(a[2]), "r"(a[3]), "r"(b[0]), "r"(b[1]));
}
__device__ __forceinline__ void mma16816(float* d, const uint32_t* a, const uint32_t* b) {
    asm volatile("mma.sync.aligned.m16n8k16.row.col.f32.bf16.bf16.f32 {%0,%1,%2,%3},{%4,%5,%6,%7},{%8,%9},{%0,%1,%2,%3};"
                 : "+f"(d[0]), "+f"(d[1]), "+f"(d[2]), "+f"(d[3])
                 : "r"(a[0]), "r"(a[1]), "r"(a[2]), "r"(a[3]), "r"(b[0]), "r"(b[1]));
}
__device__ __forceinline__ void cp16(uint32_t saddr, const void* gptr) {
    asm volatile("cp.async.cg.shared.global [%0], [%1], 16;" :: "r"(saddr), "l"(gptr));
}
__device__ __forceinline__ void cp_commit() { asm volatile("cp.async.commit_group;"); }
__device__ __forceinline__ void cp_wait1() { asm volatile("cp.async.wait_group 1;"); }

// ---------------- LayerNorm -> xn2, and x -> x2 (fused, fp16 splits) ----------------
__global__ void ln_kernel(const float* __restrict__ x,
                          const float* __restrict__ gamma,
                          __half* __restrict__ xn2,
                          __half* __restrict__ x2) {
    int row = blockIdx.x;
    const float* xr = x + (size_t)row * DIM_;
    float v[4];
    float s = 0.f, sq = 0.f;
#pragma unroll
    for (int i = 0; i < 4; i++) {
        float t = xr[threadIdx.x + i * 256];
        v[i] = t; s += t; sq += t * t;
    }
#pragma unroll
    for (int off = 16; off > 0; off >>= 1) {
        s  += __shfl_xor_sync(0xffffffffu, s,  off);
        sq += __shfl_xor_sync(0xffffffffu, sq, off);
    }
    __shared__ float sa[8], sb[8];
    int w = threadIdx.x >> 5, l = threadIdx.x & 31;
    if (l == 0) { sa[w] = s; sb[w] = sq; }
    __syncthreads();
    if (threadIdx.x == 0) {
        float a = 0.f, bq = 0.f;
#pragma unroll
        for (int i = 0; i < 8; i++) { a += sa[i]; bq += sb[i]; }
        sa[0] = a; sb[0] = bq;
    }
    __syncthreads();
    float mean = sa[0] * (1.0f / DIM_);
    float var  = sb[0] * (1.0f / DIM_) - mean * mean;
    float rstd = rsqrtf(var + 1e-5f);
    __half* outr = xn2 + (size_t)row * KP2;
    __half* xo   = x2  + (size_t)row * KP2;
#pragma unroll
    for (int i = 0; i < 4; i++) {
        int d = threadIdx.x + i * 256;
        float o = (v[i] - mean) * rstd * gamma[d];
        __half hi, lo; split_f16(o, hi, lo);
        outr[d] = hi; outr[DIM_ + d] = lo;
        split_f16(v[i], hi, lo);
        xo[d] = hi; xo[DIM_ + d] = lo;
    }
}

// ---------------- W [K=1024][N] -> W2T [N][2048] = [Whi|Whi] ----------------
__global__ void wconv_kernel(const float* __restrict__ W, __half* __restrict__ W2T, int N) {
    __shared__ float t[32][33];
    int k0 = blockIdx.y * 32, n0 = blockIdx.x * 32;
    int tx = threadIdx.x, ty = threadIdx.y;   // 32 x 8
#pragma unroll
    for (int i = 0; i < 4; i++)
        t[ty + i * 8][tx] = W[(size_t)(k0 + ty + i * 8) * N + n0 + tx];
    __syncthreads();
#pragma unroll
    for (int i = 0; i < 4; i++) {
        int n = n0 + ty + i * 8;
        int k = k0 + tx;
        __half hi = __float2half_rn(t[tx][ty + i * 8]);
        __half* o = W2T + (size_t)n * KP2;
        o[k] = hi; o[DIM_ + k] = hi;
    }
}

// ---------------- fp16 HMMA GEMM, 3-stage cp.async, 2 CTAs/SM ----------------
// nkt=32 -> 1-term (hi only), nkt=64 -> 2-term.
#define STAGES 3
#define BK 32
#define STRIDE 40
#define STG_ELEM (128 * STRIDE)

__global__ void __launch_bounds__(256, 2) hgemm_kernel(
        const __half* __restrict__ A,   // [M][KP2]
        const __half* __restrict__ BT,  // [N][KP2]
        float* __restrict__ C, int M, int N, int nkt) {
    __shared__ __half As[STAGES * STG_ELEM];
    __shared__ __half Bs[STAGES * STG_ELEM];

    const int tid  = threadIdx.x;
    const int wid  = tid >> 5, lane = tid & 31;
    const int wm   = wid & 1, wn = wid >> 1;
    const int g    = lane >> 2, tig = lane & 3;

    const int row0 = blockIdx.y * 128;
    const int col0 = blockIdx.x * 128;

    const int lrow = tid >> 1;
    const int lcol = (tid & 1) << 4;
    const __half* Ag = A  + (size_t)(row0 + lrow) * KP2 + lcol;
    const __half* Bg = BT + (size_t)(col0 + lrow) * KP2 + lcol;

    const uint32_t a_base = (uint32_t)__cvta_generic_to_shared(As);
    const uint32_t b_base = (uint32_t)__cvta_generic_to_shared(Bs);
    const uint32_t a_dst = a_base + (uint32_t)((lrow * STRIDE + lcol) * 2);
    const uint32_t b_dst = b_base + (uint32_t)((lrow * STRIDE + lcol) * 2);

    float acc[4][4][4];
#pragma unroll
    for (int mi = 0; mi < 4; mi++)
#pragma unroll
        for (int ni = 0; ni < 4; ni++)
#pragma unroll
            for (int e = 0; e < 4; e++) acc[mi][ni][e] = 0.f;

    const int a_row_in = lane & 15;
    const int a_k_in   = (lane >> 4) << 3;
    // paired-B x4 lane mapping: row-of-pair + k-half
    const int bp_row   = ((lane >> 4) << 3) + (lane & 7);   // 0..15 within 16-row pair
    const int bp_k     = ((lane >> 3) & 1) << 3;            // 0 or 8

    // prologue: issue stages 0..1
#pragma unroll
    for (int s = 0; s < STAGES - 1; s++) {
        uint32_t so = (uint32_t)(s * STG_ELEM * 2);
        cp16(a_dst + so,      Ag + s * BK);
        cp16(a_dst + so + 16, Ag + s * BK + 8);
        cp16(b_dst + so,      Bg + s * BK);
        cp16(b_dst + so + 16, Bg + s * BK + 8);
        cp_commit();
    }

    for (int t = 0; t < nkt; t++) {
        cp_wait1();
        __syncthreads();

        if (t + STAGES - 1 < nkt) {
            uint32_t so = (uint32_t)(((t + STAGES - 1) % STAGES) * STG_ELEM * 2);
            const __half* ap = Ag + (t + STAGES - 1) * BK;
            const __half* bp = Bg + (t + STAGES - 1) * BK;
            cp16(a_dst + so,      ap);
            cp16(a_dst + so + 16, ap + 8);
            cp16(b_dst + so,      bp);
            cp16(b_dst + so + 16, bp + 8);
        }
        cp_commit();

        const uint32_t abuf = a_base + (uint32_t)((t % STAGES) * STG_ELEM * 2);
        const uint32_t bbuf = b_base + (uint32_t)((t % STAGES) * STG_ELEM * 2);
#pragma unroll
        for (int kk = 0; kk < BK; kk += 16) {
            uint32_t afr[4][4];
            uint32_t bfr[2][4];   // [nip][4 regs] = frags for ni=2nip ({0,1}) and 2nip+1 ({2,3})
#pragma unroll
            for (int mi = 0; mi < 4; mi++) {
                uint32_t a_addr = abuf +
                    (uint32_t)(((wm * 64 + mi * 16 + a_row_in) * STRIDE + kk + a_k_in) << 1);
                ldmx4(afr[mi], a_addr);
            }
#pragma unroll
            for (int nip = 0; nip < 2; nip++) {
                uint32_t b_addr = bbuf +
                    (uint32_t)(((wn * 32 + nip * 16 + bp_row) * STRIDE + kk + bp_k) << 1);
                ldmx4(bfr[nip], b_addr);
            }
#pragma unroll
            for (int mi = 0; mi < 4; mi++)
#pragma unroll
                for (int nip = 0; nip < 2; nip++) {
                    mma16816h(acc[mi][2 * nip],     afr[mi], &bfr[nip][0]);
                    mma16816h(acc[mi][2 * nip + 1], afr[mi], &bfr[nip][2]);
                }
        }
    }

#pragma unroll
    for (int mi = 0; mi < 4; mi++) {
        int r0 = row0 + wm * 64 + mi * 16 + g;
#pragma unroll
        for (int ni = 0; ni < 4; ni++) {
            int cc = col0 + wn * 32 + ni * 8 + tig * 2;
            float2 v0 = { acc[mi][ni][0], acc[mi][ni][1] };
            float2 v1 = { acc[mi][ni][2], acc[mi][ni][3] };
            *(float2*)&C[(size_t)r0 * N + cc]       = v0;
            *(float2*)&C[(size_t)(r0 + 8) * N + cc] = v1;
        }
    }
}

// ---------------- prep: emit bf16 hi/lo pairs Q3/K3/V3 ----------------
__global__ void prep_kernel(const float* __restrict__ q,
                            const float* __restrict__ kv,
                            const float* __restrict__ null_kv,
                            const float* __restrict__ q_scale,
                            const float* __restrict__ k_scale,
                            __nv_bfloat16* __restrict__ Q3,
                            __nv_bfloat16* __restrict__ K3,
                            __nv_bfloat16* __restrict__ V3) {
    int warp = (blockIdx.x * blockDim.x + threadIdx.x) >> 5;
    int lane = threadIdx.x & 31;
    if (warp >= B_ * H_ * J_) return;
    int bh = warp / J_;
    int j  = warp % J_;
    int b = bh / H_, h = bh % H_;
    int d0 = lane, d1 = lane + 32;

    float k0, k1, v0, v1;
    if (j < NNK_) {
        const float* nb = null_kv + ((size_t)(h * NNK_ + j) * 2) * DH_;
        k0 = nb[d0];        k1 = nb[d1];
        v0 = nb[DH_ + d0];  v1 = nb[DH_ + d1];
    } else {
        int n = j - NNK_;
        const float* base = kv + ((size_t)(b * N_ + n)) * (2 * DIM_) + h * DH_;
        k0 = base[d0];          k1 = base[d1];
        v0 = base[DIM_ + d0];   v1 = base[DIM_ + d1];
    }
    float ss = k0 * k0 + k1 * k1;
#pragma unroll
    for (int off = 16; off > 0; off >>= 1)
        ss += __shfl_xor_sync(0xffffffffu, ss, off);
    float inv = 1.0f / fmaxf(sqrtf(ss), 1e-12f);
    float ks0 = k0 * inv * k_scale[d0];
    float ks1 = k1 * inv * k_scale[d1];

    __nv_bfloat16 h0, l0, h1, l1;
    size_t ko = ((size_t)bh * J_PAD + j) * 128;
    split_bf16(ks0, h0, l0); split_bf16(ks1, h1, l1);
    K3[ko + d0] = h0; K3[ko + 64 + d0] = l0;
    K3[ko + d1] = h1; K3[ko + 64 + d1] = l1;

    split_bf16(v0, h0, l0); split_bf16(v1, h1, l1);
    V3[ko + d0] = h0; V3[ko + 64 + d0] = l0;
    V3[ko + d1] = h1; V3[ko + 64 + d1] = l1;

    if (j < N_) {
        int n = j;
        const float* qb = q + ((size_t)(b * N_ + n)) * DIM_ + h * DH_;
        float a0 = qb[d0], a1 = qb[d1];
        float qs2 = a0 * a0 + a1 * a1;
#pragma unroll
        for (int off = 16; off > 0; off >>= 1)
            qs2 += __shfl_xor_sync(0xffffffffu, qs2, off);
        float qinv = 1.0f / fmaxf(sqrtf(qs2), 1e-12f);
        float q0 = a0 * qinv * q_scale[d0];
        float q1 = a1 * qinv * q_scale[d1];
        size_t qo = ((size_t)bh * N_ + n) * 128;
        split_bf16(q0, h0, l0); split_bf16(q1, h1, l1);
        Q3[qo + d0] = h0; Q3[qo + 64 + d0] = l0;
        Q3[qo + d1] = h1; Q3[qo + 64 + d1] = l1;
    }
}

// ---------------- bf16 HMMA flash attention (3-term via frag reuse, 2 CTAs/SM) ----------------
#define QS_OFF   0
#define KS_OFF   34816
#define KS_SZ    17408
#define VS_OFF   69632
#define VS_SZ    17408
#define MM_OFF   104448
#define SMEM_ATT 104960

__device__ __forceinline__ float softel(float s, int ig, int jg, int h,
                                        const float* __restrict__ bias) {
    bool ok = (jg <= ig + NNK_) && (jg < J_);
    float bv = 0.f;
    if (ok && jg >= NNK_) bv = __ldg(bias + ((size_t)h * N_ + ig) * N_ + (jg - NNK_));
    float t = fmaf(s, 11.541560327111707f, fmaf(bv, 1.4426950408889634f, -23.083120654223414f));
    float r;
    asm("ex2.approx.f32 %0, %1;" : "=f"(r) : "f"(t));
    return ok ? r : 0.f;
}

__device__ __forceinline__ void load_tile(int stage, int j0, int bh, int b, int tid,
        uint32_t sbase, char* smx,
        const __nv_bfloat16* __restrict__ K3, const __nv_bfloat16* __restrict__ V3,
        const int* __restrict__ mask) {
    uint32_t ks = sbase + KS_OFF + stage * KS_SZ;
    uint32_t vs = sbase + VS_OFF + stage * VS_SZ;
#pragma unroll
    for (int i = 0; i < 4; i++) {
        int idx = i * 256 + tid;
        int row = idx >> 4, c = idx & 15;
        uint32_t doff = (uint32_t)((row * 136 + c * 8) * 2);
        size_t soff = ((size_t)bh * J_PAD + j0 + row) * 128 + c * 8;
        cp16(ks + doff, K3 + soff);
        cp16(vs + doff, V3 + soff);
    }
    if (tid < 64) {
        int jg = j0 + tid;
        float mm = 1.f;
        if (jg >= NNK_) mm = (jg < J_ && mask[b * N_ + jg - NNK_] != 0) ? 1.f : 0.f;
        ((float*)(smx + MM_OFF))[stage * 64 + tid] = mm;
    }
}

__global__ void __launch_bounds__(256, 2) attn_mma_kernel(
        const __nv_bfloat16* __restrict__ Q3, const __nv_bfloat16* __restrict__ K3,
        const __nv_bfloat16* __restrict__ V3, const float* __restrict__ bias,
        const int* __restrict__ mask, __half* __restrict__ att2) {
    extern __shared__ char smx[];
    const uint32_t sbase = (uint32_t)__cvta_generic_to_shared(smx);

    const int tid = threadIdx.x;
    const int w = tid >> 5, lane = tid & 31;
    const int g = lane >> 2, tig = lane & 3;
    const int ib = (int)gridDim.x - 1 - (int)blockIdx.x;   // heavy CTAs first
    const int i0 = ib * 128;
    const int bh = blockIdx.y, b = bh >> 4, h = bh & 15;
    const int iw = i0 + w * 16;
    const int ig0 = iw + g, ig1 = ig0 + 8;

    const int jtmax = min((i0 + 129) >> 6, J_PAD / 64 - 1);

    // Q tile: 128 rows x 128 bf16 [Qhi|Qlo]
#pragma unroll
    for (int i = 0; i < 8; i++) {
        int idx = i * 256 + tid;
        int row = idx >> 4, c = idx & 15;
        cp16(sbase + QS_OFF + (uint32_t)((row * 136 + c * 8) * 2),
             Q3 + ((size_t)bh * N_ + i0 + row) * 128 + c * 8);
    }
    load_tile(0, 0, bh, b, tid, sbase, smx, K3, V3, mask);
    cp_commit();

    float oacc[8][4];
#pragma unroll
    for (int d = 0; d < 8; d++)
#pragma unroll
        for (int e = 0; e < 4; e++) oacc[d][e] = 0.f;
    float lsum0 = 0.f, lsum1 = 0.f;

    int buf = 0;
    for (int jt = 0; jt <= jtmax; jt++) {
        const int j0 = jt * 64;
        if (jt < jtmax)
            load_tile(buf ^ 1, j0 + 64, bh, b, tid, sbase, smx, K3, V3, mask);
        cp_commit();
        cp_wait1();
        __syncthreads();

        const bool active = (j0 <= iw + 15 + NNK_);
        if (active) {
            const uint32_t ks = sbase + KS_OFF + buf * KS_SZ;
            const uint32_t vs = sbase + VS_OFF + buf * VS_SZ;
            const float* mm = (const float*)(smx + MM_OFF) + buf * 64;

            float sacc[8][4];
#pragma unroll
            for (int jf = 0; jf < 8; jf++)
#pragma unroll
                for (int e = 0; e < 4; e++) sacc[jf][e] = 0.f;

            const int a_row = w * 16 + (lane & 15);
            const int a_kin = (lane >> 4) << 3;
            const int bp_row = ((lane >> 4) << 3) + (lane & 7);   // 0..15 within jf-pair
            const int bp_k   = ((lane >> 3) & 1) << 3;
            // S = Qhi*Khi + Qlo*Khi + Qhi*Klo (frag reuse, paired-jf x4 K loads)
#pragma unroll
            for (int kc = 0; kc < 4; kc++) {
                uint32_t ah[4], al[4];
                ldmx4(ah, sbase + QS_OFF + (uint32_t)((a_row * 136 + kc * 16 + a_kin) << 1));
                ldmx4(al, sbase + QS_OFF + (uint32_t)((a_row * 136 + 64 + kc * 16 + a_kin) << 1));
#pragma unroll
                for (int jfp = 0; jfp < 4; jfp++) {
                    uint32_t khp[4], klp[4];
                    uint32_t ka = ks + (uint32_t)(((jfp * 16 + bp_row) * 136 + kc * 16 + bp_k) << 1);
                    ldmx4(khp, ka);
                    ldmx4(klp, ka + 128);
                    mma16816(sacc[2 * jfp],     ah, &khp[0]);
                    mma16816(sacc[2 * jfp],     al, &khp[0]);
                    mma16816(sacc[2 * jfp],     ah, &klp[0]);
                    mma16816(sacc[2 * jfp + 1], ah, &khp[2]);
                    mma16816(sacc[2 * jfp + 1], al, &khp[2]);
                    mma16816(sacc[2 * jfp + 1], ah, &klp[2]);
                }
            }

            uint32_t phi2[8][2], plo2[8][2];
#pragma unroll
            for (int jf = 0; jf < 8; jf++) {
                int jc = j0 + jf * 8 + tig * 2;
                float m0 = mm[jf * 8 + tig * 2];
                float m1 = mm[jf * 8 + tig * 2 + 1];
                float p0 = softel(sacc[jf][0], ig0, jc,     h, bias) * m0;
                float p1 = softel(sacc[jf][1], ig0, jc + 1, h, bias) * m1;
                float p2 = softel(sacc[jf][2], ig1, jc,     h, bias) * m0;
                float p3 = softel(sacc[jf][3], ig1, jc + 1, h, bias) * m1;
                lsum0 += p0 + p1;
                lsum1 += p2 + p3;
                __nv_bfloat16 h0, l0, h1, l1, h2, l2, h3, l3;
                split_bf16(p0, h0, l0); split_bf16(p1, h1, l1);
                split_bf16(p2, h2, l2); split_bf16(p3, h3, l3);
                phi2[jf][0] = bpack(h0, h1); phi2[jf][1] = bpack(h2, h3);
                plo2[jf][0] = bpack(l0, l1); plo2[jf][1] = bpack(l2, l3);
            }

            // O += Phi*Vhi + Plo*Vhi + Phi*Vlo (frag reuse)
#pragma unroll
            for (int kc2 = 0; kc2 < 4; kc2++) {
                uint32_t ah[4] = { phi2[2 * kc2][0], phi2[2 * kc2][1],
                                   phi2[2 * kc2 + 1][0], phi2[2 * kc2 + 1][1] };
                uint32_t al[4] = { plo2[2 * kc2][0], plo2[2 * kc2][1],
                                   plo2[2 * kc2 + 1][0], plo2[2 * kc2 + 1][1] };
#pragma unroll
                for (int df = 0; df < 8; df++) {
                    uint32_t vh[2], vl[2];
                    uint32_t va = vs + (uint32_t)((((kc2 * 16 + (lane & 15)) * 136) + df * 8) << 1);
                    ldmx2t(vh, va);
                    ldmx2t(vl, va + 128);
                    mma16816(oacc[df], ah, vh);
                    mma16816(oacc[df], al, vh);
                    mma16816(oacc[df], ah, vl);
                }
            }
        }
        __syncthreads();
        buf ^= 1;
    }

    lsum0 += __shfl_xor_sync(0xffffffffu, lsum0, 1);
    lsum0 += __shfl_xor_sync(0xffffffffu, lsum0, 2);
    lsum1 += __shfl_xor_sync(0xffffffffu, lsum1, 1);
    lsum1 += __shfl_xor_sync(0xffffffffu, lsum1, 2);
    float inv0 = 1.0f / lsum0;
    float inv1 = 1.0f / lsum1;

    // epilogue: fp16 [hi|lo] rows for the fp16 output GEMM
#pragma unroll
    for (int df = 0; df < 8; df++) {
        float o0 = oacc[df][0] * inv0, o1 = oacc[df][1] * inv0;
        float o2 = oacc[df][2] * inv1, o3 = oacc[df][3] * inv1;
        __half h0, l0, h1, l1, h2, l2, h3, l3;
        split_f16(o0, h0, l0); split_f16(o1, h1, l1);
        split_f16(o2, h2, l2); split_f16(o3, h3, l3);
        {
            __half* p = att2 + ((size_t)(b * N_ + ig0)) * KP2 + h * DH_ + df * 8 + tig * 2;
            *(uint32_t*)(p)        = hpack(h0, h1);
            *(uint32_t*)(p + DIM_) = hpack(l0, l1);
        }
        {
            __half* p = att2 + ((size_t)(b * N_ + ig1)) * KP2 + h * DH_ + df * 8 + tig * 2;
            *(uint32_t*)(p)        = hpack(h2, h3);
            *(uint32_t*)(p + DIM_) = hpack(l2, l3);
        }
    }
}

// ---------------- launch ----------------
extern "C" void kernel_launch(void* const* d_in, const int* in_sizes, int n_in,
                              void* d_out, int out_size) {
    const float* x     = (const float*)d_in[0];
    const int*   mask  = (const int*)d_in[1];
    const float* bias  = (const float*)d_in[2];
    const float* gamma = (const float*)d_in[3];
    const float* nkv   = (const float*)d_in[4];
    const float* Wq    = (const float*)d_in[5];
    const float* Wkv   = (const float*)d_in[6];
    const float* qsc   = (const float*)d_in[7];
    const float* ksc   = (const float*)d_in[8];
    const float* Wo    = (const float*)d_in[9];
    float* out = (float*)d_out;

    __half *p_x2, *p_xn2, *p_att2, *p_Wq2T, *p_Wkv2T, *p_Wo2T;
    __nv_bfloat16 *p_Q3, *p_K3, *p_V3;
    float *p_q, *p_kv;
    cudaGetSymbolAddress((void**)&p_x2,    g_x2);
    cudaGetSymbolAddress((void**)&p_xn2,   g_xn2);
    cudaGetSymbolAddress((void**)&p_att2,  g_att2);
    cudaGetSymbolAddress((void**)&p_Wq2T,  g_Wq2T);
    cudaGetSymbolAddress((void**)&p_Wkv2T, g_Wkv2T);
    cudaGetSymbolAddress((void**)&p_Wo2T,  g_Wo2T);
    cudaGetSymbolAddress((void**)&p_q,     g_q);
    cudaGetSymbolAddress((void**)&p_kv,    g_kv);
    cudaGetSymbolAddress((void**)&p_Q3,    g_Q3);
    cudaGetSymbolAddress((void**)&p_K3,    g_K3);
    cudaGetSymbolAddress((void**)&p_V3,    g_V3);

    dim3 wb(32, 8);
    ln_kernel<<<MTOT, 256>>>(x, gamma, p_xn2, p_x2);                                  // 1
    wconv_kernel<<<dim3(DIM_ / 32,     DIM_ / 32), wb>>>(Wq,  p_Wq2T,  DIM_);         // 2
    wconv_kernel<<<dim3(2 * DIM_ / 32, DIM_ / 32), wb>>>(Wkv, p_Wkv2T, 2 * DIM_);     // 3

    dim3 gq(DIM_ / 128, MTOT / 128);
    // Q and KV projections: 1-term fp16 (hi halves only)
    hgemm_kernel<<<gq, 256>>>(p_xn2, p_Wq2T, p_q, MTOT, DIM_, DIM_ / BK);             // 4 (profiled)
    dim3 gkv(2 * DIM_ / 128, MTOT / 128);
    hgemm_kernel<<<gkv, 256>>>(p_x2, p_Wkv2T, p_kv, MTOT, 2 * DIM_, DIM_ / BK);       // 5

    wconv_kernel<<<dim3(DIM_ / 32,     DIM_ / 32), wb>>>(Wo,  p_Wo2T,  DIM_);         // 6

    int nwarp = B_ * H_ * J_;
    prep_kernel<<<(nwarp + 7) / 8, 256>>>(p_q, p_kv, nkv, qsc, ksc, p_Q3, p_K3, p_V3);// 7

    cudaFuncSetAttribute(attn_mma_kernel, cudaFuncAttributeMaxDynamicSharedMemorySize, SMEM_ATT);
    dim3 ga(N_ / 128, B_ * H_);
    attn_mma_kernel<<<ga, 256, SMEM_ATT>>>(p_Q3, p_K3, p_V3, bias, mask, p_att2);     // 8

    // output projection: 1-term fp16
    hgemm_kernel<<<gq, 256>>>(p_att2, p_Wo2T, out, MTOT, DIM_, DIM_ / BK);            // 9
}

// round 15
// speedup vs baseline: 2.9578x; 1.1076x over previous
#include <cuda_runtime.h>
#include <cuda_fp16.h>
#include <cuda_bf16.h>
#include <math.h>
#include <stdint.h>

// ---------------- problem constants ----------------
#define B_    2
#define N_    2048
#define DIM_  1024
#define H_    16
#define DH_   64
#define NNK_  2
#define J_    (N_ + NNK_)    // 2050
#define J_PAD 2112           // 33 tiles of 64
#define KP2   2048           // fp16 2-term split K' (row stride)
#define MTOT  (B_ * N_)      // 4096

// ---------------- scratch (device globals; no allocs allowed) ----------------
__device__ __align__(16) __half g_x2   [MTOT * KP2];      // [xhi|xlo]
__device__ __align__(16) __half g_xn2  [MTOT * KP2];      // layernorm(x) split
__device__ __align__(16) __half g_att2 [MTOT * KP2];      // attention out split
__device__ __align__(16) __half g_Wq2T [DIM_ * KP2];      // [N][Whi|Whi]
__device__ __align__(16) __half g_Wkv2T[2 * DIM_ * KP2];
__device__ __align__(16) __half g_Wo2T [DIM_ * KP2];
__device__ float g_q  [MTOT * DIM_];
__device__ float g_kv [MTOT * 2 * DIM_];
// attention operands (padding rows stay zero-initialized)
__device__ __align__(16) __half        g_Q2 [B_ * H_ * N_ * 128];     // fp16 [Qhi|Qlo]
__device__ __align__(16) __half        g_K2 [B_ * H_ * J_PAD * 64];   // fp16 Khi
__device__ __align__(16) __nv_bfloat16 g_V3 [B_ * H_ * J_PAD * 128];  // bf16 [Vhi|Vlo]

// ---------------- helpers ----------------
__device__ __forceinline__ void split_f16(float v, __half& hi, __half& lo) {
    hi = __float2half_rn(v);
    lo = __float2half_rn(v - __half2float(hi));
}
__device__ __forceinline__ void split_bf16(float v, __nv_bfloat16& hi, __nv_bfloat16& lo) {
    hi = __float2bfloat16_rn(v);
    lo = __float2bfloat16_rn(v - __bfloat162float(hi));
}
__device__ __forceinline__ uint32_t hpack(__half a, __half b) {
    __half2 t = __halves2half2(a, b);
    return *reinterpret_cast<uint32_t*>(&t);
}
__device__ __forceinline__ uint32_t bpack(__nv_bfloat16 a, __nv_bfloat16 b) {
    __nv_bfloat162 t = __halves2bfloat162(a, b);
    return *reinterpret_cast<uint32_t*>(&t);
}
__device__ __forceinline__ void ldmx4(uint32_t* r, uint32_t addr) {
    asm volatile("ldmatrix.sync.aligned.m8n8.x4.shared.b16 {%0,%1,%2,%3}, [%4];"
                 : "=r"(r[0]), "=r"(r[1]), "=r"(r[2]), "=r"(r[3]) : "r"(addr));
}
__device__ __forceinline__ void ldmx2t(uint32_t* r, uint32_t addr) {
    asm volatile("ldmatrix.sync.aligned.m8n8.x2.trans.shared.b16 {%0,%1}, [%2];"
                 : "=r"(r[0]), "=r"(r[1]) : "r"(addr));
}
__device__ __forceinline__ void mma16816h(float* d, const uint32_t* a, const uint32_t* b) {
    asm volatile("mma.sync.aligned.m16n8k16.row.col.f32.f16.f16.f32 {%0,%1,%2,%3},{%4,%5,%6,%7},{%8,%9},{%0,%1,%2,%3};"
                 : "+f"(d[0]), "+f"(d[1]), "+f"(d[2]), "+f"(d[3])
                 : "r"(a[0]), "r"(a[1]), "r"(a[2]), "r"(a[3]), "r"(b[0]), "r"(b[1]));
}
__device__ __forceinline__ void mma16816(float* d, const uint32_t* a, const uint32_t* b) {
    asm volatile("mma.sync.aligned.m16n8k16.row.col.f32.bf16.bf16.f32 {%0,%1,%2,%3},{%4,%5,%6,%7},{%8,%9},{%0,%1,%2,%3};"
                 : "+f"(d[0]), "+f"(d[1]), "+f"(d[2]), "+f"(d[3])
                 : "r"(a[0]), "r"(a[1]), "r"(a[2]), "r"(a[3]), "r"(b[0]), "r"(b[1]));
}
__device__ __forceinline__ void cp16(uint32_t saddr, const void* gptr) {
    asm volatile("cp.async.cg.shared.global [%0], [%1], 16;" :: "r"(saddr), "l"(gptr));
}
__device__ __forceinline__ void cp_commit() { asm volatile("cp.async.commit_group;"); }
__device__ __forceinline__ void cp_wait1() { asm volatile("cp.async.wait_group 1;"); }

// ---------------- LayerNorm -> xn2, and x -> x2 (fused, fp16 splits) ----------------
__global__ void ln_kernel(const float* __restrict__ x,
                          const float* __restrict__ gamma,
                          __half* __restrict__ xn2,
                          __half* __restrict__ x2) {
    int row = blockIdx.x;
    const float* xr = x + (size_t)row * DIM_;
    float v[4];
    float s = 0.f, sq = 0.f;
#pragma unroll
    for (int i = 0; i < 4; i++) {
        float t = xr[threadIdx.x + i * 256];
        v[i] = t; s += t; sq += t * t;
    }
#pragma unroll
    for (int off = 16; off > 0; off >>= 1) {
        s  += __shfl_xor_sync(0xffffffffu, s,  off);
        sq += __shfl_xor_sync(0xffffffffu, sq, off);
    }
    __shared__ float sa[8], sb[8];
    int w = threadIdx.x >> 5, l = threadIdx.x & 31;
    if (l == 0) { sa[w] = s; sb[w] = sq; }
    __syncthreads();
    if (threadIdx.x == 0) {
        float a = 0.f, bq = 0.f;
#pragma unroll
        for (int i = 0; i < 8; i++) { a += sa[i]; bq += sb[i]; }
        sa[0] = a; sb[0] = bq;
    }
    __syncthreads();
    float mean = sa[0] * (1.0f / DIM_);
    float var  = sb[0] * (1.0f / DIM_) - mean * mean;
    float rstd = rsqrtf(var + 1e-5f);
    __half* outr = xn2 + (size_t)row * KP2;
    __half* xo   = x2  + (size_t)row * KP2;
#pragma unroll
    for (int i = 0; i < 4; i++) {
        int d = threadIdx.x + i * 256;
        float o = (v[i] - mean) * rstd * gamma[d];
        __half hi, lo; split_f16(o, hi, lo);
        outr[d] = hi; outr[DIM_ + d] = lo;
        split_f16(v[i], hi, lo);
        xo[d] = hi; xo[DIM_ + d] = lo;
    }
}

// ---------------- merged weight conversion: z=0 Wq, z=1 Wkv, z=2 Wo ----------------
__global__ void wconv_all_kernel(const float* __restrict__ Wq, __half* __restrict__ Wq2T,
                                 const float* __restrict__ Wkv, __half* __restrict__ Wkv2T,
                                 const float* __restrict__ Wo, __half* __restrict__ Wo2T) {
    const float* W; __half* W2T; int N;
    if (blockIdx.z == 0)      { W = Wq;  W2T = Wq2T;  N = DIM_; }
    else if (blockIdx.z == 1) { W = Wkv; W2T = Wkv2T; N = 2 * DIM_; }
    else                      { W = Wo;  W2T = Wo2T;  N = DIM_; }
    int n0 = blockIdx.x * 32;
    if (n0 >= N) return;
    __shared__ float t[32][33];
    int k0 = blockIdx.y * 32;
    int tx = threadIdx.x, ty = threadIdx.y;   // 32 x 8
#pragma unroll
    for (int i = 0; i < 4; i++)
        t[ty + i * 8][tx] = W[(size_t)(k0 + ty + i * 8) * N + n0 + tx];
    __syncthreads();
#pragma unroll
    for (int i = 0; i < 4; i++) {
        int n = n0 + ty + i * 8;
        int k = k0 + tx;
        __half hi = __float2half_rn(t[tx][ty + i * 8]);
        __half* o = W2T + (size_t)n * KP2;
        o[k] = hi; o[DIM_ + k] = hi;
    }
}

// ---------------- fp16 HMMA GEMM, 3-stage cp.async, 2 CTAs/SM ----------------
#define STAGES 3
#define BK 32
#define STRIDE 40
#define STG_ELEM (128 * STRIDE)

__global__ void __launch_bounds__(256, 2) hgemm_kernel(
        const __half* __restrict__ A,   // [M][KP2]
        const __half* __restrict__ BT,  // [N][KP2]
        float* __restrict__ C, int M, int N, int nkt) {
    __shared__ __half As[STAGES * STG_ELEM];
    __shared__ __half Bs[STAGES * STG_ELEM];

    const int tid  = threadIdx.x;
    const int wid  = tid >> 5, lane = tid & 31;
    const int wm   = wid & 1, wn = wid >> 1;
    const int g    = lane >> 2, tig = lane & 3;

    const int row0 = blockIdx.y * 128;
    const int col0 = blockIdx.x * 128;

    const int lrow = tid >> 1;
    const int lcol = (tid & 1) << 4;
    const __half* Ag = A  + (size_t)(row0 + lrow) * KP2 + lcol;
    const __half* Bg = BT + (size_t)(col0 + lrow) * KP2 + lcol;

    const uint32_t a_base = (uint32_t)__cvta_generic_to_shared(As);
    const uint32_t b_base = (uint32_t)__cvta_generic_to_shared(Bs);
    const uint32_t a_dst = a_base + (uint32_t)((lrow * STRIDE + lcol) * 2);
    const uint32_t b_dst = b_base + (uint32_t)((lrow * STRIDE + lcol) * 2);

    float acc[4][4][4];
#pragma unroll
    for (int mi = 0; mi < 4; mi++)
#pragma unroll
        for (int ni = 0; ni < 4; ni++)
#pragma unroll
            for (int e = 0; e < 4; e++) acc[mi][ni][e] = 0.f;

    const int a_row_in = lane & 15;
    const int a_k_in   = (lane >> 4) << 3;
    const int bp_row   = ((lane >> 4) << 3) + (lane & 7);
    const int bp_k     = ((lane >> 3) & 1) << 3;

#pragma unroll
    for (int s = 0; s < STAGES - 1; s++) {
        uint32_t so = (uint32_t)(s * STG_ELEM * 2);
        cp16(a_dst + so,      Ag + s * BK);
        cp16(a_dst + so + 16, Ag + s * BK + 8);
        cp16(b_dst + so,      Bg + s * BK);
        cp16(b_dst + so + 16, Bg + s * BK + 8);
        cp_commit();
    }

    for (int t = 0; t < nkt; t++) {
        cp_wait1();
        __syncthreads();

        if (t + STAGES - 1 < nkt) {
            uint32_t so = (uint32_t)(((t + STAGES - 1) % STAGES) * STG_ELEM * 2);
            const __half* ap = Ag + (t + STAGES - 1) * BK;
            const __half* bp = Bg + (t + STAGES - 1) * BK;
            cp16(a_dst + so,      ap);
            cp16(a_dst + so + 16, ap + 8);
            cp16(b_dst + so,      bp);
            cp16(b_dst + so + 16, bp + 8);
        }
        cp_commit();

        const uint32_t abuf = a_base + (uint32_t)((t % STAGES) * STG_ELEM * 2);
        const uint32_t bbuf = b_base + (uint32_t)((t % STAGES) * STG_ELEM * 2);
#pragma unroll
        for (int kk = 0; kk < BK; kk += 16) {
            uint32_t afr[4][4];
            uint32_t bfr[2][4];
#pragma unroll
            for (int mi = 0; mi < 4; mi++) {
                uint32_t a_addr = abuf +
                    (uint32_t)(((wm * 64 + mi * 16 + a_row_in) * STRIDE + kk + a_k_in) << 1);
                ldmx4(afr[mi], a_addr);
            }
#pragma unroll
            for (int nip = 0; nip < 2; nip++) {
                uint32_t b_addr = bbuf +
                    (uint32_t)(((wn * 32 + nip * 16 + bp_row) * STRIDE + kk + bp_k) << 1);
                ldmx4(bfr[nip], b_addr);
            }
#pragma unroll
            for (int mi = 0; mi < 4; mi++)
#pragma unroll
                for (int nip = 0; nip < 2; nip++) {
                    mma16816h(acc[mi][2 * nip],     afr[mi], &bfr[nip][0]);
                    mma16816h(acc[mi][2 * nip + 1], afr[mi], &bfr[nip][2]);
                }
        }
    }

#pragma unroll
    for (int mi = 0; mi < 4; mi++) {
        int r0 = row0 + wm * 64 + mi * 16 + g;
#pragma unroll
        for (int ni = 0; ni < 4; ni++) {
            int cc = col0 + wn * 32 + ni * 8 + tig * 2;
            float2 v0 = { acc[mi][ni][0], acc[mi][ni][1] };
            float2 v1 = { acc[mi][ni][2], acc[mi][ni][3] };
            *(float2*)&C[(size_t)r0 * N + cc]       = v0;
            *(float2*)&C[(size_t)(r0 + 8) * N + cc] = v1;
        }
    }
}

// ---------------- prep: Q2/K2 fp16, V3 bf16 ----------------
__global__ void prep_kernel(const float* __restrict__ q,
                            const float* __restrict__ kv,
                            const float* __restrict__ null_kv,
                            const float* __restrict__ q_scale,
                            const float* __restrict__ k_scale,
                            __half* __restrict__ Q2,
                            __half* __restrict__ K2,
                            __nv_bfloat16* __restrict__ V3) {
    int warp = (blockIdx.x * blockDim.x + threadIdx.x) >> 5;
    int lane = threadIdx.x & 31;
    if (warp >= B_ * H_ * J_) return;
    int bh = warp / J_;
    int j  = warp % J_;
    int b = bh / H_, h = bh % H_;
    int d0 = lane, d1 = lane + 32;

    float k0, k1, v0, v1;
    if (j < NNK_) {
        const float* nb = null_kv + ((size_t)(h * NNK_ + j) * 2) * DH_;
        k0 = nb[d0];        k1 = nb[d1];
        v0 = nb[DH_ + d0];  v1 = nb[DH_ + d1];
    } else {
        int n = j - NNK_;
        const float* base = kv + ((size_t)(b * N_ + n)) * (2 * DIM_) + h * DH_;
        k0 = base[d0];          k1 = base[d1];
        v0 = base[DIM_ + d0];   v1 = base[DIM_ + d1];
    }
    float ss = k0 * k0 + k1 * k1;
#pragma unroll
    for (int off = 16; off > 0; off >>= 1)
        ss += __shfl_xor_sync(0xffffffffu, ss, off);
    float inv = 1.0f / fmaxf(sqrtf(ss), 1e-12f);
    size_t ko = ((size_t)bh * J_PAD + j) * 64;
    K2[ko + d0] = __float2half_rn(k0 * inv * k_scale[d0]);
    K2[ko + d1] = __float2half_rn(k1 * inv * k_scale[d1]);

    __nv_bfloat16 bh0, bl0, bh1, bl1;
    size_t vo = ((size_t)bh * J_PAD + j) * 128;
    split_bf16(v0, bh0, bl0); split_bf16(v1, bh1, bl1);
    V3[vo + d0] = bh0; V3[vo + 64 + d0] = bl0;
    V3[vo + d1] = bh1; V3[vo + 64 + d1] = bl1;

    if (j < N_) {
        int n = j;
        const float* qb = q + ((size_t)(b * N_ + n)) * DIM_ + h * DH_;
        float a0 = qb[d0], a1 = qb[d1];
        float qs2 = a0 * a0 + a1 * a1;
#pragma unroll
        for (int off = 16; off > 0; off >>= 1)
            qs2 += __shfl_xor_sync(0xffffffffu, qs2, off);
        float qinv = 1.0f / fmaxf(sqrtf(qs2), 1e-12f);
        float q0 = a0 * qinv * q_scale[d0];
        float q1 = a1 * qinv * q_scale[d1];
        size_t qo = ((size_t)bh * N_ + n) * 128;
        __half hh, hl;
        split_f16(q0, hh, hl);
        Q2[qo + d0] = hh; Q2[qo + 64 + d0] = hl;
        split_f16(q1, hh, hl);
        Q2[qo + d1] = hh; Q2[qo + 64 + d1] = hl;
    }
}

// ---------------- hybrid flash attention: fp16 2-term QK, bf16 3-term PV ----------------
// smem (bytes): Qs fp16 [128][136] @0 (34816), Ks fp16 [2][64][72] @34816 (2x9216),
//               Vs bf16 [2][64][136] @53248 (2x17408), mm [2][64] @88064 (512)
#define QS_OFF   0
#define KS_OFF   34816
#define KS_SZ    9216
#define VS_OFF   53248
#define VS_SZ    17408
#define MM_OFF   88064
#define SMEM_ATT 88576

__device__ __forceinline__ float softel(float s, int ig, int jg, int h,
                                        const float* __restrict__ bias) {
    bool ok = (jg <= ig + NNK_) && (jg < J_);
    float bv = 0.f;
    if (ok && jg >= NNK_) bv = __ldg(bias + ((size_t)h * N_ + ig) * N_ + (jg - NNK_));
    float t = fmaf(s, 11.541560327111707f, fmaf(bv, 1.4426950408889634f, -23.083120654223414f));
    float r;
    asm("ex2.approx.f32 %0, %1;" : "=f"(r) : "f"(t));
    return ok ? r : 0.f;
}

__device__ __forceinline__ void load_tile(int stage, int j0, int bh, int b, int tid,
        uint32_t sbase, char* smx,
        const __half* __restrict__ K2, const __nv_bfloat16* __restrict__ V3,
        const int* __restrict__ mask) {
    uint32_t ks = sbase + KS_OFF + stage * KS_SZ;
    uint32_t vs = sbase + VS_OFF + stage * VS_SZ;
#pragma unroll
    for (int i = 0; i < 2; i++) {
        int idx = i * 256 + tid;
        int row = idx >> 3, c = idx & 7;
        cp16(ks + (uint32_t)((row * 72 + c * 8) * 2),
             K2 + ((size_t)bh * J_PAD + j0 + row) * 64 + c * 8);
    }
#pragma unroll
    for (int i = 0; i < 4; i++) {
        int idx = i * 256 + tid;
        int row = idx >> 4, c = idx & 15;
        cp16(vs + (uint32_t)((row * 136 + c * 8) * 2),
             V3 + ((size_t)bh * J_PAD + j0 + row) * 128 + c * 8);
    }
    if (tid < 64) {
        int jg = j0 + tid;
        float mm = 1.f;
        if (jg >= NNK_) mm = (jg < J_ && mask[b * N_ + jg - NNK_] != 0) ? 1.f : 0.f;
        ((float*)(smx + MM_OFF))[stage * 64 + tid] = mm;
    }
}

__global__ void __launch_bounds__(256, 2) attn_mma_kernel(
        const __half* __restrict__ Q2, const __half* __restrict__ K2,
        const __nv_bfloat16* __restrict__ V3, const float* __restrict__ bias,
        const int* __restrict__ mask, __half* __restrict__ att2) {
    extern __shared__ char smx[];
    const uint32_t sbase = (uint32_t)__cvta_generic_to_shared(smx);

    const int tid = threadIdx.x;
    const int w = tid >> 5, lane = tid & 31;
    const int g = lane >> 2, tig = lane & 3;
    const int ib = (int)gridDim.x - 1 - (int)blockIdx.x;   // heavy CTAs first
    const int i0 = ib * 128;
    const int bh = blockIdx.y, b = bh >> 4, h = bh & 15;
    const int iw = i0 + w * 16;
    const int ig0 = iw + g, ig1 = ig0 + 8;

    const int jtmax = min((i0 + 129) >> 6, J_PAD / 64 - 1);

    // Q tile: 128 rows x 128 fp16 [Qhi|Qlo]
#pragma unroll
    for (int i = 0; i < 8; i++) {
        int idx = i * 256 + tid;
        int row = idx >> 4, c = idx & 15;
        cp16(sbase + QS_OFF + (uint32_t)((row * 136 + c * 8) * 2),
             Q2 + ((size_t)bh * N_ + i0 + row) * 128 + c * 8);
    }
    load_tile(0, 0, bh, b, tid, sbase, smx, K2, V3, mask);
    cp_commit();

    float oacc[8][4];
#pragma unroll
    for (int d = 0; d < 8; d++)
#pragma unroll
        for (int e = 0; e < 4; e++) oacc[d][e] = 0.f;
    float lsum0 = 0.f, lsum1 = 0.f;

    int buf = 0;
    for (int jt = 0; jt <= jtmax; jt++) {
        const int j0 = jt * 64;
        if (jt < jtmax)
            load_tile(buf ^ 1, j0 + 64, bh, b, tid, sbase, smx, K2, V3, mask);
        cp_commit();
        cp_wait1();
        __syncthreads();

        const bool active = (j0 <= iw + 15 + NNK_);
        if (active) {
            const uint32_t ks = sbase + KS_OFF + buf * KS_SZ;
            const uint32_t vs = sbase + VS_OFF + buf * VS_SZ;
            const float* mm = (const float*)(smx + MM_OFF) + buf * 64;

            float sacc[8][4];
#pragma unroll
            for (int jf = 0; jf < 8; jf++)
#pragma unroll
                for (int e = 0; e < 4; e++) sacc[jf][e] = 0.f;

            const int a_row = w * 16 + (lane & 15);
            const int a_kin = (lane >> 4) << 3;
            const int bp_row = ((lane >> 4) << 3) + (lane & 7);
            const int bp_k   = ((lane >> 3) & 1) << 3;
            // S = [Qhi|Qlo] . Khi  (fp16 2-term; paired-jf x4 K loads, K stride 72)
#pragma unroll
            for (int kc = 0; kc < 4; kc++) {
                uint32_t ah[4], al[4];
                ldmx4(ah, sbase + QS_OFF + (uint32_t)((a_row * 136 + kc * 16 + a_kin) << 1));
                ldmx4(al, sbase + QS_OFF + (uint32_t)((a_row * 136 + 64 + kc * 16 + a_kin) << 1));
#pragma unroll
                for (int jfp = 0; jfp < 4; jfp++) {
                    uint32_t khp[4];
                    uint32_t ka = ks + (uint32_t)(((jfp * 16 + bp_row) * 72 + kc * 16 + bp_k) << 1);
                    ldmx4(khp, ka);
                    mma16816h(sacc[2 * jfp],     ah, &khp[0]);
                    mma16816h(sacc[2 * jfp],     al, &khp[0]);
                    mma16816h(sacc[2 * jfp + 1], ah, &khp[2]);
                    mma16816h(sacc[2 * jfp + 1], al, &khp[2]);
                }
            }

            // softmax + split P to bf16 (wide exponent: no underflow)
            uint32_t phi2[8][2], plo2[8][2];
#pragma unroll
            for (int jf = 0; jf < 8; jf++) {
                int jc = j0 + jf * 8 + tig * 2;
                float m0 = mm[jf * 8 + tig * 2];
                float m1 = mm[jf * 8 + tig * 2 + 1];
                float p0 = softel(sacc[jf][0], ig0, jc,     h, bias) * m0;
                float p1 = softel(sacc[jf][1], ig0, jc + 1, h, bias) * m1;
                float p2 = softel(sacc[jf][2], ig1, jc,     h, bias) * m0;
                float p3 = softel(sacc[jf][3], ig1, jc + 1, h, bias) * m1;
                lsum0 += p0 + p1;
                lsum1 += p2 + p3;
                __nv_bfloat16 h0, l0, h1, l1, h2, l2, h3, l3;
                split_bf16(p0, h0, l0); split_bf16(p1, h1, l1);
                split_bf16(p2, h2, l2); split_bf16(p3, h3, l3);
                phi2[jf][0] = bpack(h0, h1); phi2[jf][1] = bpack(h2, h3);
                plo2[jf][0] = bpack(l0, l1); plo2[jf][1] = bpack(l2, l3);
            }

            // O += Phi*Vhi + Plo*Vhi + Phi*Vlo (bf16 3-term, frag reuse)
#pragma unroll
            for (int kc2 = 0; kc2 < 4; kc2++) {
                uint32_t ah[4] = { phi2[2 * kc2][0], phi2[2 * kc2][1],
                                   phi2[2 * kc2 + 1][0], phi2[2 * kc2 + 1][1] };
                uint32_t al[4] = { plo2[2 * kc2][0], plo2[2 * kc2][1],
                                   plo2[2 * kc2 + 1][0], plo2[2 * kc2 + 1][1] };
#pragma unroll
                for (int df = 0; df < 8; df++) {
                    uint32_t vh[2], vl[2];
                    uint32_t va = vs + (uint32_t)((((kc2 * 16 + (lane & 15)) * 136) + df * 8) << 1);
                    ldmx2t(vh, va);
                    ldmx2t(vl, va + 128);
                    mma16816(oacc[df], ah, vh);
                    mma16816(oacc[df], al, vh);
                    mma16816(oacc[df], ah, vl);
                }
            }
        }
        __syncthreads();
        buf ^= 1;
    }

    lsum0 += __shfl_xor_sync(0xffffffffu, lsum0, 1);
    lsum0 += __shfl_xor_sync(0xffffffffu, lsum0, 2);
    lsum1 += __shfl_xor_sync(0xffffffffu, lsum1, 1);
    lsum1 += __shfl_xor_sync(0xffffffffu, lsum1, 2);
    float inv0 = 1.0f / lsum0;
    float inv1 = 1.0f / lsum1;

    // epilogue: fp16 [hi|lo] rows for the fp16 output GEMM
#pragma unroll
    for (int df = 0; df < 8; df++) {
        float o0 = oacc[df][0] * inv0, o1 = oacc[df][1] * inv0;
        float o2 = oacc[df][2] * inv1, o3 = oacc[df][3] * inv1;
        __half h0, l0, h1, l1, h2, l2, h3, l3;
        split_f16(o0, h0, l0); split_f16(o1, h1, l1);
        split_f16(o2, h2, l2); split_f16(o3, h3, l3);
        {
            __half* p = att2 + ((size_t)(b * N_ + ig0)) * KP2 + h * DH_ + df * 8 + tig * 2;
            *(uint32_t*)(p)        = hpack(h0, h1);
            *(uint32_t*)(p + DIM_) = hpack(l0, l1);
        }
        {
            __half* p = att2 + ((size_t)(b * N_ + ig1)) * KP2 + h * DH_ + df * 8 + tig * 2;
            *(uint32_t*)(p)        = hpack(h2, h3);
            *(uint32_t*)(p + DIM_) = hpack(l2, l3);
        }
    }
}

// ---------------- launch ----------------
extern "C" void kernel_launch(void* const* d_in, const int* in_sizes, int n_in,
                              void* d_out, int out_size) {
    const float* x     = (const float*)d_in[0];
    const int*   mask  = (const int*)d_in[1];
    const float* bias  = (const float*)d_in[2];
    const float* gamma = (const float*)d_in[3];
    const float* nkv   = (const float*)d_in[4];
    const float* Wq    = (const float*)d_in[5];
    const float* Wkv   = (const float*)d_in[6];
    const float* qsc   = (const float*)d_in[7];
    const float* ksc   = (const float*)d_in[8];
    const float* Wo    = (const float*)d_in[9];
    float* out = (float*)d_out;

    __half *p_x2, *p_xn2, *p_att2, *p_Wq2T, *p_Wkv2T, *p_Wo2T, *p_Q2, *p_K2;
    __nv_bfloat16 *p_V3;
    float *p_q, *p_kv;
    cudaGetSymbolAddress((void**)&p_x2,    g_x2);
    cudaGetSymbolAddress((void**)&p_xn2,   g_xn2);
    cudaGetSymbolAddress((void**)&p_att2,  g_att2);
    cudaGetSymbolAddress((void**)&p_Wq2T,  g_Wq2T);
    cudaGetSymbolAddress((void**)&p_Wkv2T, g_Wkv2T);
    cudaGetSymbolAddress((void**)&p_Wo2T,  g_Wo2T);
    cudaGetSymbolAddress((void**)&p_q,     g_q);
    cudaGetSymbolAddress((void**)&p_kv,    g_kv);
    cudaGetSymbolAddress((void**)&p_Q2,    g_Q2);
    cudaGetSymbolAddress((void**)&p_K2,    g_K2);
    cudaGetSymbolAddress((void**)&p_V3,    g_V3);

    ln_kernel<<<MTOT, 256>>>(x, gamma, p_xn2, p_x2);                                  // 1
    wconv_all_kernel<<<dim3(2 * DIM_ / 32, DIM_ / 32, 3), dim3(32, 8)>>>(
        Wq, p_Wq2T, Wkv, p_Wkv2T, Wo, p_Wo2T);                                        // 2

    dim3 gq(DIM_ / 128, MTOT / 128);
    hgemm_kernel<<<gq, 256>>>(p_xn2, p_Wq2T, p_q, MTOT, DIM_, DIM_ / BK);             // 3
    dim3 gkv(2 * DIM_ / 128, MTOT / 128);
    hgemm_kernel<<<gkv, 256>>>(p_x2, p_Wkv2T, p_kv, MTOT, 2 * DIM_, DIM_ / BK);       // 4

    int nwarp = B_ * H_ * J_;
    prep_kernel<<<(nwarp + 7) / 8, 256>>>(p_q, p_kv, nkv, qsc, ksc, p_Q2, p_K2, p_V3);// 5

    cudaFuncSetAttribute(attn_mma_kernel, cudaFuncAttributeMaxDynamicSharedMemorySize, SMEM_ATT);
    dim3 ga(N_ / 128, B_ * H_);
    attn_mma_kernel<<<ga, 256, SMEM_ATT>>>(p_Q2, p_K2, p_V3, bias, mask, p_att2);     // 6

    hgemm_kernel<<<gq, 256>>>(p_att2, p_Wo2T, out, MTOT, DIM_, DIM_ / BK);            // 7
}

// round 16
// speedup vs baseline: 3.4617x; 1.1704x over previous
#include <cuda_runtime.h>
#include <cuda_fp16.h>
#include <cuda_bf16.h>
#include <math.h>
#include <stdint.h>

// ---------------- problem constants ----------------
#define B_    2
#define N_    2048
#define DIM_  1024
#define H_    16
#define DH_   64
#define NNK_  2
#define J_    (N_ + NNK_)    // 2050
#define J_PAD 2112           // 33 tiles of 64
#define KP2   2048           // fp16 2-term split K' (row stride)
#define MTOT  (B_ * N_)      // 4096

// ---------------- scratch (device globals; no allocs allowed) ----------------
__device__ __align__(16) __half g_x2   [MTOT * KP2];      // [xhi|xlo]
__device__ __align__(16) __half g_xn2  [MTOT * KP2];      // layernorm(x) split
__device__ __align__(16) __half g_att2 [MTOT * KP2];      // attention out split
__device__ __align__(16) __half g_Wq2T [DIM_ * KP2];      // [N][Whi|Whi]
__device__ __align__(16) __half g_Wkv2T[2 * DIM_ * KP2];
__device__ __align__(16) __half g_Wo2T [DIM_ * KP2];
__device__ float g_q  [MTOT * DIM_];
__device__ float g_kv [MTOT * 2 * DIM_];
// attention operands (padding rows stay zero-initialized)
__device__ __align__(16) __half        g_Q2 [B_ * H_ * N_ * 128];     // fp16 [Qhi|Qlo]
__device__ __align__(16) __half        g_K2 [B_ * H_ * J_PAD * 64];   // fp16 Khi
__device__ __align__(16) __nv_bfloat16 g_V3 [B_ * H_ * J_PAD * 128];  // bf16 [Vhi|Vlo]

// ---------------- helpers ----------------
__device__ __forceinline__ void split_f16(float v, __half& hi, __half& lo) {
    hi = __float2half_rn(v);
    lo = __float2half_rn(v - __half2float(hi));
}
__device__ __forceinline__ void split_bf16(float v, __nv_bfloat16& hi, __nv_bfloat16& lo) {
    hi = __float2bfloat16_rn(v);
    lo = __float2bfloat16_rn(v - __bfloat162float(hi));
}
__device__ __forceinline__ uint32_t hpack(__half a, __half b) {
    __half2 t = __halves2half2(a, b);
    return *reinterpret_cast<uint32_t*>(&t);
}
__device__ __forceinline__ uint32_t bpack(__nv_bfloat16 a, __nv_bfloat16 b) {
    __nv_bfloat162 t = __halves2bfloat162(a, b);
    return *reinterpret_cast<uint32_t*>(&t);
}
__device__ __forceinline__ void ldmx4(uint32_t* r, uint32_t addr) {
    asm volatile("ldmatrix.sync.aligned.m8n8.x4.shared.b16 {%0,%1,%2,%3}, [%4];"
                 : "=r"(r[0]), "=r"(r[1]), "=r"(r[2]), "=r"(r[3]) : "r"(addr));
}
__device__ __forceinline__ void ldmx4t(uint32_t* r, uint32_t addr) {
    asm volatile("ldmatrix.sync.aligned.m8n8.x4.trans.shared.b16 {%0,%1,%2,%3}, [%4];"
                 : "=r"(r[0]), "=r"(r[1]), "=r"(r[2]), "=r"(r[3]) : "r"(addr));
}
__device__ __forceinline__ void mma16816h(float* d, const uint32_t* a, const uint32_t* b) {
    asm volatile("mma.sync.aligned.m16n8k16.row.col.f32.f16.f16.f32 {%0,%1,%2,%3},{%4,%5,%6,%7},{%8,%9},{%0,%1,%2,%3};"
                 : "+f"(d[0]), "+f"(d[1]), "+f"(d[2]), "+f"(d[3])
                 : "r"(a[0]), "r"(a[1]), "r"(a[2]), "r"(a[3]), "r"(b[0]), "r"(b[1]));
}
__device__ __forceinline__ void mma16816(float* d, const uint32_t* a, const uint32_t* b) {
    asm volatile("mma.sync.aligned.m16n8k16.row.col.f32.bf16.bf16.f32 {%0,%1,%2,%3},{%4,%5,%6,%7},{%8,%9},{%0,%1,%2,%3};"
                 : "+f"(d[0]), "+f"(d[1]), "+f"(d[2]), "+f"(d[3])
                 : "r"(a[0]), "r"(a[1]), "r"(a[2]), "r"(a[3]), "r"(b[0]), "r"(b[1]));
}
__device__ __forceinline__ void cp16(uint32_t saddr, const void* gptr) {
    asm volatile("cp.async.cg.shared.global [%0], [%1], 16;" :: "r"(saddr), "l"(gptr));
}
__device__ __forceinline__ void cp_commit() { asm volatile("cp.async.commit_group;"); }
__device__ __forceinline__ void cp_wait1() { asm volatile("cp.async.wait_group 1;"); }

// ---------------- LayerNorm -> xn2, and x -> x2 (fused, fp16 splits) ----------------
__global__ void ln_kernel(const float* __restrict__ x,
                          const float* __restrict__ gamma,
                          __half* __restrict__ xn2,
                          __half* __restrict__ x2) {
    int row = blockIdx.x;
    const float* xr = x + (size_t)row * DIM_;
    float v[4];
    float s = 0.f, sq = 0.f;
#pragma unroll
    for (int i = 0; i < 4; i++) {
        float t = xr[threadIdx.x + i * 256];
        v[i] = t; s += t; sq += t * t;
    }
#pragma unroll
    for (int off = 16; off > 0; off >>= 1) {
        s  += __shfl_xor_sync(0xffffffffu, s,  off);
        sq += __shfl_xor_sync(0xffffffffu, sq, off);
    }
    __shared__ float sa[8], sb[8];
    int w = threadIdx.x >> 5, l = threadIdx.x & 31;
    if (l == 0) { sa[w] = s; sb[w] = sq; }
    __syncthreads();
    if (threadIdx.x == 0) {
        float a = 0.f, bq = 0.f;
#pragma unroll
        for (int i = 0; i < 8; i++) { a += sa[i]; bq += sb[i]; }
        sa[0] = a; sb[0] = bq;
    }
    __syncthreads();
    float mean = sa[0] * (1.0f / DIM_);
    float var  = sb[0] * (1.0f / DIM_) - mean * mean;
    float rstd = rsqrtf(var + 1e-5f);
    __half* outr = xn2 + (size_t)row * KP2;
    __half* xo   = x2  + (size_t)row * KP2;
#pragma unroll
    for (int i = 0; i < 4; i++) {
        int d = threadIdx.x + i * 256;
        float o = (v[i] - mean) * rstd * gamma[d];
        __half hi, lo; split_f16(o, hi, lo);
        outr[d] = hi; outr[DIM_ + d] = lo;
        split_f16(v[i], hi, lo);
        xo[d] = hi; xo[DIM_ + d] = lo;
    }
}

// ---------------- merged weight conversion: z=0 Wq, z=1 Wkv, z=2 Wo ----------------
__global__ void wconv_all_kernel(const float* __restrict__ Wq, __half* __restrict__ Wq2T,
                                 const float* __restrict__ Wkv, __half* __restrict__ Wkv2T,
                                 const float* __restrict__ Wo, __half* __restrict__ Wo2T) {
    const float* W; __half* W2T; int N;
    if (blockIdx.z == 0)      { W = Wq;  W2T = Wq2T;  N = DIM_; }
    else if (blockIdx.z == 1) { W = Wkv; W2T = Wkv2T; N = 2 * DIM_; }
    else                      { W = Wo;  W2T = Wo2T;  N = DIM_; }
    int n0 = blockIdx.x * 32;
    if (n0 >= N) return;
    __shared__ float t[32][33];
    int k0 = blockIdx.y * 32;
    int tx = threadIdx.x, ty = threadIdx.y;   // 32 x 8
#pragma unroll
    for (int i = 0; i < 4; i++)
        t[ty + i * 8][tx] = W[(size_t)(k0 + ty + i * 8) * N + n0 + tx];
    __syncthreads();
#pragma unroll
    for (int i = 0; i < 4; i++) {
        int n = n0 + ty + i * 8;
        int k = k0 + tx;
        __half hi = __float2half_rn(t[tx][ty + i * 8]);
        __half* o = W2T + (size_t)n * KP2;
        o[k] = hi; o[DIM_ + k] = hi;
    }
}

// ---------------- fp16 HMMA GEMM body (3-stage cp.async) ----------------
#define STAGES 3
#define BK 32
#define STRIDE 40
#define STG_ELEM (128 * STRIDE)

__device__ __forceinline__ void gemm_body(
        const __half* __restrict__ A, const __half* __restrict__ BT,
        float* __restrict__ C, int N, int nkt, int row0, int col0,
        __half* As, __half* Bs) {
    const int tid  = threadIdx.x;
    const int wid  = tid >> 5, lane = tid & 31;
    const int wm   = wid & 1, wn = wid >> 1;
    const int g    = lane >> 2, tig = lane & 3;

    const int lrow = tid >> 1;
    const int lcol = (tid & 1) << 4;
    const __half* Ag = A  + (size_t)(row0 + lrow) * KP2 + lcol;
    const __half* Bg = BT + (size_t)(col0 + lrow) * KP2 + lcol;

    const uint32_t a_base = (uint32_t)__cvta_generic_to_shared(As);
    const uint32_t b_base = (uint32_t)__cvta_generic_to_shared(Bs);
    const uint32_t a_dst = a_base + (uint32_t)((lrow * STRIDE + lcol) * 2);
    const uint32_t b_dst = b_base + (uint32_t)((lrow * STRIDE + lcol) * 2);

    float acc[4][4][4];
#pragma unroll
    for (int mi = 0; mi < 4; mi++)
#pragma unroll
        for (int ni = 0; ni < 4; ni++)
#pragma unroll
            for (int e = 0; e < 4; e++) acc[mi][ni][e] = 0.f;

    const int a_row_in = lane & 15;
    const int a_k_in   = (lane >> 4) << 3;
    const int bp_row   = ((lane >> 4) << 3) + (lane & 7);
    const int bp_k     = ((lane >> 3) & 1) << 3;

#pragma unroll
    for (int s = 0; s < STAGES - 1; s++) {
        uint32_t so = (uint32_t)(s * STG_ELEM * 2);
        cp16(a_dst + so,      Ag + s * BK);
        cp16(a_dst + so + 16, Ag + s * BK + 8);
        cp16(b_dst + so,      Bg + s * BK);
        cp16(b_dst + so + 16, Bg + s * BK + 8);
        cp_commit();
    }

    for (int t = 0; t < nkt; t++) {
        cp_wait1();
        __syncthreads();

        if (t + STAGES - 1 < nkt) {
            uint32_t so = (uint32_t)(((t + STAGES - 1) % STAGES) * STG_ELEM * 2);
            const __half* ap = Ag + (t + STAGES - 1) * BK;
            const __half* bp = Bg + (t + STAGES - 1) * BK;
            cp16(a_dst + so,      ap);
            cp16(a_dst + so + 16, ap + 8);
            cp16(b_dst + so,      bp);
            cp16(b_dst + so + 16, bp + 8);
        }
        cp_commit();

        const uint32_t abuf = a_base + (uint32_t)((t % STAGES) * STG_ELEM * 2);
        const uint32_t bbuf = b_base + (uint32_t)((t % STAGES) * STG_ELEM * 2);
#pragma unroll
        for (int kk = 0; kk < BK; kk += 16) {
            uint32_t afr[4][4];
            uint32_t bfr[2][4];
#pragma unroll
            for (int mi = 0; mi < 4; mi++) {
                uint32_t a_addr = abuf +
                    (uint32_t)(((wm * 64 + mi * 16 + a_row_in) * STRIDE + kk + a_k_in) << 1);
                ldmx4(afr[mi], a_addr);
            }
#pragma unroll
            for (int nip = 0; nip < 2; nip++) {
                uint32_t b_addr = bbuf +
                    (uint32_t)(((wn * 32 + nip * 16 + bp_row) * STRIDE + kk + bp_k) << 1);
                ldmx4(bfr[nip], b_addr);
            }
#pragma unroll
            for (int mi = 0; mi < 4; mi++)
#pragma unroll
                for (int nip = 0; nip < 2; nip++) {
                    mma16816h(acc[mi][2 * nip],     afr[mi], &bfr[nip][0]);
                    mma16816h(acc[mi][2 * nip + 1], afr[mi], &bfr[nip][2]);
                }
        }
    }

#pragma unroll
    for (int mi = 0; mi < 4; mi++) {
        int r0 = row0 + wm * 64 + mi * 16 + g;
#pragma unroll
        for (int ni = 0; ni < 4; ni++) {
            int cc = col0 + wn * 32 + ni * 8 + tig * 2;
            float2 v0 = { acc[mi][ni][0], acc[mi][ni][1] };
            float2 v1 = { acc[mi][ni][2], acc[mi][ni][3] };
            *(float2*)&C[(size_t)r0 * N + cc]       = v0;
            *(float2*)&C[(size_t)(r0 + 8) * N + cc] = v1;
        }
    }
}

// merged Q + KV projection: grid.x 0..7 -> Q, 8..23 -> KV
__global__ void __launch_bounds__(256, 2) qkv_gemm_kernel(
        const __half* __restrict__ xn2, const __half* __restrict__ Wq2T, float* __restrict__ q,
        const __half* __restrict__ x2, const __half* __restrict__ Wkv2T, float* __restrict__ kvout) {
    __shared__ __half As[STAGES * STG_ELEM];
    __shared__ __half Bs[STAGES * STG_ELEM];
    int cx = blockIdx.x;
    int row0 = blockIdx.y * 128;
    if (cx < 8) gemm_body(xn2, Wq2T, q, DIM_, DIM_ / BK, row0, cx * 128, As, Bs);
    else        gemm_body(x2, Wkv2T, kvout, 2 * DIM_, DIM_ / BK, row0, (cx - 8) * 128, As, Bs);
}

// output projection
__global__ void __launch_bounds__(256, 2) o_gemm_kernel(
        const __half* __restrict__ A, const __half* __restrict__ BT, float* __restrict__ C) {
    __shared__ __half As[STAGES * STG_ELEM];
    __shared__ __half Bs[STAGES * STG_ELEM];
    gemm_body(A, BT, C, DIM_, DIM_ / BK, blockIdx.y * 128, blockIdx.x * 128, As, Bs);
}

// ---------------- prep: Q2/K2 fp16, V3 bf16 ----------------
__global__ void prep_kernel(const float* __restrict__ q,
                            const float* __restrict__ kv,
                            const float* __restrict__ null_kv,
                            const float* __restrict__ q_scale,
                            const float* __restrict__ k_scale,
                            __half* __restrict__ Q2,
                            __half* __restrict__ K2,
                            __nv_bfloat16* __restrict__ V3) {
    int warp = (blockIdx.x * blockDim.x + threadIdx.x) >> 5;
    int lane = threadIdx.x & 31;
    if (warp >= B_ * H_ * J_) return;
    int bh = warp / J_;
    int j  = warp % J_;
    int b = bh / H_, h = bh % H_;
    int d0 = lane, d1 = lane + 32;

    float k0, k1, v0, v1;
    if (j < NNK_) {
        const float* nb = null_kv + ((size_t)(h * NNK_ + j) * 2) * DH_;
        k0 = nb[d0];        k1 = nb[d1];
        v0 = nb[DH_ + d0];  v1 = nb[DH_ + d1];
    } else {
        int n = j - NNK_;
        const float* base = kv + ((size_t)(b * N_ + n)) * (2 * DIM_) + h * DH_;
        k0 = base[d0];          k1 = base[d1];
        v0 = base[DIM_ + d0];   v1 = base[DIM_ + d1];
    }
    float ss = k0 * k0 + k1 * k1;
#pragma unroll
    for (int off = 16; off > 0; off >>= 1)
        ss += __shfl_xor_sync(0xffffffffu, ss, off);
    float inv = 1.0f / fmaxf(sqrtf(ss), 1e-12f);
    size_t ko = ((size_t)bh * J_PAD + j) * 64;
    K2[ko + d0] = __float2half_rn(k0 * inv * k_scale[d0]);
    K2[ko + d1] = __float2half_rn(k1 * inv * k_scale[d1]);

    __nv_bfloat16 bh0, bl0, bh1, bl1;
    size_t vo = ((size_t)bh * J_PAD + j) * 128;
    split_bf16(v0, bh0, bl0); split_bf16(v1, bh1, bl1);
    V3[vo + d0] = bh0; V3[vo + 64 + d0] = bl0;
    V3[vo + d1] = bh1; V3[vo + 64 + d1] = bl1;

    if (j < N_) {
        int n = j;
        const float* qb = q + ((size_t)(b * N_ + n)) * DIM_ + h * DH_;
        float a0 = qb[d0], a1 = qb[d1];
        float qs2 = a0 * a0 + a1 * a1;
#pragma unroll
        for (int off = 16; off > 0; off >>= 1)
            qs2 += __shfl_xor_sync(0xffffffffu, qs2, off);
        float qinv = 1.0f / fmaxf(sqrtf(qs2), 1e-12f);
        float q0 = a0 * qinv * q_scale[d0];
        float q1 = a1 * qinv * q_scale[d1];
        size_t qo = ((size_t)bh * N_ + n) * 128;
        __half hh, hl;
        split_f16(q0, hh, hl);
        Q2[qo + d0] = hh; Q2[qo + 64 + d0] = hl;
        split_f16(q1, hh, hl);
        Q2[qo + d1] = hh; Q2[qo + 64 + d1] = hl;
    }
}

// ---------------- hybrid flash attention: fp16 2-term QK, bf16 3-term PV ----------------
#define QS_OFF   0
#define KS_OFF   34816
#define KS_SZ    9216
#define VS_OFF   53248
#define VS_SZ    17408
#define MM_OFF   88064
#define SMEM_ATT 88576

__device__ __forceinline__ float softel2(float s, float bv, bool ok) {
    float t = fmaf(s, 11.541560327111707f, fmaf(bv, 1.4426950408889634f, -23.083120654223414f));
    float r;
    asm("ex2.approx.f32 %0, %1;" : "=f"(r) : "f"(t));
    return ok ? r : 0.f;
}

__device__ __forceinline__ void load_tile(int stage, int j0, int bh, int b, int tid,
        uint32_t sbase, char* smx,
        const __half* __restrict__ K2, const __nv_bfloat16* __restrict__ V3,
        const int* __restrict__ mask) {
    uint32_t ks = sbase + KS_OFF + stage * KS_SZ;
    uint32_t vs = sbase + VS_OFF + stage * VS_SZ;
#pragma unroll
    for (int i = 0; i < 2; i++) {
        int idx = i * 256 + tid;
        int row = idx >> 3, c = idx & 7;
        cp16(ks + (uint32_t)((row * 72 + c * 8) * 2),
             K2 + ((size_t)bh * J_PAD + j0 + row) * 64 + c * 8);
    }
#pragma unroll
    for (int i = 0; i < 4; i++) {
        int idx = i * 256 + tid;
        int row = idx >> 4, c = idx & 15;
        cp16(vs + (uint32_t)((row * 136 + c * 8) * 2),
             V3 + ((size_t)bh * J_PAD + j0 + row) * 128 + c * 8);
    }
    if (tid < 64) {
        int jg = j0 + tid;
        float mm = 1.f;
        if (jg >= NNK_) mm = (jg < J_ && mask[b * N_ + jg - NNK_] != 0) ? 1.f : 0.f;
        ((float*)(smx + MM_OFF))[stage * 64 + tid] = mm;
    }
}

__global__ void __launch_bounds__(256, 2) attn_mma_kernel(
        const __half* __restrict__ Q2, const __half* __restrict__ K2,
        const __nv_bfloat16* __restrict__ V3, const float* __restrict__ bias,
        const int* __restrict__ mask, __half* __restrict__ att2) {
    extern __shared__ char smx[];
    const uint32_t sbase = (uint32_t)__cvta_generic_to_shared(smx);

    const int tid = threadIdx.x;
    const int w = tid >> 5, lane = tid & 31;
    const int g = lane >> 2, tig = lane & 3;
    const int ib = (int)gridDim.x - 1 - (int)blockIdx.x;   // heavy CTAs first
    const int i0 = ib * 128;
    const int bh = blockIdx.y, b = bh >> 4, h = bh & 15;
    const int iw = i0 + w * 16;
    const int ig0 = iw + g, ig1 = ig0 + 8;
    const float* brow0 = bias + ((size_t)h * N_ + ig0) * N_ - NNK_;
    const float* brow1 = bias + ((size_t)h * N_ + ig1) * N_ - NNK_;

    const int jtmax = min((i0 + 129) >> 6, J_PAD / 64 - 1);

    // Q tile: 128 rows x 128 fp16 [Qhi|Qlo]
#pragma unroll
    for (int i = 0; i < 8; i++) {
        int idx = i * 256 + tid;
        int row = idx >> 4, c = idx & 15;
        cp16(sbase + QS_OFF + (uint32_t)((row * 136 + c * 8) * 2),
             Q2 + ((size_t)bh * N_ + i0 + row) * 128 + c * 8);
    }
    load_tile(0, 0, bh, b, tid, sbase, smx, K2, V3, mask);
    cp_commit();

    float oacc[8][4];
#pragma unroll
    for (int d = 0; d < 8; d++)
#pragma unroll
        for (int e = 0; e < 4; e++) oacc[d][e] = 0.f;
    float lsum0 = 0.f, lsum1 = 0.f;

    int buf = 0;
    for (int jt = 0; jt <= jtmax; jt++) {
        const int j0 = jt * 64;
        if (jt < jtmax)
            load_tile(buf ^ 1, j0 + 64, bh, b, tid, sbase, smx, K2, V3, mask);
        cp_commit();
        cp_wait1();
        __syncthreads();

        const bool active = (j0 <= iw + 15 + NNK_);
        if (active) {
            const uint32_t ks = sbase + KS_OFF + buf * KS_SZ;
            const uint32_t vs = sbase + VS_OFF + buf * VS_SZ;
            const float* mm = (const float*)(smx + MM_OFF) + buf * 64;

            float sacc[8][4];
#pragma unroll
            for (int jf = 0; jf < 8; jf++)
#pragma unroll
                for (int e = 0; e < 4; e++) sacc[jf][e] = 0.f;

            const int a_row = w * 16 + (lane & 15);
            const int a_kin = (lane >> 4) << 3;
            const int bp_row = ((lane >> 4) << 3) + (lane & 7);
            const int bp_k   = ((lane >> 3) & 1) << 3;
            // S = [Qhi|Qlo] . Khi  (fp16 2-term; paired-jf x4 K loads, K stride 72)
#pragma unroll
            for (int kc = 0; kc < 4; kc++) {
                uint32_t ah[4], al[4];
                ldmx4(ah, sbase + QS_OFF + (uint32_t)((a_row * 136 + kc * 16 + a_kin) << 1));
                ldmx4(al, sbase + QS_OFF + (uint32_t)((a_row * 136 + 64 + kc * 16 + a_kin) << 1));
#pragma unroll
                for (int jfp = 0; jfp < 4; jfp++) {
                    uint32_t khp[4];
                    uint32_t ka = ks + (uint32_t)(((jfp * 16 + bp_row) * 72 + kc * 16 + bp_k) << 1);
                    ldmx4(khp, ka);
                    mma16816h(sacc[2 * jfp],     ah, &khp[0]);
                    mma16816h(sacc[2 * jfp],     al, &khp[0]);
                    mma16816h(sacc[2 * jfp + 1], ah, &khp[2]);
                    mma16816h(sacc[2 * jfp + 1], al, &khp[2]);
                }
            }

            // softmax + split P to bf16 (float2 bias loads per row-pair)
            uint32_t phi2[8][2], plo2[8][2];
#pragma unroll
            for (int jf = 0; jf < 8; jf++) {
                int jc = j0 + jf * 8 + tig * 2;
                float m0 = mm[jf * 8 + tig * 2];
                float m1 = mm[jf * 8 + tig * 2 + 1];
                float2 bv0 = { 0.f, 0.f }, bv1 = { 0.f, 0.f };
                if (jc >= NNK_ && jc < J_) {     // jc even => pair fully in range
                    bv0 = *(const float2*)(brow0 + jc);
                    bv1 = *(const float2*)(brow1 + jc);
                }
                bool ok00 = (jc     <= ig0 + NNK_) && (jc     < J_);
                bool ok01 = (jc + 1 <= ig0 + NNK_) && (jc + 1 < J_);
                bool ok10 = (jc     <= ig1 + NNK_) && (jc     < J_);
                bool ok11 = (jc + 1 <= ig1 + NNK_) && (jc + 1 < J_);
                float p0 = softel2(sacc[jf][0], bv0.x, ok00) * m0;
                float p1 = softel2(sacc[jf][1], bv0.y, ok01) * m1;
                float p2 = softel2(sacc[jf][2], bv1.x, ok10) * m0;
                float p3 = softel2(sacc[jf][3], bv1.y, ok11) * m1;
                lsum0 += p0 + p1;
                lsum1 += p2 + p3;
                __nv_bfloat16 h0, l0, h1, l1, h2, l2, h3, l3;
                split_bf16(p0, h0, l0); split_bf16(p1, h1, l1);
                split_bf16(p2, h2, l2); split_bf16(p3, h3, l3);
                phi2[jf][0] = bpack(h0, h1); phi2[jf][1] = bpack(h2, h3);
                plo2[jf][0] = bpack(l0, l1); plo2[jf][1] = bpack(l2, l3);
            }

            // O += Phi*Vhi + Plo*Vhi + Phi*Vlo (bf16 3-term; x4t loads pack Vhi+Vlo)
            const int v_row = (lane & 7) + ((lane >> 3) & 1) * 8;  // row within 16
            const int v_cofs = (lane >> 4) * 64;                   // 0 -> Vhi, 64 -> Vlo
#pragma unroll
            for (int kc2 = 0; kc2 < 4; kc2++) {
                uint32_t ah[4] = { phi2[2 * kc2][0], phi2[2 * kc2][1],
                                   phi2[2 * kc2 + 1][0], phi2[2 * kc2 + 1][1] };
                uint32_t al[4] = { plo2[2 * kc2][0], plo2[2 * kc2][1],
                                   plo2[2 * kc2 + 1][0], plo2[2 * kc2 + 1][1] };
#pragma unroll
                for (int df = 0; df < 8; df++) {
                    uint32_t vf[4];
                    uint32_t va = vs + (uint32_t)((((kc2 * 16 + v_row) * 136) + df * 8 + v_cofs) << 1);
                    ldmx4t(vf, va);
                    mma16816(oacc[df], ah, &vf[0]);   // Phi * Vhi
                    mma16816(oacc[df], al, &vf[0]);   // Plo * Vhi
                    mma16816(oacc[df], ah, &vf[2]);   // Phi * Vlo
                }
            }
        }
        __syncthreads();
        buf ^= 1;
    }

    lsum0 += __shfl_xor_sync(0xffffffffu, lsum0, 1);
    lsum0 += __shfl_xor_sync(0xffffffffu, lsum0, 2);
    lsum1 += __shfl_xor_sync(0xffffffffu, lsum1, 1);
    lsum1 += __shfl_xor_sync(0xffffffffu, lsum1, 2);
    float inv0 = 1.0f / lsum0;
    float inv1 = 1.0f / lsum1;

    // epilogue: fp16 [hi|lo] rows for the fp16 output GEMM
#pragma unroll
    for (int df = 0; df < 8; df++) {
        float o0 = oacc[df][0] * inv0, o1 = oacc[df][1] * inv0;
        float o2 = oacc[df][2] * inv1, o3 = oacc[df][3] * inv1;
        __half h0, l0, h1, l1, h2, l2, h3, l3;
        split_f16(o0, h0, l0); split_f16(o1, h1, l1);
        split_f16(o2, h2, l2); split_f16(o3, h3, l3);
        {
            __half* p = att2 + ((size_t)(b * N_ + ig0)) * KP2 + h * DH_ + df * 8 + tig * 2;
            *(uint32_t*)(p)        = hpack(h0, h1);
            *(uint32_t*)(p + DIM_) = hpack(l0, l1);
        }
        {
            __half* p = att2 + ((size_t)(b * N_ + ig1)) * KP2 + h * DH_ + df * 8 + tig * 2;
            *(uint32_t*)(p)        = hpack(h2, h3);
            *(uint32_t*)(p + DIM_) = hpack(l2, l3);
        }
    }
}

// ---------------- launch ----------------
extern "C" void kernel_launch(void* const* d_in, const int* in_sizes, int n_in,
                              void* d_out, int out_size) {
    const float* x     = (const float*)d_in[0];
    const int*   mask  = (const int*)d_in[1];
    const float* bias  = (const float*)d_in[2];
    const float* gamma = (const float*)d_in[3];
    const float* nkv   = (const float*)d_in[4];
    const float* Wq    = (const float*)d_in[5];
    const float* Wkv   = (const float*)d_in[6];
    const float* qsc   = (const float*)d_in[7];
    const float* ksc   = (const float*)d_in[8];
    const float* Wo    = (const float*)d_in[9];
    float* out = (float*)d_out;

    __half *p_x2, *p_xn2, *p_att2, *p_Wq2T, *p_Wkv2T, *p_Wo2T, *p_Q2, *p_K2;
    __nv_bfloat16 *p_V3;
    float *p_q, *p_kv;
    cudaGetSymbolAddress((void**)&p_x2,    g_x2);
    cudaGetSymbolAddress((void**)&p_xn2,   g_xn2);
    cudaGetSymbolAddress((void**)&p_att2,  g_att2);
    cudaGetSymbolAddress((void**)&p_Wq2T,  g_Wq2T);
    cudaGetSymbolAddress((void**)&p_Wkv2T, g_Wkv2T);
    cudaGetSymbolAddress((void**)&p_Wo2T,  g_Wo2T);
    cudaGetSymbolAddress((void**)&p_q,     g_q);
    cudaGetSymbolAddress((void**)&p_kv,    g_kv);
    cudaGetSymbolAddress((void**)&p_Q2,    g_Q2);
    cudaGetSymbolAddress((void**)&p_K2,    g_K2);
    cudaGetSymbolAddress((void**)&p_V3,    g_V3);

    ln_kernel<<<MTOT, 256>>>(x, gamma, p_xn2, p_x2);                                  // 1
    wconv_all_kernel<<<dim3(2 * DIM_ / 32, DIM_ / 32, 3), dim3(32, 8)>>>(
        Wq, p_Wq2T, Wkv, p_Wkv2T, Wo, p_Wo2T);                                        // 2

    // merged Q + KV projection (768 CTAs)
    qkv_gemm_kernel<<<dim3(24, MTOT / 128), 256>>>(
        p_xn2, p_Wq2T, p_q, p_x2, p_Wkv2T, p_kv);                                     // 3

    int nwarp = B_ * H_ * J_;
    prep_kernel<<<(nwarp + 7) / 8, 256>>>(p_q, p_kv, nkv, qsc, ksc, p_Q2, p_K2, p_V3);// 4

    cudaFuncSetAttribute(attn_mma_kernel, cudaFuncAttributeMaxDynamicSharedMemorySize, SMEM_ATT);
    dim3 ga(N_ / 128, B_ * H_);
    attn_mma_kernel<<<ga, 256, SMEM_ATT>>>(p_Q2, p_K2, p_V3, bias, mask, p_att2);     // 5

    o_gemm_kernel<<<dim3(DIM_ / 128, MTOT / 128), 256>>>(p_att2, p_Wo2T, out);        // 6
}

// round 17
// speedup vs baseline: 3.7312x; 1.0779x over previous
#include <cuda_runtime.h>
#include <cuda_fp16.h>
#include <cuda_bf16.h>
#include <math.h>
#include <stdint.h>

// ---------------- problem constants ----------------
#define B_    2
#define N_    2048
#define DIM_  1024
#define H_    16
#define DH_   64
#define NNK_  2
#define J_    (N_ + NNK_)    // 2050
#define J_PAD 2112           // 33 tiles of 64
#define KP2   2048           // fp16 2-term split K' (row stride)
#define MTOT  (B_ * N_)      // 4096

// ---------------- scratch (device globals; no allocs allowed) ----------------
__device__ __align__(16) __half g_x2   [MTOT * KP2];      // [xhi|xlo]
__device__ __align__(16) __half g_xn2  [MTOT * KP2];      // layernorm(x) split
__device__ __align__(16) __half g_att2 [MTOT * KP2];      // attention out split
__device__ __align__(16) __half g_Wq2T [DIM_ * KP2];      // [N][Whi|Whi]
__device__ __align__(16) __half g_Wkv2T[2 * DIM_ * KP2];
__device__ __align__(16) __half g_Wo2T [DIM_ * KP2];
__device__ float g_q  [MTOT * DIM_];
__device__ float g_kv [MTOT * 2 * DIM_];
// attention operands (padding rows stay zero-initialized)
__device__ __align__(16) __half g_Q2 [B_ * H_ * N_ * 128];     // fp16 [Qhi|Qlo]
__device__ __align__(16) __half g_K2 [B_ * H_ * J_PAD * 64];   // fp16 Khi
__device__ __align__(16) __half g_V2 [B_ * H_ * J_PAD * 64];   // fp16 Vhi

// ---------------- helpers ----------------
__device__ __forceinline__ void split_f16(float v, __half& hi, __half& lo) {
    hi = __float2half_rn(v);
    lo = __float2half_rn(v - __half2float(hi));
}
__device__ __forceinline__ uint32_t hpack(__half a, __half b) {
    __half2 t = __halves2half2(a, b);
    return *reinterpret_cast<uint32_t*>(&t);
}
__device__ __forceinline__ uint32_t hpackf(float a, float b) {
    __half2 t = __halves2half2(__float2half_rn(a), __float2half_rn(b));
    return *reinterpret_cast<uint32_t*>(&t);
}
__device__ __forceinline__ float ex2(float t) {
    float r;
    asm("ex2.approx.f32 %0, %1;" : "=f"(r) : "f"(t));
    return r;
}
__device__ __forceinline__ void ldmx4(uint32_t* r, uint32_t addr) {
    asm volatile("ldmatrix.sync.aligned.m8n8.x4.shared.b16 {%0,%1,%2,%3}, [%4];"
                 : "=r"(r[0]), "=r"(r[1]), "=r"(r[2]), "=r"(r[3]) : "r"(addr));
}
__device__ __forceinline__ void ldmx4t(uint32_t* r, uint32_t addr) {
    asm volatile("ldmatrix.sync.aligned.m8n8.x4.trans.shared.b16 {%0,%1,%2,%3}, [%4];"
                 : "=r"(r[0]), "=r"(r[1]), "=r"(r[2]), "=r"(r[3]) : "r"(addr));
}
__device__ __forceinline__ void mma16816h(float* d, const uint32_t* a, const uint32_t* b) {
    asm volatile("mma.sync.aligned.m16n8k16.row.col.f32.f16.f16.f32 {%0,%1,%2,%3},{%4,%5,%6,%7},{%8,%9},{%0,%1,%2,%3};"
                 : "+f"(d[0]), "+f"(d[1]), "+f"(d[2]), "+f"(d[3])
                 : "r"(a[0]), "r"(a[1]), "r"(a[2]), "r"(a[3]), "r"(b[0]), "r"(b[1]));
}
__device__ __forceinline__ void cp16(uint32_t saddr, const void* gptr) {
    asm volatile("cp.async.cg.shared.global [%0], [%1], 16;" :: "r"(saddr), "l"(gptr));
}
__device__ __forceinline__ void cp_commit() { asm volatile("cp.async.commit_group;"); }
__device__ __forceinline__ void cp_wait1() { asm volatile("cp.async.wait_group 1;"); }

// ---------------- LayerNorm -> xn2, and x -> x2 (fused, fp16 splits) ----------------
__global__ void ln_kernel(const float* __restrict__ x,
                          const float* __restrict__ gamma,
                          __half* __restrict__ xn2,
                          __half* __restrict__ x2) {
    int row = blockIdx.x;
    const float* xr = x + (size_t)row * DIM_;
    float v[4];
    float s = 0.f, sq = 0.f;
#pragma unroll
    for (int i = 0; i < 4; i++) {
        float t = xr[threadIdx.x + i * 256];
        v[i] = t; s += t; sq += t * t;
    }
#pragma unroll
    for (int off = 16; off > 0; off >>= 1) {
        s  += __shfl_xor_sync(0xffffffffu, s,  off);
        sq += __shfl_xor_sync(0xffffffffu, sq, off);
    }
    __shared__ float sa[8], sb[8];
    int w = threadIdx.x >> 5, l = threadIdx.x & 31;
    if (l == 0) { sa[w] = s; sb[w] = sq; }
    __syncthreads();
    if (threadIdx.x == 0) {
        float a = 0.f, bq = 0.f;
#pragma unroll
        for (int i = 0; i < 8; i++) { a += sa[i]; bq += sb[i]; }
        sa[0] = a; sb[0] = bq;
    }
    __syncthreads();
    float mean = sa[0] * (1.0f / DIM_);
    float var  = sb[0] * (1.0f / DIM_) - mean * mean;
    float rstd = rsqrtf(var + 1e-5f);
    __half* outr = xn2 + (size_t)row * KP2;
    __half* xo   = x2  + (size_t)row * KP2;
#pragma unroll
    for (int i = 0; i < 4; i++) {
        int d = threadIdx.x + i * 256;
        float o = (v[i] - mean) * rstd * gamma[d];
        __half hi, lo; split_f16(o, hi, lo);
        outr[d] = hi; outr[DIM_ + d] = lo;
        split_f16(v[i], hi, lo);
        xo[d] = hi; xo[DIM_ + d] = lo;
    }
}

// ---------------- merged weight conversion: z=0 Wq, z=1 Wkv, z=2 Wo ----------------
__global__ void wconv_all_kernel(const float* __restrict__ Wq, __half* __restrict__ Wq2T,
                                 const float* __restrict__ Wkv, __half* __restrict__ Wkv2T,
                                 const float* __restrict__ Wo, __half* __restrict__ Wo2T) {
    const float* W; __half* W2T; int N;
    if (blockIdx.z == 0)      { W = Wq;  W2T = Wq2T;  N = DIM_; }
    else if (blockIdx.z == 1) { W = Wkv; W2T = Wkv2T; N = 2 * DIM_; }
    else                      { W = Wo;  W2T = Wo2T;  N = DIM_; }
    int n0 = blockIdx.x * 32;
    if (n0 >= N) return;
    __shared__ float t[32][33];
    int k0 = blockIdx.y * 32;
    int tx = threadIdx.x, ty = threadIdx.y;   // 32 x 8
#pragma unroll
    for (int i = 0; i < 4; i++)
        t[ty + i * 8][tx] = W[(size_t)(k0 + ty + i * 8) * N + n0 + tx];
    __syncthreads();
#pragma unroll
    for (int i = 0; i < 4; i++) {
        int n = n0 + ty + i * 8;
        int k = k0 + tx;
        __half hi = __float2half_rn(t[tx][ty + i * 8]);
        __half* o = W2T + (size_t)n * KP2;
        o[k] = hi; o[DIM_ + k] = hi;
    }
}

// ---------------- fp16 HMMA GEMM body (3-stage cp.async) ----------------
#define STAGES 3
#define BK 32
#define STRIDE 40
#define STG_ELEM (128 * STRIDE)

__device__ __forceinline__ void gemm_body(
        const __half* __restrict__ A, const __half* __restrict__ BT,
        float* __restrict__ C, int N, int nkt, int row0, int col0,
        __half* As, __half* Bs) {
    const int tid  = threadIdx.x;
    const int wid  = tid >> 5, lane = tid & 31;
    const int wm   = wid & 1, wn = wid >> 1;
    const int g    = lane >> 2, tig = lane & 3;

    const int lrow = tid >> 1;
    const int lcol = (tid & 1) << 4;
    const __half* Ag = A  + (size_t)(row0 + lrow) * KP2 + lcol;
    const __half* Bg = BT + (size_t)(col0 + lrow) * KP2 + lcol;

    const uint32_t a_base = (uint32_t)__cvta_generic_to_shared(As);
    const uint32_t b_base = (uint32_t)__cvta_generic_to_shared(Bs);
    const uint32_t a_dst = a_base + (uint32_t)((lrow * STRIDE + lcol) * 2);
    const uint32_t b_dst = b_base + (uint32_t)((lrow * STRIDE + lcol) * 2);

    float acc[4][4][4];
#pragma unroll
    for (int mi = 0; mi < 4; mi++)
#pragma unroll
        for (int ni = 0; ni < 4; ni++)
#pragma unroll
            for (int e = 0; e < 4; e++) acc[mi][ni][e] = 0.f;

    const int a_row_in = lane & 15;
    const int a_k_in   = (lane >> 4) << 3;
    const int bp_row   = ((lane >> 4) << 3) + (lane & 7);
    const int bp_k     = ((lane >> 3) & 1) << 3;

#pragma unroll
    for (int s = 0; s < STAGES - 1; s++) {
        uint32_t so = (uint32_t)(s * STG_ELEM * 2);
        cp16(a_dst + so,      Ag + s * BK);
        cp16(a_dst + so + 16, Ag + s * BK + 8);
        cp16(b_dst + so,      Bg + s * BK);
        cp16(b_dst + so + 16, Bg + s * BK + 8);
        cp_commit();
    }

    for (int t = 0; t < nkt; t++) {
        cp_wait1();
        __syncthreads();

        if (t + STAGES - 1 < nkt) {
            uint32_t so = (uint32_t)(((t + STAGES - 1) % STAGES) * STG_ELEM * 2);
            const __half* ap = Ag + (t + STAGES - 1) * BK;
            const __half* bp = Bg + (t + STAGES - 1) * BK;
            cp16(a_dst + so,      ap);
            cp16(a_dst + so + 16, ap + 8);
            cp16(b_dst + so,      bp);
            cp16(b_dst + so + 16, bp + 8);
        }
        cp_commit();

        const uint32_t abuf = a_base + (uint32_t)((t % STAGES) * STG_ELEM * 2);
        const uint32_t bbuf = b_base + (uint32_t)((t % STAGES) * STG_ELEM * 2);
#pragma unroll
        for (int kk = 0; kk < BK; kk += 16) {
            uint32_t afr[4][4];
            uint32_t bfr[2][4];
#pragma unroll
            for (int mi = 0; mi < 4; mi++) {
                uint32_t a_addr = abuf +
                    (uint32_t)(((wm * 64 + mi * 16 + a_row_in) * STRIDE + kk + a_k_in) << 1);
                ldmx4(afr[mi], a_addr);
            }
#pragma unroll
            for (int nip = 0; nip < 2; nip++) {
                uint32_t b_addr = bbuf +
                    (uint32_t)(((wn * 32 + nip * 16 + bp_row) * STRIDE + kk + bp_k) << 1);
                ldmx4(bfr[nip], b_addr);
            }
#pragma unroll
            for (int mi = 0; mi < 4; mi++)
#pragma unroll
                for (int nip = 0; nip < 2; nip++) {
                    mma16816h(acc[mi][2 * nip],     afr[mi], &bfr[nip][0]);
                    mma16816h(acc[mi][2 * nip + 1], afr[mi], &bfr[nip][2]);
                }
        }
    }

#pragma unroll
    for (int mi = 0; mi < 4; mi++) {
        int r0 = row0 + wm * 64 + mi * 16 + g;
#pragma unroll
        for (int ni = 0; ni < 4; ni++) {
            int cc = col0 + wn * 32 + ni * 8 + tig * 2;
            float2 v0 = { acc[mi][ni][0], acc[mi][ni][1] };
            float2 v1 = { acc[mi][ni][2], acc[mi][ni][3] };
            *(float2*)&C[(size_t)r0 * N + cc]       = v0;
            *(float2*)&C[(size_t)(r0 + 8) * N + cc] = v1;
        }
    }
}

// merged Q + KV projection: grid.x 0..7 -> Q, 8..23 -> KV
__global__ void __launch_bounds__(256, 2) qkv_gemm_kernel(
        const __half* __restrict__ xn2, const __half* __restrict__ Wq2T, float* __restrict__ q,
        const __half* __restrict__ x2, const __half* __restrict__ Wkv2T, float* __restrict__ kvout) {
    __shared__ __half As[STAGES * STG_ELEM];
    __shared__ __half Bs[STAGES * STG_ELEM];
    int cx = blockIdx.x;
    int row0 = blockIdx.y * 128;
    if (cx < 8) gemm_body(xn2, Wq2T, q, DIM_, DIM_ / BK, row0, cx * 128, As, Bs);
    else        gemm_body(x2, Wkv2T, kvout, 2 * DIM_, DIM_ / BK, row0, (cx - 8) * 128, As, Bs);
}

// output projection
__global__ void __launch_bounds__(256, 2) o_gemm_kernel(
        const __half* __restrict__ A, const __half* __restrict__ BT, float* __restrict__ C) {
    __shared__ __half As[STAGES * STG_ELEM];
    __shared__ __half Bs[STAGES * STG_ELEM];
    gemm_body(A, BT, C, DIM_, DIM_ / BK, blockIdx.y * 128, blockIdx.x * 128, As, Bs);
}

// ---------------- prep: Q2/K2/V2 fp16 ----------------
__global__ void prep_kernel(const float* __restrict__ q,
                            const float* __restrict__ kv,
                            const float* __restrict__ null_kv,
                            const float* __restrict__ q_scale,
                            const float* __restrict__ k_scale,
                            __half* __restrict__ Q2,
                            __half* __restrict__ K2,
                            __half* __restrict__ V2) {
    int warp = (blockIdx.x * blockDim.x + threadIdx.x) >> 5;
    int lane = threadIdx.x & 31;
    if (warp >= B_ * H_ * J_) return;
    int bh = warp / J_;
    int j  = warp % J_;
    int b = bh / H_, h = bh % H_;
    int d0 = lane, d1 = lane + 32;

    float k0, k1, v0, v1;
    if (j < NNK_) {
        const float* nb = null_kv + ((size_t)(h * NNK_ + j) * 2) * DH_;
        k0 = nb[d0];        k1 = nb[d1];
        v0 = nb[DH_ + d0];  v1 = nb[DH_ + d1];
    } else {
        int n = j - NNK_;
        const float* base = kv + ((size_t)(b * N_ + n)) * (2 * DIM_) + h * DH_;
        k0 = base[d0];          k1 = base[d1];
        v0 = base[DIM_ + d0];   v1 = base[DIM_ + d1];
    }
    float ss = k0 * k0 + k1 * k1;
#pragma unroll
    for (int off = 16; off > 0; off >>= 1)
        ss += __shfl_xor_sync(0xffffffffu, ss, off);
    float inv = 1.0f / fmaxf(sqrtf(ss), 1e-12f);
    size_t ko = ((size_t)bh * J_PAD + j) * 64;
    K2[ko + d0] = __float2half_rn(k0 * inv * k_scale[d0]);
    K2[ko + d1] = __float2half_rn(k1 * inv * k_scale[d1]);
    V2[ko + d0] = __float2half_rn(v0);
    V2[ko + d1] = __float2half_rn(v1);

    if (j < N_) {
        int n = j;
        const float* qb = q + ((size_t)(b * N_ + n)) * DIM_ + h * DH_;
        float a0 = qb[d0], a1 = qb[d1];
        float qs2 = a0 * a0 + a1 * a1;
#pragma unroll
        for (int off = 16; off > 0; off >>= 1)
            qs2 += __shfl_xor_sync(0xffffffffu, qs2, off);
        float qinv = 1.0f / fmaxf(sqrtf(qs2), 1e-12f);
        float q0 = a0 * qinv * q_scale[d0];
        float q1 = a1 * qinv * q_scale[d1];
        size_t qo = ((size_t)bh * N_ + n) * 128;
        __half hh, hl;
        split_f16(q0, hh, hl);
        Q2[qo + d0] = hh; Q2[qo + 64 + d0] = hl;
        split_f16(q1, hh, hl);
        Q2[qo + d1] = hh; Q2[qo + 64 + d1] = hl;
    }
}

// ---------------- flash attention: fp16 QK 2-term + online-max fp16 PV ----------------
// smem: Qs fp16 [128][136] @0 (34816), Ks fp16 [2][64][72] @34816 (2x9216),
//       Vs fp16 [2][64][72] @53248 (2x9216), mm [2][64] @71680 (512)
#define QS_OFF   0
#define KS_OFF   34816
#define KS_SZ    9216
#define VS_OFF   53248
#define VS_SZ    9216
#define MM_OFF   71680
#define SMEM_ATT 72192

__device__ __forceinline__ void load_tile(int stage, int j0, int bh, int b, int tid,
        uint32_t sbase, char* smx,
        const __half* __restrict__ K2, const __half* __restrict__ V2,
        const int* __restrict__ mask) {
    uint32_t ks = sbase + KS_OFF + stage * KS_SZ;
    uint32_t vs = sbase + VS_OFF + stage * VS_SZ;
#pragma unroll
    for (int i = 0; i < 2; i++) {
        int idx = i * 256 + tid;
        int row = idx >> 3, c = idx & 7;
        uint32_t doff = (uint32_t)((row * 72 + c * 8) * 2);
        size_t soff = ((size_t)bh * J_PAD + j0 + row) * 64 + c * 8;
        cp16(ks + doff, K2 + soff);
        cp16(vs + doff, V2 + soff);
    }
    if (tid < 64) {
        int jg = j0 + tid;
        float mm = 1.f;
        if (jg >= NNK_) mm = (jg < J_ && mask[b * N_ + jg - NNK_] != 0) ? 1.f : 0.f;
        ((float*)(smx + MM_OFF))[stage * 64 + tid] = mm;
    }
}

__global__ void __launch_bounds__(256, 2) attn_mma_kernel(
        const __half* __restrict__ Q2, const __half* __restrict__ K2,
        const __half* __restrict__ V2, const float* __restrict__ bias,
        const int* __restrict__ mask, __half* __restrict__ att2) {
    extern __shared__ char smx[];
    const uint32_t sbase = (uint32_t)__cvta_generic_to_shared(smx);

    const int tid = threadIdx.x;
    const int w = tid >> 5, lane = tid & 31;
    const int g = lane >> 2, tig = lane & 3;
    const int ib = (int)gridDim.x - 1 - (int)blockIdx.x;   // heavy CTAs first
    const int i0 = ib * 128;
    const int bh = blockIdx.y, b = bh >> 4, h = bh & 15;
    const int iw = i0 + w * 16;
    const int ig0 = iw + g, ig1 = ig0 + 8;
    const float* brow0 = bias + ((size_t)h * N_ + ig0) * N_ - NNK_;
    const float* brow1 = bias + ((size_t)h * N_ + ig1) * N_ - NNK_;

    const int jtmax = min((i0 + 129) >> 6, J_PAD / 64 - 1);

    // Q tile: 128 rows x 128 fp16 [Qhi|Qlo]
#pragma unroll
    for (int i = 0; i < 8; i++) {
        int idx = i * 256 + tid;
        int row = idx >> 4, c = idx & 15;
        cp16(sbase + QS_OFF + (uint32_t)((row * 136 + c * 8) * 2),
             Q2 + ((size_t)bh * N_ + i0 + row) * 128 + c * 8);
    }
    load_tile(0, 0, bh, b, tid, sbase, smx, K2, V2, mask);
    cp_commit();

    float oacc[8][4];
#pragma unroll
    for (int d = 0; d < 8; d++)
#pragma unroll
        for (int e = 0; e < 4; e++) oacc[d][e] = 0.f;
    float lsum0 = 0.f, lsum1 = 0.f;
    float rmax0 = -1e30f, rmax1 = -1e30f;    // running row maxes (exp2 domain)

    int buf = 0;
    for (int jt = 0; jt <= jtmax; jt++) {
        const int j0 = jt * 64;
        if (jt < jtmax)
            load_tile(buf ^ 1, j0 + 64, bh, b, tid, sbase, smx, K2, V2, mask);
        cp_commit();
        cp_wait1();
        __syncthreads();

        const bool active = (j0 <= iw + 15 + NNK_);
        if (active) {
            const uint32_t ks = sbase + KS_OFF + buf * KS_SZ;
            const uint32_t vs = sbase + VS_OFF + buf * VS_SZ;
            const float* mm = (const float*)(smx + MM_OFF) + buf * 64;

            float sacc[8][4];
#pragma unroll
            for (int jf = 0; jf < 8; jf++)
#pragma unroll
                for (int e = 0; e < 4; e++) sacc[jf][e] = 0.f;

            const int a_row = w * 16 + (lane & 15);
            const int a_kin = (lane >> 4) << 3;
            const int bp_row = ((lane >> 4) << 3) + (lane & 7);
            const int bp_k   = ((lane >> 3) & 1) << 3;
            // S = [Qhi|Qlo] . Khi  (fp16 2-term; paired-jf x4 K loads, K stride 72)
#pragma unroll
            for (int kc = 0; kc < 4; kc++) {
                uint32_t ah[4], al[4];
                ldmx4(ah, sbase + QS_OFF + (uint32_t)((a_row * 136 + kc * 16 + a_kin) << 1));
                ldmx4(al, sbase + QS_OFF + (uint32_t)((a_row * 136 + 64 + kc * 16 + a_kin) << 1));
#pragma unroll
                for (int jfp = 0; jfp < 4; jfp++) {
                    uint32_t khp[4];
                    uint32_t ka = ks + (uint32_t)(((jfp * 16 + bp_row) * 72 + kc * 16 + bp_k) << 1);
                    ldmx4(khp, ka);
                    mma16816h(sacc[2 * jfp],     ah, &khp[0]);
                    mma16816h(sacc[2 * jfp],     al, &khp[0]);
                    mma16816h(sacc[2 * jfp + 1], ah, &khp[2]);
                    mma16816h(sacc[2 * jfp + 1], al, &khp[2]);
                }
            }

            // logits (exp2 domain), masked -> -1e30 (in-place in sacc)
#pragma unroll
            for (int jf = 0; jf < 8; jf++) {
                int jc = j0 + jf * 8 + tig * 2;
                float km0 = mm[jf * 8 + tig * 2];
                float km1 = mm[jf * 8 + tig * 2 + 1];
                float2 bv0 = { 0.f, 0.f }, bv1 = { 0.f, 0.f };
                if (jc >= NNK_ && jc < J_) {     // jc even => pair fully in range
                    bv0 = *(const float2*)(brow0 + jc);
                    bv1 = *(const float2*)(brow1 + jc);
                }
                bool ok00 = (jc     <= ig0 + NNK_) && (jc     < J_) && (km0 > 0.5f);
                bool ok01 = (jc + 1 <= ig0 + NNK_) && (jc + 1 < J_) && (km1 > 0.5f);
                bool ok10 = (jc     <= ig1 + NNK_) && (jc     < J_) && (km0 > 0.5f);
                bool ok11 = (jc + 1 <= ig1 + NNK_) && (jc + 1 < J_) && (km1 > 0.5f);
                sacc[jf][0] = ok00 ? fmaf(sacc[jf][0], 11.541560327111707f, bv0.x * 1.4426950408889634f) : -1e30f;
                sacc[jf][1] = ok01 ? fmaf(sacc[jf][1], 11.541560327111707f, bv0.y * 1.4426950408889634f) : -1e30f;
                sacc[jf][2] = ok10 ? fmaf(sacc[jf][2], 11.541560327111707f, bv1.x * 1.4426950408889634f) : -1e30f;
                sacc[jf][3] = ok11 ? fmaf(sacc[jf][3], 11.541560327111707f, bv1.y * 1.4426950408889634f) : -1e30f;
            }

            // tile row maxes (quad reduce), rescale running state
            float tm0 = -1e30f, tm1 = -1e30f;
#pragma unroll
            for (int jf = 0; jf < 8; jf++) {
                tm0 = fmaxf(tm0, fmaxf(sacc[jf][0], sacc[jf][1]));
                tm1 = fmaxf(tm1, fmaxf(sacc[jf][2], sacc[jf][3]));
            }
            tm0 = fmaxf(tm0, __shfl_xor_sync(0xffffffffu, tm0, 1));
            tm0 = fmaxf(tm0, __shfl_xor_sync(0xffffffffu, tm0, 2));
            tm1 = fmaxf(tm1, __shfl_xor_sync(0xffffffffu, tm1, 1));
            tm1 = fmaxf(tm1, __shfl_xor_sync(0xffffffffu, tm1, 2));
            float mn0 = fmaxf(rmax0, tm0), mn1 = fmaxf(rmax1, tm1);
            float corr0 = ex2(rmax0 - mn0), corr1 = ex2(rmax1 - mn1);
            rmax0 = mn0; rmax1 = mn1;
#pragma unroll
            for (int d = 0; d < 8; d++) {
                oacc[d][0] *= corr0; oacc[d][1] *= corr0;
                oacc[d][2] *= corr1; oacc[d][3] *= corr1;
            }

            // p = exp2(l - rowmax) in (0,1]; pack fp16 P frags
            uint32_t pfr[8][2];
            float rs0 = 0.f, rs1 = 0.f;
#pragma unroll
            for (int jf = 0; jf < 8; jf++) {
                float p0 = ex2(sacc[jf][0] - mn0);
                float p1 = ex2(sacc[jf][1] - mn0);
                float p2 = ex2(sacc[jf][2] - mn1);
                float p3 = ex2(sacc[jf][3] - mn1);
                rs0 += p0 + p1;
                rs1 += p2 + p3;
                pfr[jf][0] = hpackf(p0, p1);
                pfr[jf][1] = hpackf(p2, p3);
            }
            lsum0 = lsum0 * corr0 + rs0;
            lsum1 = lsum1 * corr1 + rs1;

            // O += P . Vhi  (fp16 1-term; x4t pairs df blocks)
            const int v_row = (lane & 7) + ((lane >> 3) & 1) * 8;  // row within 16
            const int v_cofs = (lane >> 4) * 8;                    // df-pair half
#pragma unroll
            for (int kc2 = 0; kc2 < 4; kc2++) {
                uint32_t ah[4] = { pfr[2 * kc2][0], pfr[2 * kc2][1],
                                   pfr[2 * kc2 + 1][0], pfr[2 * kc2 + 1][1] };
#pragma unroll
                for (int df2 = 0; df2 < 4; df2++) {
                    uint32_t vf[4];
                    uint32_t va = vs + (uint32_t)((((kc2 * 16 + v_row) * 72) + df2 * 16 + v_cofs) << 1);
                    ldmx4t(vf, va);
                    mma16816h(oacc[2 * df2],     ah, &vf[0]);
                    mma16816h(oacc[2 * df2 + 1], ah, &vf[2]);
                }
            }
        }
        __syncthreads();
        buf ^= 1;
    }

    lsum0 += __shfl_xor_sync(0xffffffffu, lsum0, 1);
    lsum0 += __shfl_xor_sync(0xffffffffu, lsum0, 2);
    lsum1 += __shfl_xor_sync(0xffffffffu, lsum1, 1);
    lsum1 += __shfl_xor_sync(0xffffffffu, lsum1, 2);
    float inv0 = 1.0f / lsum0;
    float inv1 = 1.0f / lsum1;

    // epilogue: fp16 [hi|lo] rows for the fp16 output GEMM
#pragma unroll
    for (int df = 0; df < 8; df++) {
        float o0 = oacc[df][0] * inv0, o1 = oacc[df][1] * inv0;
        float o2 = oacc[df][2] * inv1, o3 = oacc[df][3] * inv1;
        __half h0, l0, h1, l1, h2, l2, h3, l3;
        split_f16(o0, h0, l0); split_f16(o1, h1, l1);
        split_f16(o2, h2, l2); split_f16(o3, h3, l3);
        {
            __half* p = att2 + ((size_t)(b * N_ + ig0)) * KP2 + h * DH_ + df * 8 + tig * 2;
            *(uint32_t*)(p)        = hpack(h0, h1);
            *(uint32_t*)(p + DIM_) = hpack(l0, l1);
        }
        {
            __half* p = att2 + ((size_t)(b * N_ + ig1)) * KP2 + h * DH_ + df * 8 + tig * 2;
            *(uint32_t*)(p)        = hpack(h2, h3);
            *(uint32_t*)(p + DIM_) = hpack(l2, l3);
        }
    }
}

// ---------------- launch ----------------
extern "C" void kernel_launch(void* const* d_in, const int* in_sizes, int n_in,
                              void* d_out, int out_size) {
    const float* x     = (const float*)d_in[0];
    const int*   mask  = (const int*)d_in[1];
    const float* bias  = (const float*)d_in[2];
    const float* gamma = (const float*)d_in[3];
    const float* nkv   = (const float*)d_in[4];
    const float* Wq    = (const float*)d_in[5];
    const float* Wkv   = (const float*)d_in[6];
    const float* qsc   = (const float*)d_in[7];
    const float* ksc   = (const float*)d_in[8];
    const float* Wo    = (const float*)d_in[9];
    float* out = (float*)d_out;

    __half *p_x2, *p_xn2, *p_att2, *p_Wq2T, *p_Wkv2T, *p_Wo2T, *p_Q2, *p_K2, *p_V2;
    float *p_q, *p_kv;
    cudaGetSymbolAddress((void**)&p_x2,    g_x2);
    cudaGetSymbolAddress((void**)&p_xn2,   g_xn2);
    cudaGetSymbolAddress((void**)&p_att2,  g_att2);
    cudaGetSymbolAddress((void**)&p_Wq2T,  g_Wq2T);
    cudaGetSymbolAddress((void**)&p_Wkv2T, g_Wkv2T);
    cudaGetSymbolAddress((void**)&p_Wo2T,  g_Wo2T);
    cudaGetSymbolAddress((void**)&p_q,     g_q);
    cudaGetSymbolAddress((void**)&p_kv,    g_kv);
    cudaGetSymbolAddress((void**)&p_Q2,    g_Q2);
    cudaGetSymbolAddress((void**)&p_K2,    g_K2);
    cudaGetSymbolAddress((void**)&p_V2,    g_V2);

    ln_kernel<<<MTOT, 256>>>(x, gamma, p_xn2, p_x2);                                  // 1
    wconv_all_kernel<<<dim3(2 * DIM_ / 32, DIM_ / 32, 3), dim3(32, 8)>>>(
        Wq, p_Wq2T, Wkv, p_Wkv2T, Wo, p_Wo2T);                                        // 2

    // merged Q + KV projection (768 CTAs)
    qkv_gemm_kernel<<<dim3(24, MTOT / 128), 256>>>(
        p_xn2, p_Wq2T, p_q, p_x2, p_Wkv2T, p_kv);                                     // 3

    int nwarp = B_ * H_ * J_;
    prep_kernel<<<(nwarp + 7) / 8, 256>>>(p_q, p_kv, nkv, qsc, ksc, p_Q2, p_K2, p_V2);// 4

    cudaFuncSetAttribute(attn_mma_kernel, cudaFuncAttributeMaxDynamicSharedMemorySize, SMEM_ATT);
    dim3 ga(N_ / 128, B_ * H_);
    attn_mma_kernel<<<ga, 256, SMEM_ATT>>>(p_Q2, p_K2, p_V2, bias, mask, p_att2);     // 5

    o_gemm_kernel<<<dim3(DIM_ / 128, MTOT / 128), 256>>>(p_att2, p_Wo2T, out);        // 6
}